// round 9
// baseline (speedup 1.0000x reference)
#include <cuda_runtime.h>
#include <cuda_bf16.h>
#include <cstdint>

// Problem constants
#define BB 4
#define NN 2048
#define DD 1024
#define HH 16
#define DH 64
#define BN (BB*NN)          // 8192
#define LN_EPS 1e-5f

// ---------------------------------------------------------------------------
// Device scratch (no allocation allowed)
// ---------------------------------------------------------------------------
__device__ __nv_bfloat16 g_xn_hi[BN * DD];
__device__ __nv_bfloat16 g_xn_lo[BN * DD];
__device__ __nv_bfloat16 g_ao_hi[BN * DD];
__device__ __nv_bfloat16 g_ao_lo[BN * DD];
__device__ __nv_bfloat16 g_whi[4 * DD * DD];
__device__ __nv_bfloat16 g_wlo[4 * DD * DD];
__device__ float g_q[BB * HH * NN * DH];
__device__ float g_k[BB * HH * NN * DH];
__device__ __nv_bfloat16 g_qh[BB * HH * NN * DH];
__device__ __nv_bfloat16 g_ql[BB * HH * NN * DH];
__device__ __nv_bfloat16 g_kh[BB * HH * NN * DH];
__device__ __nv_bfloat16 g_kl[BB * HH * NN * DH];
__device__ __nv_bfloat16 g_vh[BB * HH * NN * DH];
__device__ __nv_bfloat16 g_vl[BB * HH * NN * DH];
__device__ float g_maskbias[BB * NN];
__device__ float g_bqkv[3 * DD];

// ---------------------------------------------------------------------------
// Helpers
// ---------------------------------------------------------------------------
__device__ __forceinline__ uint32_t s2u(const void* p) {
    uint32_t a;
    asm("{ .reg .u64 t; cvta.to.shared.u64 t, %1; cvt.u32.u64 %0, t; }"
        : "=r"(a) : "l"(p));
    return a;
}

__device__ __forceinline__ void cpa16(uint32_t dst, const void* src) {
    asm volatile("cp.async.cg.shared.global [%0], [%1], 16;"
                 :: "r"(dst), "l"(src) : "memory");
}
#define CP_COMMIT() asm volatile("cp.async.commit_group;" ::: "memory")
#define CP_WAIT(N)  asm volatile("cp.async.wait_group %0;" :: "n"(N) : "memory")

__device__ __forceinline__ void ldsm4(uint32_t& r0, uint32_t& r1,
                                      uint32_t& r2, uint32_t& r3,
                                      uint32_t addr) {
    asm volatile("ldmatrix.sync.aligned.m8n8.x4.shared.b16 {%0,%1,%2,%3}, [%4];"
                 : "=r"(r0), "=r"(r1), "=r"(r2), "=r"(r3) : "r"(addr));
}

__device__ __forceinline__ void ldsm4t(uint32_t& r0, uint32_t& r1,
                                       uint32_t& r2, uint32_t& r3,
                                       uint32_t addr) {
    asm volatile("ldmatrix.sync.aligned.m8n8.x4.trans.shared.b16 {%0,%1,%2,%3}, [%4];"
                 : "=r"(r0), "=r"(r1), "=r"(r2), "=r"(r3) : "r"(addr));
}

__device__ __forceinline__ void mma16816(float* c, const uint32_t* a,
                                         uint32_t b0, uint32_t b1) {
    asm volatile(
        "mma.sync.aligned.m16n8k16.row.col.f32.bf16.bf16.f32 "
        "{%0,%1,%2,%3}, {%4,%5,%6,%7}, {%8,%9}, {%0,%1,%2,%3};"
        : "+f"(c[0]), "+f"(c[1]), "+f"(c[2]), "+f"(c[3])
        : "r"(a[0]), "r"(a[1]), "r"(a[2]), "r"(a[3]), "r"(b0), "r"(b1));
}

// hi/lo bf16 split of a float pair -> two packed bf16x2 regs
__device__ __forceinline__ void hl_pack(float a, float b, uint32_t& hi, uint32_t& lo) {
    __nv_bfloat162 h = __float22bfloat162_rn(make_float2(a, b));
    float2 f = __bfloat1622float2(h);
    __nv_bfloat162 l = __float22bfloat162_rn(make_float2(a - f.x, b - f.y));
    hi = *reinterpret_cast<uint32_t*>(&h);
    lo = *reinterpret_cast<uint32_t*>(&l);
}

__device__ __forceinline__ void hl2_store(float a, float b,
                                          __nv_bfloat16* hip, __nv_bfloat16* lop) {
    uint32_t hi, lo;
    hl_pack(a, b, hi, lo);
    *(uint32_t*)hip = hi;
    *(uint32_t*)lop = lo;
}

__device__ __forceinline__ void hl4_store(float4 v, __nv_bfloat16* hip,
                                          __nv_bfloat16* lop) {
    hl2_store(v.x, v.y, hip, lop);
    hl2_store(v.z, v.w, hip + 2, lop + 2);
}

// ---------------------------------------------------------------------------
// Kernel 0: mask preprocessing + bias concat
// ---------------------------------------------------------------------------
__global__ __launch_bounds__(256)
void prep_kernel(const void* __restrict__ mask,
                 const float* __restrict__ bq,
                 const float* __restrict__ bk,
                 const float* __restrict__ bv)
{
    __shared__ int s_packed;
    if (threadIdx.x == 0) s_packed = 0;
    __syncthreads();

    const unsigned* mw = (const unsigned*)mask;
    int bad = 0;
    for (int i = threadIdx.x; i < 2048; i += 256)
        if (mw[i] > 1u) bad = 1;
    if (bad) atomicOr(&s_packed, 1);
    __syncthreads();
    const bool packed = (s_packed != 0);

    const int* mi = (const int*)mask;
    const unsigned char* mb = (const unsigned char*)mask;
    for (int i = threadIdx.x; i < BB * NN; i += 256) {
        const int on = packed ? (int)mb[i] : mi[i];
        g_maskbias[i] = on ? 0.0f : -1e30f;
    }
    for (int i = threadIdx.x; i < DD; i += 256) {
        g_bqkv[i]          = bq[i];
        g_bqkv[DD + i]     = bk[i];
        g_bqkv[2 * DD + i] = bv[i];
    }
}

// ---------------------------------------------------------------------------
// Kernel W: split all four W[1024x1024] into hi/lo bf16 (grid.y = slot)
// ---------------------------------------------------------------------------
__global__ __launch_bounds__(256)
void wconv_kernel(const float* __restrict__ W0, const float* __restrict__ W1,
                  const float* __restrict__ W2, const float* __restrict__ W3)
{
    const int slot = blockIdx.y;
    const float* W = (slot == 0) ? W0 : (slot == 1) ? W1 : (slot == 2) ? W2 : W3;
    const size_t i = ((size_t)blockIdx.x * 256 + threadIdx.x) * 4;
    float4 v = *(const float4*)(W + i);
    const size_t off = (size_t)slot * DD * DD + i;
    hl4_store(v, g_whi + off, g_wlo + off);
}

// ---------------------------------------------------------------------------
// Kernel 1: row LayerNorm over D=1024 -> hi/lo bf16
// ---------------------------------------------------------------------------
__global__ __launch_bounds__(256)
void ln_x_kernel(const float* __restrict__ x,
                 const float* __restrict__ w,
                 const float* __restrict__ b)
{
    __shared__ float red_s[8];
    __shared__ float red_q[8];
    __shared__ float stats[2];
    const int row = blockIdx.x;
    const int t = threadIdx.x;
    const int lane = t & 31, warp = t >> 5;

    const float* xr = x + (long)row * DD;
    float4 xv = *(const float4*)(xr + t * 4);
    float sum = xv.x + xv.y + xv.z + xv.w;
    float ssq = fmaf(xv.x, xv.x, fmaf(xv.y, xv.y, fmaf(xv.z, xv.z, xv.w * xv.w)));
    #pragma unroll
    for (int o = 16; o > 0; o >>= 1) {
        sum += __shfl_xor_sync(0xffffffffu, sum, o);
        ssq += __shfl_xor_sync(0xffffffffu, ssq, o);
    }
    if (lane == 0) { red_s[warp] = sum; red_q[warp] = ssq; }
    __syncthreads();
    if (warp == 0) {
        float a = (lane < 8) ? red_s[lane] : 0.0f;
        float c = (lane < 8) ? red_q[lane] : 0.0f;
        #pragma unroll
        for (int o = 4; o > 0; o >>= 1) {
            a += __shfl_xor_sync(0xffffffffu, a, o);
            c += __shfl_xor_sync(0xffffffffu, c, o);
        }
        if (lane == 0) { stats[0] = a * (1.0f / DD); stats[1] = c * (1.0f / DD); }
    }
    __syncthreads();
    const float mean = stats[0];
    const float var = stats[1] - mean * mean;
    const float rstd = rsqrtf(var + LN_EPS);

    float4 wv = *(const float4*)(w + t * 4);
    float4 bv = *(const float4*)(b + t * 4);
    float4 ov;
    ov.x = (xv.x - mean) * rstd * wv.x + bv.x;
    ov.y = (xv.y - mean) * rstd * wv.y + bv.y;
    ov.z = (xv.z - mean) * rstd * wv.z + bv.z;
    ov.w = (xv.w - mean) * rstd * wv.w + bv.w;
    const size_t off = (size_t)row * DD + t * 4;
    hl4_store(ov, g_xn_hi + off, g_xn_lo + off);
}

// ---------------------------------------------------------------------------
// Kernel 2: HMMA bf16x3 GEMM, cp.async double-buffered, K-slab 32.
// 128x128 CTA tile, 4 warps (2M x 2N), warp tile 64x64, 128 threads.
// MODE 0: A=g_ao(hi/lo), B=Wo slot3, C=Cout plain (grid 8x64).
// MODE 4: fused QKV, A=g_xn, B=slots 0..2 (N=3072, grid 24x64),
//         scatter: q,k fp32 + bias; v hi/lo bf16 + bias.
// ---------------------------------------------------------------------------
#define KSL 32
#define SST2 40                              // 32 + 8 pad (80B rows)
#define BUF2 (128 * SST2)                    // 5120 elems
#define STAGE_ELE (4 * BUF2)                 // 20480 elems = 40960 B
#define GEMM_SMEM2 (2 * STAGE_ELE * 2)       // 81920 B

template<int MODE>
__global__ __launch_bounds__(128, 2)
void gemm_mma2(float* __restrict__ Cout)
{
    extern __shared__ __nv_bfloat16 smg[];
    const uint32_t u0 = s2u(smg);

    const int tid = threadIdx.x;
    const int wid = tid >> 5, lane = tid & 31;
    const int wm = (wid & 1) << 6;          // 0, 64
    const int wn = (wid >> 1) << 6;         // 0, 64
    const int bm = blockIdx.y << 7;
    const int bn = blockIdx.x << 7;

    const __nv_bfloat16* gAh = (MODE == 0) ? g_ao_hi : g_xn_hi;
    const __nv_bfloat16* gAl = (MODE == 0) ? g_ao_lo : g_xn_lo;
    const __nv_bfloat16* gBh = (MODE == 0) ? (g_whi + (size_t)3 * DD * DD) : g_whi;
    const __nv_bfloat16* gBl = (MODE == 0) ? (g_wlo + (size_t)3 * DD * DD) : g_wlo;

    float acc[4][8][4];
    #pragma unroll
    for (int i = 0; i < 4; i++)
        #pragma unroll
        for (int j = 0; j < 8; j++)
            #pragma unroll
            for (int k = 0; k < 4; k++) acc[i][j][k] = 0.0f;

    // cp.async: each thread owns one 64B row per buffer (4 x cpa16)
    const int lrow = tid;
    const __nv_bfloat16* pAh = gAh + (size_t)(bm + lrow) * DD;
    const __nv_bfloat16* pAl = gAl + (size_t)(bm + lrow) * DD;
    const __nv_bfloat16* pBh = gBh + (size_t)(bn + lrow) * DD;
    const __nv_bfloat16* pBl = gBl + (size_t)(bn + lrow) * DD;
    const uint32_t dbase = u0 + lrow * SST2 * 2;

    // ldmatrix lane addressing
    const int aRow = (lane & 7) + ((lane & 8) ? 8 : 0);
    const int aK   = (lane & 16) ? 8 : 0;
    const int bRow = (lane & 7) + ((lane & 16) ? 8 : 0);
    const int bK   = (lane & 8) ? 8 : 0;

    #define ISSUE_STAGE(kt, stg) do {                                        \
        const uint32_t d_ = dbase + (stg) * (STAGE_ELE * 2);                  \
        _Pragma("unroll")                                                     \
        for (int q_ = 0; q_ < 4; q_++) {                                      \
            cpa16(d_ + 0 * BUF2 * 2 + q_ * 16, pAh + (kt) + q_ * 8);          \
            cpa16(d_ + 1 * BUF2 * 2 + q_ * 16, pAl + (kt) + q_ * 8);          \
            cpa16(d_ + 2 * BUF2 * 2 + q_ * 16, pBh + (kt) + q_ * 8);          \
            cpa16(d_ + 3 * BUF2 * 2 + q_ * 16, pBl + (kt) + q_ * 8);          \
        }                                                                     \
        CP_COMMIT();                                                          \
    } while (0)

    ISSUE_STAGE(0, 0);

    const int NSLAB = DD / KSL;   // 32
    for (int s = 0; s < NSLAB; s++) {
        if (s + 1 < NSLAB) {
            ISSUE_STAGE((s + 1) * KSL, (s + 1) & 1);
            CP_WAIT(1);
        } else {
            CP_WAIT(0);
        }
        __syncthreads();

        const uint32_t sb = u0 + (s & 1) * (STAGE_ELE * 2);
        const uint32_t aAh = sb + ((wm + aRow) * SST2 + aK) * 2;
        const uint32_t aAl = aAh + BUF2 * 2;
        const uint32_t aBh = sb + 2 * BUF2 * 2 + ((wn + bRow) * SST2 + bK) * 2;
        const uint32_t aBl = aBh + BUF2 * 2;

        #pragma unroll
        for (int k16 = 0; k16 < 2; k16++) {
            const uint32_t koff = (k16 << 4) * 2;
            uint32_t ah[4][4], al[4][4];
            #pragma unroll
            for (int mt = 0; mt < 4; mt++) {
                const uint32_t moff = (mt << 4) * SST2 * 2;
                ldsm4(ah[mt][0], ah[mt][1], ah[mt][2], ah[mt][3], aAh + moff + koff);
                ldsm4(al[mt][0], al[mt][1], al[mt][2], al[mt][3], aAl + moff + koff);
            }
            #pragma unroll
            for (int p = 0; p < 4; p++) {
                const uint32_t noff = (p << 4) * SST2 * 2;
                uint32_t bh0, bh1, bh2, bh3, bl0, bl1, bl2, bl3;
                ldsm4(bh0, bh1, bh2, bh3, aBh + noff + koff);
                ldsm4(bl0, bl1, bl2, bl3, aBl + noff + koff);
                #pragma unroll
                for (int mt = 0; mt < 4; mt++) {
                    mma16816(acc[mt][2 * p + 0], ah[mt], bh0, bh1);
                    mma16816(acc[mt][2 * p + 1], ah[mt], bh2, bh3);
                    mma16816(acc[mt][2 * p + 0], ah[mt], bl0, bl1);
                    mma16816(acc[mt][2 * p + 1], ah[mt], bl2, bl3);
                    mma16816(acc[mt][2 * p + 0], al[mt], bh0, bh1);
                    mma16816(acc[mt][2 * p + 1], al[mt], bh2, bh3);
                }
            }
        }
        __syncthreads();
    }
    #undef ISSUE_STAGE

    // Epilogue
    const int g = lane >> 2, tq = lane & 3;
    #pragma unroll
    for (int mt = 0; mt < 4; mt++) {
        #pragma unroll
        for (int nt = 0; nt < 8; nt++) {
            const int c = bn + wn + nt * 8 + 2 * tq;
            #pragma unroll
            for (int half = 0; half < 2; half++) {
                const int r = bm + wm + mt * 16 + g + half * 8;
                float2 v;
                v.x = acc[mt][nt][2 * half + 0];
                v.y = acc[mt][nt][2 * half + 1];
                if (MODE == 0) {
                    *(float2*)(Cout + (size_t)r * DD + c) = v;
                } else {
                    const float2 bv = *(const float2*)(g_bqkv + c);
                    v.x += bv.x; v.y += bv.y;
                    const int which = c >> 10;
                    const int cc = c & 1023;
                    const int h = cc >> 6;
                    const size_t idx = ((((size_t)((r >> 11) * HH + h)) * NN
                                        + (r & 2047)) << 6) + (cc & 63);
                    if (which == 0)      *(float2*)(g_q + idx) = v;
                    else if (which == 1) *(float2*)(g_k + idx) = v;
                    else                 hl2_store(v.x, v.y, g_vh + idx, g_vl + idx);
                }
            }
        }
    }
}

// ---------------------------------------------------------------------------
// Kernel 3: per-head LayerNorm over DH=64 -> hi/lo bf16 (grid.y: 0=q, 1=k)
// ---------------------------------------------------------------------------
__global__ __launch_bounds__(256)
void headln_kernel(const float* __restrict__ qw, const float* __restrict__ qb,
                   const float* __restrict__ kw, const float* __restrict__ kb)
{
    const int isq = (blockIdx.y == 0);
    const float* base = isq ? g_q : g_k;
    __nv_bfloat16* oh = isq ? g_qh : g_kh;
    __nv_bfloat16* ol = isq ? g_ql : g_kl;
    const float* w = isq ? qw : kw;
    const float* b = isq ? qb : kb;
    const float sc = isq ? 0.125f : 1.0f;

    const int warp = threadIdx.x >> 5;
    const int lane = threadIdx.x & 31;
    const long row = (long)blockIdx.x * 8 + warp;
    const float* p = base + row * DH;

    float2 xv = *(const float2*)(p + lane * 2);
    float sum = xv.x + xv.y;
    float ssq = fmaf(xv.x, xv.x, xv.y * xv.y);
    #pragma unroll
    for (int o = 16; o > 0; o >>= 1) {
        sum += __shfl_xor_sync(0xffffffffu, sum, o);
        ssq += __shfl_xor_sync(0xffffffffu, ssq, o);
    }
    const float mean = sum * (1.0f / DH);
    const float var = ssq * (1.0f / DH) - mean * mean;
    const float rstd = rsqrtf(var + LN_EPS);

    float2 wv = *(const float2*)(w + lane * 2);
    float2 bv = *(const float2*)(b + lane * 2);
    float a = ((xv.x - mean) * rstd * wv.x + bv.x) * sc;
    float c = ((xv.y - mean) * rstd * wv.y + bv.y) * sc;
    hl2_store(a, c, oh + row * DH + lane * 2, ol + row * DH + lane * 2);
}

// ---------------------------------------------------------------------------
// Kernel 4: tensor-core flash attention (bf16x3 QK^T and PV)
// grid (16, 16, 4): 128 queries x one (b,h) per CTA; 8 warps x 16 q-rows.
// Q staged in TWO passes through K-region rows to avoid overlap.
// ---------------------------------------------------------------------------
#define ASTR 72

__global__ __launch_bounds__(256)
void attn_mma_kernel()
{
    __shared__ __align__(16) __nv_bfloat16 sm[4 * 64 * ASTR];  // 36864 B
    __shared__ float mb[64];

    const int tid = threadIdx.x, wid = tid >> 5, lane = tid & 31;
    const int bq = blockIdx.x << 7;
    const int h = blockIdx.y, b = blockIdx.z;
    const size_t head_off = ((size_t)(b * HH + h)) * NN;

    const uint32_t u0 = s2u(sm);
    const uint32_t Kh = u0;
    const uint32_t Kl = u0 + 64 * ASTR * 2;
    const uint32_t Vh = u0 + 2 * 64 * ASTR * 2;
    const uint32_t Vl = u0 + 3 * 64 * ASTR * 2;

    // ldmatrix lane addressing
    const int aRow = (lane & 7) + ((lane & 8) ? 8 : 0);
    const int aK   = (lane & 16) ? 8 : 0;
    const int bRow = (lane & 7) + ((lane & 16) ? 8 : 0);
    const int bK   = (lane & 8) ? 8 : 0;
    const int vRow = (lane & 7) + ((lane & 8) ? 8 : 0);
    const int vCol = (lane & 16) ? 8 : 0;

    // ---- Phase 1: stage Q hi then Q lo through rows [0,128) (two passes)
    uint32_t qh[4][4], ql[4][4];
    {
        const int r = tid >> 1;
        const int c = (tid & 1) << 5;
        const uint32_t qb = u0 + ((wid * 16 + aRow) * ASTR + aK) * 2;

        const __nv_bfloat16* sh = g_qh + (head_off + bq + r) * DH + c;
        #pragma unroll
        for (int i = 0; i < 4; i++)
            *(uint4*)(sm + r * ASTR + c + i * 8) = *(const uint4*)(sh + i * 8);
        __syncthreads();
        #pragma unroll
        for (int k = 0; k < 4; k++)
            ldsm4(qh[k][0], qh[k][1], qh[k][2], qh[k][3], qb + (k * 16) * 2);
        __syncthreads();

        const __nv_bfloat16* sl = g_ql + (head_off + bq + r) * DH + c;
        #pragma unroll
        for (int i = 0; i < 4; i++)
            *(uint4*)(sm + r * ASTR + c + i * 8) = *(const uint4*)(sl + i * 8);
        __syncthreads();
        #pragma unroll
        for (int k = 0; k < 4; k++)
            ldsm4(ql[k][0], ql[k][1], ql[k][2], ql[k][3], qb + (k * 16) * 2);
    }

    float o[8][4];
    #pragma unroll
    for (int i = 0; i < 8; i++)
        #pragma unroll
        for (int j = 0; j < 4; j++) o[i][j] = 0.0f;
    float m0 = -1e30f, m1 = -1e30f, l0 = 0.0f, l1 = 0.0f;

    const float* mrow = g_maskbias + b * NN;
    const int tq2 = (lane & 3) * 2;

    for (int kt = 0; kt < NN; kt += 64) {
        __syncthreads();
        // load K/V tiles (bf16 hi/lo, pre-split)
        {
            const int r = tid >> 2;
            const int c = (tid & 3) << 4;
            const size_t gidx = (head_off + kt + r) * DH + c;
            const int so = r * ASTR + c;
            #pragma unroll
            for (int i = 0; i < 2; i++) {
                *(uint4*)(sm + so + i * 8)                 = *(const uint4*)(g_kh + gidx + i * 8);
                *(uint4*)(sm + 64 * ASTR + so + i * 8)     = *(const uint4*)(g_kl + gidx + i * 8);
                *(uint4*)(sm + 2 * 64 * ASTR + so + i * 8) = *(const uint4*)(g_vh + gidx + i * 8);
                *(uint4*)(sm + 3 * 64 * ASTR + so + i * 8) = *(const uint4*)(g_vl + gidx + i * 8);
            }
            if (tid < 64) mb[tid] = mrow[kt + tid];
        }
        __syncthreads();

        // S = Q K^T  (bf16x3)
        float s[8][4];
        #pragma unroll
        for (int i = 0; i < 8; i++)
            #pragma unroll
            for (int j = 0; j < 4; j++) s[i][j] = 0.0f;

        #pragma unroll
        for (int k = 0; k < 4; k++) {
            #pragma unroll
            for (int p = 0; p < 4; p++) {
                const uint32_t nb = ((p * 16 + bRow) * ASTR + k * 16 + bK) * 2;
                uint32_t bh0, bh1, bh2, bh3, bl0, bl1, bl2, bl3;
                ldsm4(bh0, bh1, bh2, bh3, Kh + nb);
                ldsm4(bl0, bl1, bl2, bl3, Kl + nb);
                mma16816(s[2 * p + 0], qh[k], bh0, bh1);
                mma16816(s[2 * p + 1], qh[k], bh2, bh3);
                mma16816(s[2 * p + 0], qh[k], bl0, bl1);
                mma16816(s[2 * p + 1], qh[k], bl2, bl3);
                mma16816(s[2 * p + 0], ql[k], bh0, bh1);
                mma16816(s[2 * p + 1], ql[k], bh2, bh3);
            }
        }

        // mask + online softmax
        float mx0 = -1e30f, mx1 = -1e30f;
        #pragma unroll
        for (int nt = 0; nt < 8; nt++) {
            const float b0 = mb[nt * 8 + tq2];
            const float b1 = mb[nt * 8 + tq2 + 1];
            s[nt][0] += b0; s[nt][1] += b1;
            s[nt][2] += b0; s[nt][3] += b1;
            mx0 = fmaxf(mx0, fmaxf(s[nt][0], s[nt][1]));
            mx1 = fmaxf(mx1, fmaxf(s[nt][2], s[nt][3]));
        }
        mx0 = fmaxf(mx0, __shfl_xor_sync(0xffffffffu, mx0, 1));
        mx0 = fmaxf(mx0, __shfl_xor_sync(0xffffffffu, mx0, 2));
        mx1 = fmaxf(mx1, __shfl_xor_sync(0xffffffffu, mx1, 1));
        mx1 = fmaxf(mx1, __shfl_xor_sync(0xffffffffu, mx1, 2));
        const float mn0 = fmaxf(m0, mx0), mn1 = fmaxf(m1, mx1);
        const float sc0 = __expf(m0 - mn0), sc1 = __expf(m1 - mn1);
        m0 = mn0; m1 = mn1;
        float ps0 = 0.0f, ps1 = 0.0f;
        #pragma unroll
        for (int nt = 0; nt < 8; nt++) {
            s[nt][0] = __expf(s[nt][0] - m0);
            s[nt][1] = __expf(s[nt][1] - m0);
            s[nt][2] = __expf(s[nt][2] - m1);
            s[nt][3] = __expf(s[nt][3] - m1);
            ps0 += s[nt][0] + s[nt][1];
            ps1 += s[nt][2] + s[nt][3];
        }
        ps0 += __shfl_xor_sync(0xffffffffu, ps0, 1);
        ps0 += __shfl_xor_sync(0xffffffffu, ps0, 2);
        ps1 += __shfl_xor_sync(0xffffffffu, ps1, 1);
        ps1 += __shfl_xor_sync(0xffffffffu, ps1, 2);
        l0 = l0 * sc0 + ps0;
        l1 = l1 * sc1 + ps1;
        #pragma unroll
        for (int nt = 0; nt < 8; nt++) {
            o[nt][0] *= sc0; o[nt][1] *= sc0;
            o[nt][2] *= sc1; o[nt][3] *= sc1;
        }

        // O += P V   (P hi/lo x V hi/lo, 3 passes)
        #pragma unroll
        for (int jj = 0; jj < 4; jj++) {
            uint32_t ph[4], pl[4];
            hl_pack(s[2 * jj][0],     s[2 * jj][1],     ph[0], pl[0]);
            hl_pack(s[2 * jj][2],     s[2 * jj][3],     ph[1], pl[1]);
            hl_pack(s[2 * jj + 1][0], s[2 * jj + 1][1], ph[2], pl[2]);
            hl_pack(s[2 * jj + 1][2], s[2 * jj + 1][3], ph[3], pl[3]);
            #pragma unroll
            for (int p = 0; p < 4; p++) {
                const uint32_t off = ((jj * 16 + vRow) * ASTR + p * 16 + vCol) * 2;
                uint32_t bh0, bh1, bh2, bh3, bl0, bl1, bl2, bl3;
                ldsm4t(bh0, bh1, bh2, bh3, Vh + off);
                ldsm4t(bl0, bl1, bl2, bl3, Vl + off);
                mma16816(o[2 * p + 0], ph, bh0, bh1);
                mma16816(o[2 * p + 1], ph, bh2, bh3);
                mma16816(o[2 * p + 0], ph, bl0, bl1);
                mma16816(o[2 * p + 1], ph, bl2, bl3);
                mma16816(o[2 * p + 0], pl, bh0, bh1);
                mma16816(o[2 * p + 1], pl, bh2, bh3);
            }
        }
    }

    // epilogue -> g_ao hi/lo   [b, n, h*64+dh]
    const float inv0 = 1.0f / l0, inv1 = 1.0f / l1;
    const int g = lane >> 2;
    const int q0 = bq + wid * 16 + g;
    const size_t ob = ((size_t)(b * NN) + q0) * DD + h * DH;
    #pragma unroll
    for (int nt = 0; nt < 8; nt++) {
        const int dh = nt * 8 + tq2;
        hl2_store(o[nt][0] * inv0, o[nt][1] * inv0, g_ao_hi + ob + dh, g_ao_lo + ob + dh);
        hl2_store(o[nt][2] * inv1, o[nt][3] * inv1,
                  g_ao_hi + ob + 8 * DD + dh, g_ao_lo + ob + 8 * DD + dh);
    }
}

// ---------------------------------------------------------------------------
// Launch
// ---------------------------------------------------------------------------
extern "C" void kernel_launch(void* const* d_in, const int* in_sizes, int n_in,
                              void* d_out, int out_size)
{
    const float* x       = (const float*)d_in[0];
    const void*  mask    = (const void*)d_in[1];
    const float* norm_w  = (const float*)d_in[2];
    const float* norm_b  = (const float*)d_in[3];
    const float* qn_w    = (const float*)d_in[4];
    const float* qn_b    = (const float*)d_in[5];
    const float* kn_w    = (const float*)d_in[6];
    const float* kn_b    = (const float*)d_in[7];
    const float* Wq      = (const float*)d_in[8];
    const float* bq      = (const float*)d_in[9];
    const float* Wk      = (const float*)d_in[10];
    const float* bk      = (const float*)d_in[11];
    const float* Wv      = (const float*)d_in[12];
    const float* bv      = (const float*)d_in[13];
    const float* Wo      = (const float*)d_in[14];
    float* out = (float*)d_out;

    static bool attr_done = false;
    if (!attr_done) {
        cudaFuncSetAttribute(gemm_mma2<0>, cudaFuncAttributeMaxDynamicSharedMemorySize, GEMM_SMEM2);
        cudaFuncSetAttribute(gemm_mma2<4>, cudaFuncAttributeMaxDynamicSharedMemorySize, GEMM_SMEM2);
        attr_done = true;
    }

    // 0. Mask -> float bias; bias concat; W -> hi/lo bf16
    prep_kernel<<<1, 256>>>(mask, bq, bk, bv);
    wconv_kernel<<<dim3(1024, 4), 256>>>(Wq, Wk, Wv, Wo);

    // 1. LN(x) -> hi/lo bf16
    ln_x_kernel<<<BN, 256>>>(x, norm_w, norm_b);

    // 2. Fused QKV projection (cp.async pipelined HMMA bf16x3)
    gemm_mma2<4><<<dim3(3 * DD / 128, BN / 128), 128, GEMM_SMEM2>>>(nullptr);

    // 3. Per-head LN -> q/k hi/lo bf16 (q scaled by DH^-0.5)
    headln_kernel<<<dim3((BB * HH * NN) / 8, 2), 256>>>(qn_w, qn_b, kn_w, kn_b);

    // 4. Tensor-core flash attention -> g_ao hi/lo
    attn_mma_kernel<<<dim3(NN / 128, HH, BB), 256>>>();

    // 5. Output projection -> d_out
    gemm_mma2<0><<<dim3(DD / 128, BN / 128), 128, GEMM_SMEM2>>>(out);
}

// round 10
// speedup vs baseline: 1.0005x; 1.0005x over previous
#include <cuda_runtime.h>
#include <cuda_bf16.h>
#include <cstdint>

// Problem constants
#define BB 4
#define NN 2048
#define DD 1024
#define HH 16
#define DH 64
#define BN (BB*NN)          // 8192
#define LN_EPS 1e-5f

// ---------------------------------------------------------------------------
// Device scratch (no allocation allowed)
// ---------------------------------------------------------------------------
__device__ __nv_bfloat16 g_xn_hi[BN * DD];
__device__ __nv_bfloat16 g_xn_lo[BN * DD];
__device__ __nv_bfloat16 g_ao_hi[BN * DD];
__device__ __nv_bfloat16 g_ao_lo[BN * DD];
__device__ __nv_bfloat16 g_whi[4 * DD * DD];
__device__ __nv_bfloat16 g_wlo[4 * DD * DD];
__device__ float g_q[BB * HH * NN * DH];
__device__ float g_k[BB * HH * NN * DH];
__device__ __nv_bfloat16 g_qh[BB * HH * NN * DH];
__device__ __nv_bfloat16 g_ql[BB * HH * NN * DH];
__device__ __nv_bfloat16 g_kh[BB * HH * NN * DH];
__device__ __nv_bfloat16 g_kl[BB * HH * NN * DH];
__device__ __nv_bfloat16 g_vh[BB * HH * NN * DH];
__device__ __nv_bfloat16 g_vl[BB * HH * NN * DH];
__device__ float g_maskbias[BB * NN];
__device__ float g_bqkv[3 * DD];

// ---------------------------------------------------------------------------
// Helpers
// ---------------------------------------------------------------------------
__device__ __forceinline__ uint32_t s2u(const void* p) {
    uint32_t a;
    asm("{ .reg .u64 t; cvta.to.shared.u64 t, %1; cvt.u32.u64 %0, t; }"
        : "=r"(a) : "l"(p));
    return a;
}

__device__ __forceinline__ void cpa16(uint32_t dst, const void* src) {
    asm volatile("cp.async.cg.shared.global [%0], [%1], 16;"
                 :: "r"(dst), "l"(src) : "memory");
}
#define CP_COMMIT() asm volatile("cp.async.commit_group;" ::: "memory")
#define CP_WAIT(N)  asm volatile("cp.async.wait_group %0;" :: "n"(N) : "memory")

__device__ __forceinline__ void ldsm4(uint32_t& r0, uint32_t& r1,
                                      uint32_t& r2, uint32_t& r3,
                                      uint32_t addr) {
    asm volatile("ldmatrix.sync.aligned.m8n8.x4.shared.b16 {%0,%1,%2,%3}, [%4];"
                 : "=r"(r0), "=r"(r1), "=r"(r2), "=r"(r3) : "r"(addr));
}

__device__ __forceinline__ void ldsm4t(uint32_t& r0, uint32_t& r1,
                                       uint32_t& r2, uint32_t& r3,
                                       uint32_t addr) {
    asm volatile("ldmatrix.sync.aligned.m8n8.x4.trans.shared.b16 {%0,%1,%2,%3}, [%4];"
                 : "=r"(r0), "=r"(r1), "=r"(r2), "=r"(r3) : "r"(addr));
}

__device__ __forceinline__ void mma16816(float* c, const uint32_t* a,
                                         uint32_t b0, uint32_t b1) {
    asm volatile(
        "mma.sync.aligned.m16n8k16.row.col.f32.bf16.bf16.f32 "
        "{%0,%1,%2,%3}, {%4,%5,%6,%7}, {%8,%9}, {%0,%1,%2,%3};"
        : "+f"(c[0]), "+f"(c[1]), "+f"(c[2]), "+f"(c[3])
        : "r"(a[0]), "r"(a[1]), "r"(a[2]), "r"(a[3]), "r"(b0), "r"(b1));
}

// hi/lo bf16 split of a float pair -> two packed bf16x2 regs
__device__ __forceinline__ void hl_pack(float a, float b, uint32_t& hi, uint32_t& lo) {
    __nv_bfloat162 h = __float22bfloat162_rn(make_float2(a, b));
    float2 f = __bfloat1622float2(h);
    __nv_bfloat162 l = __float22bfloat162_rn(make_float2(a - f.x, b - f.y));
    hi = *reinterpret_cast<uint32_t*>(&h);
    lo = *reinterpret_cast<uint32_t*>(&l);
}

__device__ __forceinline__ void hl2_store(float a, float b,
                                          __nv_bfloat16* hip, __nv_bfloat16* lop) {
    uint32_t hi, lo;
    hl_pack(a, b, hi, lo);
    *(uint32_t*)hip = hi;
    *(uint32_t*)lop = lo;
}

__device__ __forceinline__ void hl4_store(float4 v, __nv_bfloat16* hip,
                                          __nv_bfloat16* lop) {
    hl2_store(v.x, v.y, hip, lop);
    hl2_store(v.z, v.w, hip + 2, lop + 2);
}

// ---------------------------------------------------------------------------
// Kernel 0: mask preprocessing + bias concat
// ---------------------------------------------------------------------------
__global__ __launch_bounds__(256)
void prep_kernel(const void* __restrict__ mask,
                 const float* __restrict__ bq,
                 const float* __restrict__ bk,
                 const float* __restrict__ bv)
{
    __shared__ int s_packed;
    if (threadIdx.x == 0) s_packed = 0;
    __syncthreads();

    const unsigned* mw = (const unsigned*)mask;
    int bad = 0;
    for (int i = threadIdx.x; i < 2048; i += 256)
        if (mw[i] > 1u) bad = 1;
    if (bad) atomicOr(&s_packed, 1);
    __syncthreads();
    const bool packed = (s_packed != 0);

    const int* mi = (const int*)mask;
    const unsigned char* mb = (const unsigned char*)mask;
    for (int i = threadIdx.x; i < BB * NN; i += 256) {
        const int on = packed ? (int)mb[i] : mi[i];
        g_maskbias[i] = on ? 0.0f : -1e30f;
    }
    for (int i = threadIdx.x; i < DD; i += 256) {
        g_bqkv[i]          = bq[i];
        g_bqkv[DD + i]     = bk[i];
        g_bqkv[2 * DD + i] = bv[i];
    }
}

// ---------------------------------------------------------------------------
// Kernel W: split all four W[1024x1024] into hi/lo bf16 (grid.y = slot)
// ---------------------------------------------------------------------------
__global__ __launch_bounds__(256)
void wconv_kernel(const float* __restrict__ W0, const float* __restrict__ W1,
                  const float* __restrict__ W2, const float* __restrict__ W3)
{
    const int slot = blockIdx.y;
    const float* W = (slot == 0) ? W0 : (slot == 1) ? W1 : (slot == 2) ? W2 : W3;
    const size_t i = ((size_t)blockIdx.x * 256 + threadIdx.x) * 4;
    float4 v = *(const float4*)(W + i);
    const size_t off = (size_t)slot * DD * DD + i;
    hl4_store(v, g_whi + off, g_wlo + off);
}

// ---------------------------------------------------------------------------
// Kernel 1: row LayerNorm over D=1024 -> hi/lo bf16
// ---------------------------------------------------------------------------
__global__ __launch_bounds__(256)
void ln_x_kernel(const float* __restrict__ x,
                 const float* __restrict__ w,
                 const float* __restrict__ b)
{
    __shared__ float red_s[8];
    __shared__ float red_q[8];
    __shared__ float stats[2];
    const int row = blockIdx.x;
    const int t = threadIdx.x;
    const int lane = t & 31, warp = t >> 5;

    const float* xr = x + (long)row * DD;
    float4 xv = *(const float4*)(xr + t * 4);
    float sum = xv.x + xv.y + xv.z + xv.w;
    float ssq = fmaf(xv.x, xv.x, fmaf(xv.y, xv.y, fmaf(xv.z, xv.z, xv.w * xv.w)));
    #pragma unroll
    for (int o = 16; o > 0; o >>= 1) {
        sum += __shfl_xor_sync(0xffffffffu, sum, o);
        ssq += __shfl_xor_sync(0xffffffffu, ssq, o);
    }
    if (lane == 0) { red_s[warp] = sum; red_q[warp] = ssq; }
    __syncthreads();
    if (warp == 0) {
        float a = (lane < 8) ? red_s[lane] : 0.0f;
        float c = (lane < 8) ? red_q[lane] : 0.0f;
        #pragma unroll
        for (int o = 4; o > 0; o >>= 1) {
            a += __shfl_xor_sync(0xffffffffu, a, o);
            c += __shfl_xor_sync(0xffffffffu, c, o);
        }
        if (lane == 0) { stats[0] = a * (1.0f / DD); stats[1] = c * (1.0f / DD); }
    }
    __syncthreads();
    const float mean = stats[0];
    const float var = stats[1] - mean * mean;
    const float rstd = rsqrtf(var + LN_EPS);

    float4 wv = *(const float4*)(w + t * 4);
    float4 bv = *(const float4*)(b + t * 4);
    float4 ov;
    ov.x = (xv.x - mean) * rstd * wv.x + bv.x;
    ov.y = (xv.y - mean) * rstd * wv.y + bv.y;
    ov.z = (xv.z - mean) * rstd * wv.z + bv.z;
    ov.w = (xv.w - mean) * rstd * wv.w + bv.w;
    const size_t off = (size_t)row * DD + t * 4;
    hl4_store(ov, g_xn_hi + off, g_xn_lo + off);
}

// ---------------------------------------------------------------------------
// Kernel 2: HMMA bf16x3 GEMM, cp.async double-buffered, K-slab 32.
// 128x128 CTA tile, 4 warps (2M x 2N), warp tile 64x64, 128 threads.
// MMA streams are PASS-MAJOR: same-accumulator dependency distance = 8.
// MODE 0: A=g_ao(hi/lo), B=Wo slot3, C=Cout plain (grid 8x64).
// MODE 4: fused QKV, A=g_xn, B=slots 0..2 (N=3072, grid 24x64),
//         scatter: q,k fp32 + bias; v hi/lo bf16 + bias.
// ---------------------------------------------------------------------------
#define KSL 32
#define SST2 40                              // 32 + 8 pad (80B rows)
#define BUF2 (128 * SST2)                    // 5120 elems
#define STAGE_ELE (4 * BUF2)                 // 20480 elems = 40960 B
#define GEMM_SMEM2 (2 * STAGE_ELE * 2)       // 81920 B

template<int MODE>
__global__ __launch_bounds__(128, 2)
void gemm_mma2(float* __restrict__ Cout)
{
    extern __shared__ __nv_bfloat16 smg[];
    const uint32_t u0 = s2u(smg);

    const int tid = threadIdx.x;
    const int wid = tid >> 5, lane = tid & 31;
    const int wm = (wid & 1) << 6;          // 0, 64
    const int wn = (wid >> 1) << 6;         // 0, 64
    const int bm = blockIdx.y << 7;
    const int bn = blockIdx.x << 7;

    const __nv_bfloat16* gAh = (MODE == 0) ? g_ao_hi : g_xn_hi;
    const __nv_bfloat16* gAl = (MODE == 0) ? g_ao_lo : g_xn_lo;
    const __nv_bfloat16* gBh = (MODE == 0) ? (g_whi + (size_t)3 * DD * DD) : g_whi;
    const __nv_bfloat16* gBl = (MODE == 0) ? (g_wlo + (size_t)3 * DD * DD) : g_wlo;

    float acc[4][8][4];
    #pragma unroll
    for (int i = 0; i < 4; i++)
        #pragma unroll
        for (int j = 0; j < 8; j++)
            #pragma unroll
            for (int k = 0; k < 4; k++) acc[i][j][k] = 0.0f;

    // cp.async: each thread owns one 64B row per buffer (4 x cpa16)
    const int lrow = tid;
    const __nv_bfloat16* pAh = gAh + (size_t)(bm + lrow) * DD;
    const __nv_bfloat16* pAl = gAl + (size_t)(bm + lrow) * DD;
    const __nv_bfloat16* pBh = gBh + (size_t)(bn + lrow) * DD;
    const __nv_bfloat16* pBl = gBl + (size_t)(bn + lrow) * DD;
    const uint32_t dbase = u0 + lrow * SST2 * 2;

    // ldmatrix lane addressing
    const int aRow = (lane & 7) + ((lane & 8) ? 8 : 0);
    const int aK   = (lane & 16) ? 8 : 0;
    const int bRow = (lane & 7) + ((lane & 16) ? 8 : 0);
    const int bK   = (lane & 8) ? 8 : 0;

    #define ISSUE_STAGE(kt, stg) do {                                        \
        const uint32_t d_ = dbase + (stg) * (STAGE_ELE * 2);                  \
        _Pragma("unroll")                                                     \
        for (int q_ = 0; q_ < 4; q_++) {                                      \
            cpa16(d_ + 0 * BUF2 * 2 + q_ * 16, pAh + (kt) + q_ * 8);          \
            cpa16(d_ + 1 * BUF2 * 2 + q_ * 16, pAl + (kt) + q_ * 8);          \
            cpa16(d_ + 2 * BUF2 * 2 + q_ * 16, pBh + (kt) + q_ * 8);          \
            cpa16(d_ + 3 * BUF2 * 2 + q_ * 16, pBl + (kt) + q_ * 8);          \
        }                                                                     \
        CP_COMMIT();                                                          \
    } while (0)

    ISSUE_STAGE(0, 0);

    const int NSLAB = DD / KSL;   // 32
    for (int s = 0; s < NSLAB; s++) {
        if (s + 1 < NSLAB) {
            ISSUE_STAGE((s + 1) * KSL, (s + 1) & 1);
            CP_WAIT(1);
        } else {
            CP_WAIT(0);
        }
        __syncthreads();

        const uint32_t sb = u0 + (s & 1) * (STAGE_ELE * 2);
        const uint32_t aAh = sb + ((wm + aRow) * SST2 + aK) * 2;
        const uint32_t aAl = aAh + BUF2 * 2;
        const uint32_t aBh = sb + 2 * BUF2 * 2 + ((wn + bRow) * SST2 + bK) * 2;
        const uint32_t aBl = aBh + BUF2 * 2;

        #pragma unroll
        for (int k16 = 0; k16 < 2; k16++) {
            const uint32_t koff = (k16 << 4) * 2;
            uint32_t ah[4][4], al[4][4];
            #pragma unroll
            for (int mt = 0; mt < 4; mt++) {
                const uint32_t moff = (mt << 4) * SST2 * 2;
                ldsm4(ah[mt][0], ah[mt][1], ah[mt][2], ah[mt][3], aAh + moff + koff);
                ldsm4(al[mt][0], al[mt][1], al[mt][2], al[mt][3], aAl + moff + koff);
            }
            #pragma unroll
            for (int p = 0; p < 4; p++) {
                const uint32_t noff = (p << 4) * SST2 * 2;
                uint32_t bh0, bh1, bh2, bh3, bl0, bl1, bl2, bl3;
                ldsm4(bh0, bh1, bh2, bh3, aBh + noff + koff);
                ldsm4(bl0, bl1, bl2, bl3, aBl + noff + koff);
                // pass hh (distance-8 accumulator reuse)
                #pragma unroll
                for (int mt = 0; mt < 4; mt++) {
                    mma16816(acc[mt][2 * p + 0], ah[mt], bh0, bh1);
                    mma16816(acc[mt][2 * p + 1], ah[mt], bh2, bh3);
                }
                // pass hl
                #pragma unroll
                for (int mt = 0; mt < 4; mt++) {
                    mma16816(acc[mt][2 * p + 0], ah[mt], bl0, bl1);
                    mma16816(acc[mt][2 * p + 1], ah[mt], bl2, bl3);
                }
                // pass lh
                #pragma unroll
                for (int mt = 0; mt < 4; mt++) {
                    mma16816(acc[mt][2 * p + 0], al[mt], bh0, bh1);
                    mma16816(acc[mt][2 * p + 1], al[mt], bh2, bh3);
                }
            }
        }
        __syncthreads();
    }
    #undef ISSUE_STAGE

    // Epilogue
    const int g = lane >> 2, tq = lane & 3;
    #pragma unroll
    for (int mt = 0; mt < 4; mt++) {
        #pragma unroll
        for (int nt = 0; nt < 8; nt++) {
            const int c = bn + wn + nt * 8 + 2 * tq;
            #pragma unroll
            for (int half = 0; half < 2; half++) {
                const int r = bm + wm + mt * 16 + g + half * 8;
                float2 v;
                v.x = acc[mt][nt][2 * half + 0];
                v.y = acc[mt][nt][2 * half + 1];
                if (MODE == 0) {
                    *(float2*)(Cout + (size_t)r * DD + c) = v;
                } else {
                    const float2 bv = *(const float2*)(g_bqkv + c);
                    v.x += bv.x; v.y += bv.y;
                    const int which = c >> 10;
                    const int cc = c & 1023;
                    const int h = cc >> 6;
                    const size_t idx = ((((size_t)((r >> 11) * HH + h)) * NN
                                        + (r & 2047)) << 6) + (cc & 63);
                    if (which == 0)      *(float2*)(g_q + idx) = v;
                    else if (which == 1) *(float2*)(g_k + idx) = v;
                    else                 hl2_store(v.x, v.y, g_vh + idx, g_vl + idx);
                }
            }
        }
    }
}

// ---------------------------------------------------------------------------
// Kernel 3: per-head LayerNorm over DH=64 -> hi/lo bf16 (grid.y: 0=q, 1=k)
// ---------------------------------------------------------------------------
__global__ __launch_bounds__(256)
void headln_kernel(const float* __restrict__ qw, const float* __restrict__ qb,
                   const float* __restrict__ kw, const float* __restrict__ kb)
{
    const int isq = (blockIdx.y == 0);
    const float* base = isq ? g_q : g_k;
    __nv_bfloat16* oh = isq ? g_qh : g_kh;
    __nv_bfloat16* ol = isq ? g_ql : g_kl;
    const float* w = isq ? qw : kw;
    const float* b = isq ? qb : kb;
    const float sc = isq ? 0.125f : 1.0f;

    const int warp = threadIdx.x >> 5;
    const int lane = threadIdx.x & 31;
    const long row = (long)blockIdx.x * 8 + warp;
    const float* p = base + row * DH;

    float2 xv = *(const float2*)(p + lane * 2);
    float sum = xv.x + xv.y;
    float ssq = fmaf(xv.x, xv.x, xv.y * xv.y);
    #pragma unroll
    for (int o = 16; o > 0; o >>= 1) {
        sum += __shfl_xor_sync(0xffffffffu, sum, o);
        ssq += __shfl_xor_sync(0xffffffffu, ssq, o);
    }
    const float mean = sum * (1.0f / DH);
    const float var = ssq * (1.0f / DH) - mean * mean;
    const float rstd = rsqrtf(var + LN_EPS);

    float2 wv = *(const float2*)(w + lane * 2);
    float2 bv = *(const float2*)(b + lane * 2);
    float a = ((xv.x - mean) * rstd * wv.x + bv.x) * sc;
    float c = ((xv.y - mean) * rstd * wv.y + bv.y) * sc;
    hl2_store(a, c, oh + row * DH + lane * 2, ol + row * DH + lane * 2);
}

// ---------------------------------------------------------------------------
// Kernel 4: tensor-core flash attention (bf16x3 QK^T and PV), pass-major MMA
// grid (16, 16, 4): 128 queries x one (b,h) per CTA; 8 warps x 16 q-rows.
// ---------------------------------------------------------------------------
#define ASTR 72

__global__ __launch_bounds__(256)
void attn_mma_kernel()
{
    __shared__ __align__(16) __nv_bfloat16 sm[4 * 64 * ASTR];  // 36864 B
    __shared__ float mb[64];

    const int tid = threadIdx.x, wid = tid >> 5, lane = tid & 31;
    const int bq = blockIdx.x << 7;
    const int h = blockIdx.y, b = blockIdx.z;
    const size_t head_off = ((size_t)(b * HH + h)) * NN;

    const uint32_t u0 = s2u(sm);
    const uint32_t Kh = u0;
    const uint32_t Kl = u0 + 64 * ASTR * 2;
    const uint32_t Vh = u0 + 2 * 64 * ASTR * 2;
    const uint32_t Vl = u0 + 3 * 64 * ASTR * 2;

    // ldmatrix lane addressing
    const int aRow = (lane & 7) + ((lane & 8) ? 8 : 0);
    const int aK   = (lane & 16) ? 8 : 0;
    const int bRow = (lane & 7) + ((lane & 16) ? 8 : 0);
    const int bK   = (lane & 8) ? 8 : 0;
    const int vRow = (lane & 7) + ((lane & 8) ? 8 : 0);
    const int vCol = (lane & 16) ? 8 : 0;

    // ---- Phase 1: stage Q hi then Q lo through rows [0,128) (two passes)
    uint32_t qh[4][4], ql[4][4];
    {
        const int r = tid >> 1;
        const int c = (tid & 1) << 5;
        const uint32_t qb = u0 + ((wid * 16 + aRow) * ASTR + aK) * 2;

        const __nv_bfloat16* sh = g_qh + (head_off + bq + r) * DH + c;
        #pragma unroll
        for (int i = 0; i < 4; i++)
            *(uint4*)(sm + r * ASTR + c + i * 8) = *(const uint4*)(sh + i * 8);
        __syncthreads();
        #pragma unroll
        for (int k = 0; k < 4; k++)
            ldsm4(qh[k][0], qh[k][1], qh[k][2], qh[k][3], qb + (k * 16) * 2);
        __syncthreads();

        const __nv_bfloat16* sl = g_ql + (head_off + bq + r) * DH + c;
        #pragma unroll
        for (int i = 0; i < 4; i++)
            *(uint4*)(sm + r * ASTR + c + i * 8) = *(const uint4*)(sl + i * 8);
        __syncthreads();
        #pragma unroll
        for (int k = 0; k < 4; k++)
            ldsm4(ql[k][0], ql[k][1], ql[k][2], ql[k][3], qb + (k * 16) * 2);
    }

    float o[8][4];
    #pragma unroll
    for (int i = 0; i < 8; i++)
        #pragma unroll
        for (int j = 0; j < 4; j++) o[i][j] = 0.0f;
    float m0 = -1e30f, m1 = -1e30f, l0 = 0.0f, l1 = 0.0f;

    const float* mrow = g_maskbias + b * NN;
    const int tq2 = (lane & 3) * 2;

    for (int kt = 0; kt < NN; kt += 64) {
        __syncthreads();
        // load K/V tiles (bf16 hi/lo, pre-split)
        {
            const int r = tid >> 2;
            const int c = (tid & 3) << 4;
            const size_t gidx = (head_off + kt + r) * DH + c;
            const int so = r * ASTR + c;
            #pragma unroll
            for (int i = 0; i < 2; i++) {
                *(uint4*)(sm + so + i * 8)                 = *(const uint4*)(g_kh + gidx + i * 8);
                *(uint4*)(sm + 64 * ASTR + so + i * 8)     = *(const uint4*)(g_kl + gidx + i * 8);
                *(uint4*)(sm + 2 * 64 * ASTR + so + i * 8) = *(const uint4*)(g_vh + gidx + i * 8);
                *(uint4*)(sm + 3 * 64 * ASTR + so + i * 8) = *(const uint4*)(g_vl + gidx + i * 8);
            }
            if (tid < 64) mb[tid] = mrow[kt + tid];
        }
        __syncthreads();

        // S = Q K^T  (bf16x3), pass-major: same-acc distance = 8
        float s[8][4];
        #pragma unroll
        for (int i = 0; i < 8; i++)
            #pragma unroll
            for (int j = 0; j < 4; j++) s[i][j] = 0.0f;

        #pragma unroll
        for (int k = 0; k < 4; k++) {
            uint32_t kh[4][4], kl[4][4];
            #pragma unroll
            for (int p = 0; p < 4; p++) {
                const uint32_t nb = ((p * 16 + bRow) * ASTR + k * 16 + bK) * 2;
                ldsm4(kh[p][0], kh[p][1], kh[p][2], kh[p][3], Kh + nb);
                ldsm4(kl[p][0], kl[p][1], kl[p][2], kl[p][3], Kl + nb);
            }
            // pass hh
            #pragma unroll
            for (int p = 0; p < 4; p++) {
                mma16816(s[2 * p + 0], qh[k], kh[p][0], kh[p][1]);
                mma16816(s[2 * p + 1], qh[k], kh[p][2], kh[p][3]);
            }
            // pass hl
            #pragma unroll
            for (int p = 0; p < 4; p++) {
                mma16816(s[2 * p + 0], qh[k], kl[p][0], kl[p][1]);
                mma16816(s[2 * p + 1], qh[k], kl[p][2], kl[p][3]);
            }
            // pass lh
            #pragma unroll
            for (int p = 0; p < 4; p++) {
                mma16816(s[2 * p + 0], ql[k], kh[p][0], kh[p][1]);
                mma16816(s[2 * p + 1], ql[k], kh[p][2], kh[p][3]);
            }
        }

        // mask + online softmax
        float mx0 = -1e30f, mx1 = -1e30f;
        #pragma unroll
        for (int nt = 0; nt < 8; nt++) {
            const float b0 = mb[nt * 8 + tq2];
            const float b1 = mb[nt * 8 + tq2 + 1];
            s[nt][0] += b0; s[nt][1] += b1;
            s[nt][2] += b0; s[nt][3] += b1;
            mx0 = fmaxf(mx0, fmaxf(s[nt][0], s[nt][1]));
            mx1 = fmaxf(mx1, fmaxf(s[nt][2], s[nt][3]));
        }
        mx0 = fmaxf(mx0, __shfl_xor_sync(0xffffffffu, mx0, 1));
        mx0 = fmaxf(mx0, __shfl_xor_sync(0xffffffffu, mx0, 2));
        mx1 = fmaxf(mx1, __shfl_xor_sync(0xffffffffu, mx1, 1));
        mx1 = fmaxf(mx1, __shfl_xor_sync(0xffffffffu, mx1, 2));
        const float mn0 = fmaxf(m0, mx0), mn1 = fmaxf(m1, mx1);
        const float sc0 = __expf(m0 - mn0), sc1 = __expf(m1 - mn1);
        m0 = mn0; m1 = mn1;
        float ps0 = 0.0f, ps1 = 0.0f;
        #pragma unroll
        for (int nt = 0; nt < 8; nt++) {
            s[nt][0] = __expf(s[nt][0] - m0);
            s[nt][1] = __expf(s[nt][1] - m0);
            s[nt][2] = __expf(s[nt][2] - m1);
            s[nt][3] = __expf(s[nt][3] - m1);
            ps0 += s[nt][0] + s[nt][1];
            ps1 += s[nt][2] + s[nt][3];
        }
        ps0 += __shfl_xor_sync(0xffffffffu, ps0, 1);
        ps0 += __shfl_xor_sync(0xffffffffu, ps0, 2);
        ps1 += __shfl_xor_sync(0xffffffffu, ps1, 1);
        ps1 += __shfl_xor_sync(0xffffffffu, ps1, 2);
        l0 = l0 * sc0 + ps0;
        l1 = l1 * sc1 + ps1;
        #pragma unroll
        for (int nt = 0; nt < 8; nt++) {
            o[nt][0] *= sc0; o[nt][1] *= sc0;
            o[nt][2] *= sc1; o[nt][3] *= sc1;
        }

        // O += P V   (P hi/lo x V hi/lo, 3 passes; p processed in pairs
        //             -> same-acc distance = 4)
        #pragma unroll
        for (int jj = 0; jj < 4; jj++) {
            uint32_t ph[4], pl[4];
            hl_pack(s[2 * jj][0],     s[2 * jj][1],     ph[0], pl[0]);
            hl_pack(s[2 * jj][2],     s[2 * jj][3],     ph[1], pl[1]);
            hl_pack(s[2 * jj + 1][0], s[2 * jj + 1][1], ph[2], pl[2]);
            hl_pack(s[2 * jj + 1][2], s[2 * jj + 1][3], ph[3], pl[3]);
            #pragma unroll
            for (int pp = 0; pp < 2; pp++) {
                uint32_t vh[2][4], vl[2][4];
                #pragma unroll
                for (int q = 0; q < 2; q++) {
                    const int p = pp * 2 + q;
                    const uint32_t off = ((jj * 16 + vRow) * ASTR + p * 16 + vCol) * 2;
                    ldsm4t(vh[q][0], vh[q][1], vh[q][2], vh[q][3], Vh + off);
                    ldsm4t(vl[q][0], vl[q][1], vl[q][2], vl[q][3], Vl + off);
                }
                // pass P-hi x V-hi
                #pragma unroll
                for (int q = 0; q < 2; q++) {
                    const int p = pp * 2 + q;
                    mma16816(o[2 * p + 0], ph, vh[q][0], vh[q][1]);
                    mma16816(o[2 * p + 1], ph, vh[q][2], vh[q][3]);
                }
                // pass P-hi x V-lo
                #pragma unroll
                for (int q = 0; q < 2; q++) {
                    const int p = pp * 2 + q;
                    mma16816(o[2 * p + 0], ph, vl[q][0], vl[q][1]);
                    mma16816(o[2 * p + 1], ph, vl[q][2], vl[q][3]);
                }
                // pass P-lo x V-hi
                #pragma unroll
                for (int q = 0; q < 2; q++) {
                    const int p = pp * 2 + q;
                    mma16816(o[2 * p + 0], pl, vh[q][0], vh[q][1]);
                    mma16816(o[2 * p + 1], pl, vh[q][2], vh[q][3]);
                }
            }
        }
    }

    // epilogue -> g_ao hi/lo   [b, n, h*64+dh]
    const float inv0 = 1.0f / l0, inv1 = 1.0f / l1;
    const int g = lane >> 2;
    const int q0 = bq + wid * 16 + g;
    const size_t ob = ((size_t)(b * NN) + q0) * DD + h * DH;
    #pragma unroll
    for (int nt = 0; nt < 8; nt++) {
        const int dh = nt * 8 + tq2;
        hl2_store(o[nt][0] * inv0, o[nt][1] * inv0, g_ao_hi + ob + dh, g_ao_lo + ob + dh);
        hl2_store(o[nt][2] * inv1, o[nt][3] * inv1,
                  g_ao_hi + ob + 8 * DD + dh, g_ao_lo + ob + 8 * DD + dh);
    }
}

// ---------------------------------------------------------------------------
// Launch
// ---------------------------------------------------------------------------
extern "C" void kernel_launch(void* const* d_in, const int* in_sizes, int n_in,
                              void* d_out, int out_size)
{
    const float* x       = (const float*)d_in[0];
    const void*  mask    = (const void*)d_in[1];
    const float* norm_w  = (const float*)d_in[2];
    const float* norm_b  = (const float*)d_in[3];
    const float* qn_w    = (const float*)d_in[4];
    const float* qn_b    = (const float*)d_in[5];
    const float* kn_w    = (const float*)d_in[6];
    const float* kn_b    = (const float*)d_in[7];
    const float* Wq      = (const float*)d_in[8];
    const float* bq      = (const float*)d_in[9];
    const float* Wk      = (const float*)d_in[10];
    const float* bk      = (const float*)d_in[11];
    const float* Wv      = (const float*)d_in[12];
    const float* bv      = (const float*)d_in[13];
    const float* Wo      = (const float*)d_in[14];
    float* out = (float*)d_out;

    static bool attr_done = false;
    if (!attr_done) {
        cudaFuncSetAttribute(gemm_mma2<0>, cudaFuncAttributeMaxDynamicSharedMemorySize, GEMM_SMEM2);
        cudaFuncSetAttribute(gemm_mma2<4>, cudaFuncAttributeMaxDynamicSharedMemorySize, GEMM_SMEM2);
        attr_done = true;
    }

    // 0. Mask -> float bias; bias concat; W -> hi/lo bf16
    prep_kernel<<<1, 256>>>(mask, bq, bk, bv);
    wconv_kernel<<<dim3(1024, 4), 256>>>(Wq, Wk, Wv, Wo);

    // 1. LN(x) -> hi/lo bf16
    ln_x_kernel<<<BN, 256>>>(x, norm_w, norm_b);

    // 2. Fused QKV projection (cp.async pipelined HMMA bf16x3)
    gemm_mma2<4><<<dim3(3 * DD / 128, BN / 128), 128, GEMM_SMEM2>>>(nullptr);

    // 3. Per-head LN -> q/k hi/lo bf16 (q scaled by DH^-0.5)
    headln_kernel<<<dim3((BB * HH * NN) / 8, 2), 256>>>(qn_w, qn_b, kn_w, kn_b);

    // 4. Tensor-core flash attention -> g_ao hi/lo
    attn_mma_kernel<<<dim3(NN / 128, HH, BB), 256>>>();

    // 5. Output projection -> d_out
    gemm_mma2<0><<<dim3(DD / 128, BN / 128), 128, GEMM_SMEM2>>>(out);
}

// round 11
// speedup vs baseline: 1.1643x; 1.1637x over previous
#include <cuda_runtime.h>
#include <cuda_bf16.h>
#include <cstdint>

// Problem constants
#define BB 4
#define NN 2048
#define DD 1024
#define HH 16
#define DH 64
#define BN (BB*NN)          // 8192
#define LN_EPS 1e-5f

// ---------------------------------------------------------------------------
// Device scratch (no allocation allowed)
// ---------------------------------------------------------------------------
__device__ __nv_bfloat16 g_xn_hi[BN * DD];
__device__ __nv_bfloat16 g_xn_lo[BN * DD];
__device__ __nv_bfloat16 g_ao_hi[BN * DD];
__device__ __nv_bfloat16 g_ao_lo[BN * DD];
__device__ __nv_bfloat16 g_whi[4 * DD * DD];
__device__ __nv_bfloat16 g_wlo[4 * DD * DD];
__device__ float g_q[BB * HH * NN * DH];
__device__ float g_k[BB * HH * NN * DH];
__device__ __nv_bfloat16 g_qh[BB * HH * NN * DH];
__device__ __nv_bfloat16 g_ql[BB * HH * NN * DH];
__device__ __nv_bfloat16 g_kh[BB * HH * NN * DH];
__device__ __nv_bfloat16 g_kl[BB * HH * NN * DH];
__device__ __nv_bfloat16 g_vh[BB * HH * NN * DH];
__device__ __nv_bfloat16 g_vl[BB * HH * NN * DH];
__device__ float g_maskbias[BB * NN];
__device__ float g_bqkv[3 * DD];

// ---------------------------------------------------------------------------
// Helpers
// ---------------------------------------------------------------------------
__device__ __forceinline__ uint32_t s2u(const void* p) {
    uint32_t a;
    asm("{ .reg .u64 t; cvta.to.shared.u64 t, %1; cvt.u32.u64 %0, t; }"
        : "=r"(a) : "l"(p));
    return a;
}

__device__ __forceinline__ void cpa16(uint32_t dst, const void* src) {
    asm volatile("cp.async.cg.shared.global [%0], [%1], 16;"
                 :: "r"(dst), "l"(src) : "memory");
}
#define CP_COMMIT() asm volatile("cp.async.commit_group;" ::: "memory")
#define CP_WAIT(N)  asm volatile("cp.async.wait_group %0;" :: "n"(N) : "memory")

__device__ __forceinline__ void ldsm4(uint32_t& r0, uint32_t& r1,
                                      uint32_t& r2, uint32_t& r3,
                                      uint32_t addr) {
    asm volatile("ldmatrix.sync.aligned.m8n8.x4.shared.b16 {%0,%1,%2,%3}, [%4];"
                 : "=r"(r0), "=r"(r1), "=r"(r2), "=r"(r3) : "r"(addr));
}

__device__ __forceinline__ void ldsm4t(uint32_t& r0, uint32_t& r1,
                                       uint32_t& r2, uint32_t& r3,
                                       uint32_t addr) {
    asm volatile("ldmatrix.sync.aligned.m8n8.x4.trans.shared.b16 {%0,%1,%2,%3}, [%4];"
                 : "=r"(r0), "=r"(r1), "=r"(r2), "=r"(r3) : "r"(addr));
}

__device__ __forceinline__ void mma16816(float* c, const uint32_t* a,
                                         uint32_t b0, uint32_t b1) {
    asm volatile(
        "mma.sync.aligned.m16n8k16.row.col.f32.bf16.bf16.f32 "
        "{%0,%1,%2,%3}, {%4,%5,%6,%7}, {%8,%9}, {%0,%1,%2,%3};"
        : "+f"(c[0]), "+f"(c[1]), "+f"(c[2]), "+f"(c[3])
        : "r"(a[0]), "r"(a[1]), "r"(a[2]), "r"(a[3]), "r"(b0), "r"(b1));
}

// hi/lo bf16 split of a float pair -> two packed bf16x2 regs
__device__ __forceinline__ void hl_pack(float a, float b, uint32_t& hi, uint32_t& lo) {
    __nv_bfloat162 h = __float22bfloat162_rn(make_float2(a, b));
    float2 f = __bfloat1622float2(h);
    __nv_bfloat162 l = __float22bfloat162_rn(make_float2(a - f.x, b - f.y));
    hi = *reinterpret_cast<uint32_t*>(&h);
    lo = *reinterpret_cast<uint32_t*>(&l);
}

__device__ __forceinline__ void hl2_store(float a, float b,
                                          __nv_bfloat16* hip, __nv_bfloat16* lop) {
    uint32_t hi, lo;
    hl_pack(a, b, hi, lo);
    *(uint32_t*)hip = hi;
    *(uint32_t*)lop = lo;
}

__device__ __forceinline__ void hl4_store(float4 v, __nv_bfloat16* hip,
                                          __nv_bfloat16* lop) {
    hl2_store(v.x, v.y, hip, lop);
    hl2_store(v.z, v.w, hip + 2, lop + 2);
}

// ---------------------------------------------------------------------------
// Kernel 0: mask preprocessing + bias concat
// ---------------------------------------------------------------------------
__global__ __launch_bounds__(256)
void prep_kernel(const void* __restrict__ mask,
                 const float* __restrict__ bq,
                 const float* __restrict__ bk,
                 const float* __restrict__ bv)
{
    __shared__ int s_packed;
    if (threadIdx.x == 0) s_packed = 0;
    __syncthreads();

    const unsigned* mw = (const unsigned*)mask;
    int bad = 0;
    for (int i = threadIdx.x; i < 2048; i += 256)
        if (mw[i] > 1u) bad = 1;
    if (bad) atomicOr(&s_packed, 1);
    __syncthreads();
    const bool packed = (s_packed != 0);

    const int* mi = (const int*)mask;
    const unsigned char* mb = (const unsigned char*)mask;
    for (int i = threadIdx.x; i < BB * NN; i += 256) {
        const int on = packed ? (int)mb[i] : mi[i];
        g_maskbias[i] = on ? 0.0f : -1e30f;
    }
    for (int i = threadIdx.x; i < DD; i += 256) {
        g_bqkv[i]          = bq[i];
        g_bqkv[DD + i]     = bk[i];
        g_bqkv[2 * DD + i] = bv[i];
    }
}

// ---------------------------------------------------------------------------
// Kernel W: split all four W[1024x1024] into hi/lo bf16 (grid.y = slot)
// ---------------------------------------------------------------------------
__global__ __launch_bounds__(256)
void wconv_kernel(const float* __restrict__ W0, const float* __restrict__ W1,
                  const float* __restrict__ W2, const float* __restrict__ W3)
{
    const int slot = blockIdx.y;
    const float* W = (slot == 0) ? W0 : (slot == 1) ? W1 : (slot == 2) ? W2 : W3;
    const size_t i = ((size_t)blockIdx.x * 256 + threadIdx.x) * 4;
    float4 v = *(const float4*)(W + i);
    const size_t off = (size_t)slot * DD * DD + i;
    hl4_store(v, g_whi + off, g_wlo + off);
}

// ---------------------------------------------------------------------------
// Kernel 1: row LayerNorm over D=1024 -> hi/lo bf16
// ---------------------------------------------------------------------------
__global__ __launch_bounds__(256)
void ln_x_kernel(const float* __restrict__ x,
                 const float* __restrict__ w,
                 const float* __restrict__ b)
{
    __shared__ float red_s[8];
    __shared__ float red_q[8];
    __shared__ float stats[2];
    const int row = blockIdx.x;
    const int t = threadIdx.x;
    const int lane = t & 31, warp = t >> 5;

    const float* xr = x + (long)row * DD;
    float4 xv = *(const float4*)(xr + t * 4);
    float sum = xv.x + xv.y + xv.z + xv.w;
    float ssq = fmaf(xv.x, xv.x, fmaf(xv.y, xv.y, fmaf(xv.z, xv.z, xv.w * xv.w)));
    #pragma unroll
    for (int o = 16; o > 0; o >>= 1) {
        sum += __shfl_xor_sync(0xffffffffu, sum, o);
        ssq += __shfl_xor_sync(0xffffffffu, ssq, o);
    }
    if (lane == 0) { red_s[warp] = sum; red_q[warp] = ssq; }
    __syncthreads();
    if (warp == 0) {
        float a = (lane < 8) ? red_s[lane] : 0.0f;
        float c = (lane < 8) ? red_q[lane] : 0.0f;
        #pragma unroll
        for (int o = 4; o > 0; o >>= 1) {
            a += __shfl_xor_sync(0xffffffffu, a, o);
            c += __shfl_xor_sync(0xffffffffu, c, o);
        }
        if (lane == 0) { stats[0] = a * (1.0f / DD); stats[1] = c * (1.0f / DD); }
    }
    __syncthreads();
    const float mean = stats[0];
    const float var = stats[1] - mean * mean;
    const float rstd = rsqrtf(var + LN_EPS);

    float4 wv = *(const float4*)(w + t * 4);
    float4 bv = *(const float4*)(b + t * 4);
    float4 ov;
    ov.x = (xv.x - mean) * rstd * wv.x + bv.x;
    ov.y = (xv.y - mean) * rstd * wv.y + bv.y;
    ov.z = (xv.z - mean) * rstd * wv.z + bv.z;
    ov.w = (xv.w - mean) * rstd * wv.w + bv.w;
    const size_t off = (size_t)row * DD + t * 4;
    hl4_store(ov, g_xn_hi + off, g_xn_lo + off);
}

// ---------------------------------------------------------------------------
// Kernel 2: HMMA bf16x3 GEMM, cp.async double-buffered, K-slab 32.
// 128x128 CTA tile, 8 warps (4M x 2N), warp tile 32x64, 256 threads,
// launch_bounds(256,2) -> 16 warps/SM.
// MODE 0: A=g_ao(hi/lo), B=Wo slot3, C=Cout plain (grid 8x64).
// MODE 4: fused QKV, A=g_xn, B=slots 0..2 (N=3072, grid 24x64),
//         scatter: q,k fp32 + bias; v hi/lo bf16 + bias.
// ---------------------------------------------------------------------------
#define KSL 32
#define SST2 40                              // 32 + 8 pad (80B rows)
#define BUF2 (128 * SST2)                    // 5120 elems
#define STAGE_ELE (4 * BUF2)                 // 20480 elems = 40960 B
#define GEMM_SMEM2 (2 * STAGE_ELE * 2)       // 81920 B

template<int MODE>
__global__ __launch_bounds__(256, 2)
void gemm_mma2(float* __restrict__ Cout)
{
    extern __shared__ __nv_bfloat16 smg[];
    const uint32_t u0 = s2u(smg);

    const int tid = threadIdx.x;
    const int wid = tid >> 5, lane = tid & 31;
    const int wm = (wid & 3) << 5;          // 0,32,64,96
    const int wn = (wid >> 2) << 6;         // 0, 64
    const int bm = blockIdx.y << 7;
    const int bn = blockIdx.x << 7;

    const __nv_bfloat16* gAh = (MODE == 0) ? g_ao_hi : g_xn_hi;
    const __nv_bfloat16* gAl = (MODE == 0) ? g_ao_lo : g_xn_lo;
    const __nv_bfloat16* gBh = (MODE == 0) ? (g_whi + (size_t)3 * DD * DD) : g_whi;
    const __nv_bfloat16* gBl = (MODE == 0) ? (g_wlo + (size_t)3 * DD * DD) : g_wlo;

    float acc[2][8][4];
    #pragma unroll
    for (int i = 0; i < 2; i++)
        #pragma unroll
        for (int j = 0; j < 8; j++)
            #pragma unroll
            for (int k = 0; k < 4; k++) acc[i][j][k] = 0.0f;

    // cp.async: thread -> (row = tid>>1, 16-elem half)
    const int lrow = tid >> 1;
    const int lhalf = (tid & 1) << 4;
    const __nv_bfloat16* pAh = gAh + (size_t)(bm + lrow) * DD + lhalf;
    const __nv_bfloat16* pAl = gAl + (size_t)(bm + lrow) * DD + lhalf;
    const __nv_bfloat16* pBh = gBh + (size_t)(bn + lrow) * DD + lhalf;
    const __nv_bfloat16* pBl = gBl + (size_t)(bn + lrow) * DD + lhalf;
    const uint32_t dbase = u0 + (lrow * SST2 + lhalf) * 2;

    // ldmatrix lane addressing
    const int aRow = (lane & 7) + ((lane & 8) ? 8 : 0);
    const int aK   = (lane & 16) ? 8 : 0;
    const int bRow = (lane & 7) + ((lane & 16) ? 8 : 0);
    const int bK   = (lane & 8) ? 8 : 0;

    #define ISSUE_STAGE(kt, stg) do {                                        \
        const uint32_t d_ = dbase + (stg) * (STAGE_ELE * 2);                  \
        cpa16(d_ + 0 * BUF2 * 2,      pAh + (kt));                            \
        cpa16(d_ + 0 * BUF2 * 2 + 16, pAh + (kt) + 8);                        \
        cpa16(d_ + 1 * BUF2 * 2,      pAl + (kt));                            \
        cpa16(d_ + 1 * BUF2 * 2 + 16, pAl + (kt) + 8);                        \
        cpa16(d_ + 2 * BUF2 * 2,      pBh + (kt));                            \
        cpa16(d_ + 2 * BUF2 * 2 + 16, pBh + (kt) + 8);                        \
        cpa16(d_ + 3 * BUF2 * 2,      pBl + (kt));                            \
        cpa16(d_ + 3 * BUF2 * 2 + 16, pBl + (kt) + 8);                        \
        CP_COMMIT();                                                          \
    } while (0)

    ISSUE_STAGE(0, 0);

    const int NSLAB = DD / KSL;   // 32
    for (int s = 0; s < NSLAB; s++) {
        if (s + 1 < NSLAB) {
            ISSUE_STAGE((s + 1) * KSL, (s + 1) & 1);
            CP_WAIT(1);
        } else {
            CP_WAIT(0);
        }
        __syncthreads();

        const uint32_t sb = u0 + (s & 1) * (STAGE_ELE * 2);
        const uint32_t aAh = sb + ((wm + aRow) * SST2 + aK) * 2;
        const uint32_t aAl = aAh + BUF2 * 2;
        const uint32_t aBh = sb + 2 * BUF2 * 2 + ((wn + bRow) * SST2 + bK) * 2;
        const uint32_t aBl = aBh + BUF2 * 2;

        #pragma unroll
        for (int k16 = 0; k16 < 2; k16++) {
            const uint32_t koff = (k16 << 4) * 2;
            uint32_t ah[2][4], al[2][4];
            #pragma unroll
            for (int mt = 0; mt < 2; mt++) {
                const uint32_t moff = (mt << 4) * SST2 * 2;
                ldsm4(ah[mt][0], ah[mt][1], ah[mt][2], ah[mt][3], aAh + moff + koff);
                ldsm4(al[mt][0], al[mt][1], al[mt][2], al[mt][3], aAl + moff + koff);
            }
            #pragma unroll
            for (int p = 0; p < 4; p++) {
                const uint32_t noff = (p << 4) * SST2 * 2;
                uint32_t bh0, bh1, bh2, bh3, bl0, bl1, bl2, bl3;
                ldsm4(bh0, bh1, bh2, bh3, aBh + noff + koff);
                ldsm4(bl0, bl1, bl2, bl3, aBl + noff + koff);
                // pass hh
                #pragma unroll
                for (int mt = 0; mt < 2; mt++) {
                    mma16816(acc[mt][2 * p + 0], ah[mt], bh0, bh1);
                    mma16816(acc[mt][2 * p + 1], ah[mt], bh2, bh3);
                }
                // pass hl
                #pragma unroll
                for (int mt = 0; mt < 2; mt++) {
                    mma16816(acc[mt][2 * p + 0], ah[mt], bl0, bl1);
                    mma16816(acc[mt][2 * p + 1], ah[mt], bl2, bl3);
                }
                // pass lh
                #pragma unroll
                for (int mt = 0; mt < 2; mt++) {
                    mma16816(acc[mt][2 * p + 0], al[mt], bh0, bh1);
                    mma16816(acc[mt][2 * p + 1], al[mt], bh2, bh3);
                }
            }
        }
        __syncthreads();
    }
    #undef ISSUE_STAGE

    // Epilogue
    const int g = lane >> 2, tq = lane & 3;
    #pragma unroll
    for (int mt = 0; mt < 2; mt++) {
        #pragma unroll
        for (int nt = 0; nt < 8; nt++) {
            const int c = bn + wn + nt * 8 + 2 * tq;
            #pragma unroll
            for (int half = 0; half < 2; half++) {
                const int r = bm + wm + mt * 16 + g + half * 8;
                float2 v;
                v.x = acc[mt][nt][2 * half + 0];
                v.y = acc[mt][nt][2 * half + 1];
                if (MODE == 0) {
                    *(float2*)(Cout + (size_t)r * DD + c) = v;
                } else {
                    const float2 bv = *(const float2*)(g_bqkv + c);
                    v.x += bv.x; v.y += bv.y;
                    const int which = c >> 10;
                    const int cc = c & 1023;
                    const int h = cc >> 6;
                    const size_t idx = ((((size_t)((r >> 11) * HH + h)) * NN
                                        + (r & 2047)) << 6) + (cc & 63);
                    if (which == 0)      *(float2*)(g_q + idx) = v;
                    else if (which == 1) *(float2*)(g_k + idx) = v;
                    else                 hl2_store(v.x, v.y, g_vh + idx, g_vl + idx);
                }
            }
        }
    }
}

// ---------------------------------------------------------------------------
// Kernel 3: per-head LayerNorm over DH=64 -> hi/lo bf16 (grid.y: 0=q, 1=k)
// ---------------------------------------------------------------------------
__global__ __launch_bounds__(256)
void headln_kernel(const float* __restrict__ qw, const float* __restrict__ qb,
                   const float* __restrict__ kw, const float* __restrict__ kb)
{
    const int isq = (blockIdx.y == 0);
    const float* base = isq ? g_q : g_k;
    __nv_bfloat16* oh = isq ? g_qh : g_kh;
    __nv_bfloat16* ol = isq ? g_ql : g_kl;
    const float* w = isq ? qw : kw;
    const float* b = isq ? qb : kb;
    const float sc = isq ? 0.125f : 1.0f;

    const int warp = threadIdx.x >> 5;
    const int lane = threadIdx.x & 31;
    const long row = (long)blockIdx.x * 8 + warp;
    const float* p = base + row * DH;

    float2 xv = *(const float2*)(p + lane * 2);
    float sum = xv.x + xv.y;
    float ssq = fmaf(xv.x, xv.x, xv.y * xv.y);
    #pragma unroll
    for (int o = 16; o > 0; o >>= 1) {
        sum += __shfl_xor_sync(0xffffffffu, sum, o);
        ssq += __shfl_xor_sync(0xffffffffu, ssq, o);
    }
    const float mean = sum * (1.0f / DH);
    const float var = ssq * (1.0f / DH) - mean * mean;
    const float rstd = rsqrtf(var + LN_EPS);

    float2 wv = *(const float2*)(w + lane * 2);
    float2 bv = *(const float2*)(b + lane * 2);
    float a = ((xv.x - mean) * rstd * wv.x + bv.x) * sc;
    float c = ((xv.y - mean) * rstd * wv.y + bv.y) * sc;
    hl2_store(a, c, oh + row * DH + lane * 2, ol + row * DH + lane * 2);
}

// ---------------------------------------------------------------------------
// Kernel 4: tensor-core flash attention (bf16x3 QK^T and PV),
// cp.async double-buffered K/V/mask tiles.
// grid (16, 16, 4): 128 queries x one (b,h) per CTA; 8 warps x 16 q-rows.
// ---------------------------------------------------------------------------
#define ASTR 72
#define ATT_STAGE (4 * 64 * ASTR)                 // elems per stage (18432)
#define ATT_SMEM (2 * ATT_STAGE * 2 + 2 * 64 * 4) // 74240 B

__global__ __launch_bounds__(256)
void attn_mma_kernel()
{
    extern __shared__ __nv_bfloat16 sma[];
    const uint32_t u0 = s2u(sma);
    float* mbs = (float*)(sma + 2 * ATT_STAGE);
    const uint32_t mb_u = u0 + 2 * ATT_STAGE * 2;

    const int tid = threadIdx.x, wid = tid >> 5, lane = tid & 31;
    const int bq = blockIdx.x << 7;
    const int h = blockIdx.y, b = blockIdx.z;
    const size_t head_off = ((size_t)(b * HH + h)) * NN;

    // ldmatrix lane addressing
    const int aRow = (lane & 7) + ((lane & 8) ? 8 : 0);
    const int aK   = (lane & 16) ? 8 : 0;
    const int bRow = (lane & 7) + ((lane & 16) ? 8 : 0);
    const int bK   = (lane & 8) ? 8 : 0;
    const int vRow = (lane & 7) + ((lane & 8) ? 8 : 0);
    const int vCol = (lane & 16) ? 8 : 0;

    // ---- Phase 1: stage Q hi then Q lo through rows [0,128) (two passes)
    uint32_t qh[4][4], ql[4][4];
    {
        const int r = tid >> 1;
        const int c = (tid & 1) << 5;
        const uint32_t qb = u0 + ((wid * 16 + aRow) * ASTR + aK) * 2;

        const __nv_bfloat16* sh = g_qh + (head_off + bq + r) * DH + c;
        #pragma unroll
        for (int i = 0; i < 4; i++)
            *(uint4*)(sma + r * ASTR + c + i * 8) = *(const uint4*)(sh + i * 8);
        __syncthreads();
        #pragma unroll
        for (int k = 0; k < 4; k++)
            ldsm4(qh[k][0], qh[k][1], qh[k][2], qh[k][3], qb + (k * 16) * 2);
        __syncthreads();

        const __nv_bfloat16* sl = g_ql + (head_off + bq + r) * DH + c;
        #pragma unroll
        for (int i = 0; i < 4; i++)
            *(uint4*)(sma + r * ASTR + c + i * 8) = *(const uint4*)(sl + i * 8);
        __syncthreads();
        #pragma unroll
        for (int k = 0; k < 4; k++)
            ldsm4(ql[k][0], ql[k][1], ql[k][2], ql[k][3], qb + (k * 16) * 2);
        __syncthreads();
    }

    float o[8][4];
    #pragma unroll
    for (int i = 0; i < 8; i++)
        #pragma unroll
        for (int j = 0; j < 4; j++) o[i][j] = 0.0f;
    float m0 = -1e30f, m1 = -1e30f, l0 = 0.0f, l1 = 0.0f;

    const float* mrow = g_maskbias + b * NN;
    const int tq2 = (lane & 3) * 2;

    // cp.async mapping: r = tid>>2 (0..63), c = (tid&3)*16
    const int ldr = tid >> 2;
    const int ldc = (tid & 3) << 4;
    const uint32_t sdst = u0 + (ldr * ASTR + ldc) * 2;

    #define ISSUE_ATT(kt, stg) do {                                           \
        const uint32_t d_ = sdst + (stg) * (ATT_STAGE * 2);                    \
        const size_t gi_ = (head_off + (kt) + ldr) * DH + ldc;                 \
        cpa16(d_ + 0 * 64 * ASTR * 2,      g_kh + gi_);                        \
        cpa16(d_ + 0 * 64 * ASTR * 2 + 16, g_kh + gi_ + 8);                    \
        cpa16(d_ + 1 * 64 * ASTR * 2,      g_kl + gi_);                        \
        cpa16(d_ + 1 * 64 * ASTR * 2 + 16, g_kl + gi_ + 8);                    \
        cpa16(d_ + 2 * 64 * ASTR * 2,      g_vh + gi_);                        \
        cpa16(d_ + 2 * 64 * ASTR * 2 + 16, g_vh + gi_ + 8);                    \
        cpa16(d_ + 3 * 64 * ASTR * 2,      g_vl + gi_);                        \
        cpa16(d_ + 3 * 64 * ASTR * 2 + 16, g_vl + gi_ + 8);                    \
        if (tid < 16)                                                          \
            cpa16(mb_u + (stg) * 256 + tid * 16, mrow + (kt) + tid * 4);       \
        CP_COMMIT();                                                           \
    } while (0)

    ISSUE_ATT(0, 0);

    const int NT = NN / 64;   // 32
    for (int ti = 0; ti < NT; ti++) {
        if (ti + 1 < NT) {
            ISSUE_ATT((ti + 1) * 64, (ti + 1) & 1);
            CP_WAIT(1);
        } else {
            CP_WAIT(0);
        }
        __syncthreads();

        const uint32_t sb = u0 + (ti & 1) * (ATT_STAGE * 2);
        const uint32_t Kh = sb;
        const uint32_t Kl = sb + 64 * ASTR * 2;
        const uint32_t Vh = sb + 2 * 64 * ASTR * 2;
        const uint32_t Vl = sb + 3 * 64 * ASTR * 2;
        const float* mb = mbs + (ti & 1) * 64;

        // S = Q K^T  (bf16x3), pass-major
        float s[8][4];
        #pragma unroll
        for (int i = 0; i < 8; i++)
            #pragma unroll
            for (int j = 0; j < 4; j++) s[i][j] = 0.0f;

        #pragma unroll
        for (int k = 0; k < 4; k++) {
            uint32_t kh[4][4], kl[4][4];
            #pragma unroll
            for (int p = 0; p < 4; p++) {
                const uint32_t nb = ((p * 16 + bRow) * ASTR + k * 16 + bK) * 2;
                ldsm4(kh[p][0], kh[p][1], kh[p][2], kh[p][3], Kh + nb);
                ldsm4(kl[p][0], kl[p][1], kl[p][2], kl[p][3], Kl + nb);
            }
            #pragma unroll
            for (int p = 0; p < 4; p++) {
                mma16816(s[2 * p + 0], qh[k], kh[p][0], kh[p][1]);
                mma16816(s[2 * p + 1], qh[k], kh[p][2], kh[p][3]);
            }
            #pragma unroll
            for (int p = 0; p < 4; p++) {
                mma16816(s[2 * p + 0], qh[k], kl[p][0], kl[p][1]);
                mma16816(s[2 * p + 1], qh[k], kl[p][2], kl[p][3]);
            }
            #pragma unroll
            for (int p = 0; p < 4; p++) {
                mma16816(s[2 * p + 0], ql[k], kh[p][0], kh[p][1]);
                mma16816(s[2 * p + 1], ql[k], kh[p][2], kh[p][3]);
            }
        }

        // mask + online softmax
        float mx0 = -1e30f, mx1 = -1e30f;
        #pragma unroll
        for (int nt = 0; nt < 8; nt++) {
            const float b0 = mb[nt * 8 + tq2];
            const float b1 = mb[nt * 8 + tq2 + 1];
            s[nt][0] += b0; s[nt][1] += b1;
            s[nt][2] += b0; s[nt][3] += b1;
            mx0 = fmaxf(mx0, fmaxf(s[nt][0], s[nt][1]));
            mx1 = fmaxf(mx1, fmaxf(s[nt][2], s[nt][3]));
        }
        mx0 = fmaxf(mx0, __shfl_xor_sync(0xffffffffu, mx0, 1));
        mx0 = fmaxf(mx0, __shfl_xor_sync(0xffffffffu, mx0, 2));
        mx1 = fmaxf(mx1, __shfl_xor_sync(0xffffffffu, mx1, 1));
        mx1 = fmaxf(mx1, __shfl_xor_sync(0xffffffffu, mx1, 2));
        const float mn0 = fmaxf(m0, mx0), mn1 = fmaxf(m1, mx1);
        const float sc0 = __expf(m0 - mn0), sc1 = __expf(m1 - mn1);
        m0 = mn0; m1 = mn1;
        float ps0 = 0.0f, ps1 = 0.0f;
        #pragma unroll
        for (int nt = 0; nt < 8; nt++) {
            s[nt][0] = __expf(s[nt][0] - m0);
            s[nt][1] = __expf(s[nt][1] - m0);
            s[nt][2] = __expf(s[nt][2] - m1);
            s[nt][3] = __expf(s[nt][3] - m1);
            ps0 += s[nt][0] + s[nt][1];
            ps1 += s[nt][2] + s[nt][3];
        }
        ps0 += __shfl_xor_sync(0xffffffffu, ps0, 1);
        ps0 += __shfl_xor_sync(0xffffffffu, ps0, 2);
        ps1 += __shfl_xor_sync(0xffffffffu, ps1, 1);
        ps1 += __shfl_xor_sync(0xffffffffu, ps1, 2);
        l0 = l0 * sc0 + ps0;
        l1 = l1 * sc1 + ps1;
        #pragma unroll
        for (int nt = 0; nt < 8; nt++) {
            o[nt][0] *= sc0; o[nt][1] *= sc0;
            o[nt][2] *= sc1; o[nt][3] *= sc1;
        }

        // O += P V   (P hi/lo x V hi/lo, 3 passes; p in pairs)
        #pragma unroll
        for (int jj = 0; jj < 4; jj++) {
            uint32_t ph[4], pl[4];
            hl_pack(s[2 * jj][0],     s[2 * jj][1],     ph[0], pl[0]);
            hl_pack(s[2 * jj][2],     s[2 * jj][3],     ph[1], pl[1]);
            hl_pack(s[2 * jj + 1][0], s[2 * jj + 1][1], ph[2], pl[2]);
            hl_pack(s[2 * jj + 1][2], s[2 * jj + 1][3], ph[3], pl[3]);
            #pragma unroll
            for (int pp = 0; pp < 2; pp++) {
                uint32_t vh[2][4], vl[2][4];
                #pragma unroll
                for (int q = 0; q < 2; q++) {
                    const int p = pp * 2 + q;
                    const uint32_t off = ((jj * 16 + vRow) * ASTR + p * 16 + vCol) * 2;
                    ldsm4t(vh[q][0], vh[q][1], vh[q][2], vh[q][3], Vh + off);
                    ldsm4t(vl[q][0], vl[q][1], vl[q][2], vl[q][3], Vl + off);
                }
                #pragma unroll
                for (int q = 0; q < 2; q++) {
                    const int p = pp * 2 + q;
                    mma16816(o[2 * p + 0], ph, vh[q][0], vh[q][1]);
                    mma16816(o[2 * p + 1], ph, vh[q][2], vh[q][3]);
                }
                #pragma unroll
                for (int q = 0; q < 2; q++) {
                    const int p = pp * 2 + q;
                    mma16816(o[2 * p + 0], ph, vl[q][0], vl[q][1]);
                    mma16816(o[2 * p + 1], ph, vl[q][2], vl[q][3]);
                }
                #pragma unroll
                for (int q = 0; q < 2; q++) {
                    const int p = pp * 2 + q;
                    mma16816(o[2 * p + 0], pl, vh[q][0], vh[q][1]);
                    mma16816(o[2 * p + 1], pl, vh[q][2], vh[q][3]);
                }
            }
        }
        __syncthreads();
    }
    #undef ISSUE_ATT

    // epilogue -> g_ao hi/lo   [b, n, h*64+dh]
    const float inv0 = 1.0f / l0, inv1 = 1.0f / l1;
    const int g = lane >> 2;
    const int q0 = bq + wid * 16 + g;
    const size_t ob = ((size_t)(b * NN) + q0) * DD + h * DH;
    #pragma unroll
    for (int nt = 0; nt < 8; nt++) {
        const int dh = nt * 8 + tq2;
        hl2_store(o[nt][0] * inv0, o[nt][1] * inv0, g_ao_hi + ob + dh, g_ao_lo + ob + dh);
        hl2_store(o[nt][2] * inv1, o[nt][3] * inv1,
                  g_ao_hi + ob + 8 * DD + dh, g_ao_lo + ob + 8 * DD + dh);
    }
}

// ---------------------------------------------------------------------------
// Launch
// ---------------------------------------------------------------------------
extern "C" void kernel_launch(void* const* d_in, const int* in_sizes, int n_in,
                              void* d_out, int out_size)
{
    const float* x       = (const float*)d_in[0];
    const void*  mask    = (const void*)d_in[1];
    const float* norm_w  = (const float*)d_in[2];
    const float* norm_b  = (const float*)d_in[3];
    const float* qn_w    = (const float*)d_in[4];
    const float* qn_b    = (const float*)d_in[5];
    const float* kn_w    = (const float*)d_in[6];
    const float* kn_b    = (const float*)d_in[7];
    const float* Wq      = (const float*)d_in[8];
    const float* bq      = (const float*)d_in[9];
    const float* Wk      = (const float*)d_in[10];
    const float* bk      = (const float*)d_in[11];
    const float* Wv      = (const float*)d_in[12];
    const float* bv      = (const float*)d_in[13];
    const float* Wo      = (const float*)d_in[14];
    float* out = (float*)d_out;

    static bool attr_done = false;
    if (!attr_done) {
        cudaFuncSetAttribute(gemm_mma2<0>, cudaFuncAttributeMaxDynamicSharedMemorySize, GEMM_SMEM2);
        cudaFuncSetAttribute(gemm_mma2<4>, cudaFuncAttributeMaxDynamicSharedMemorySize, GEMM_SMEM2);
        cudaFuncSetAttribute(attn_mma_kernel, cudaFuncAttributeMaxDynamicSharedMemorySize, ATT_SMEM);
        attr_done = true;
    }

    // 0. Mask -> float bias; bias concat; W -> hi/lo bf16
    prep_kernel<<<1, 256>>>(mask, bq, bk, bv);
    wconv_kernel<<<dim3(1024, 4), 256>>>(Wq, Wk, Wv, Wo);

    // 1. LN(x) -> hi/lo bf16
    ln_x_kernel<<<BN, 256>>>(x, norm_w, norm_b);

    // 2. Fused QKV projection (cp.async pipelined HMMA bf16x3)
    gemm_mma2<4><<<dim3(3 * DD / 128, BN / 128), 256, GEMM_SMEM2>>>(nullptr);

    // 3. Per-head LN -> q/k hi/lo bf16 (q scaled by DH^-0.5)
    headln_kernel<<<dim3((BB * HH * NN) / 8, 2), 256>>>(qn_w, qn_b, kn_w, kn_b);

    // 4. Tensor-core flash attention (cp.async pipelined) -> g_ao hi/lo
    attn_mma_kernel<<<dim3(NN / 128, HH, BB), 256, ATT_SMEM>>>();

    // 5. Output projection -> d_out
    gemm_mma2<0><<<dim3(DD / 128, BN / 128), 256, GEMM_SMEM2>>>(out);
}

// round 12
// speedup vs baseline: 1.4606x; 1.2545x over previous
#include <cuda_runtime.h>
#include <cuda_bf16.h>
#include <cstdint>

// Problem constants
#define BB 4
#define NN 2048
#define DD 1024
#define HH 16
#define DH 64
#define BN (BB*NN)          // 8192
#define LN_EPS 1e-5f

// ---------------------------------------------------------------------------
// Device scratch (no allocation allowed)
// ---------------------------------------------------------------------------
__device__ __nv_bfloat16 g_xn_hi[BN * DD];
__device__ __nv_bfloat16 g_xn_lo[BN * DD];
__device__ __nv_bfloat16 g_ao_hi[BN * DD];
__device__ __nv_bfloat16 g_ao_lo[BN * DD];
__device__ __nv_bfloat16 g_whi[4 * DD * DD];
__device__ __nv_bfloat16 g_wlo[4 * DD * DD];
__device__ float g_q[BB * HH * NN * DH];
__device__ float g_k[BB * HH * NN * DH];
__device__ __nv_bfloat16 g_qh[BB * HH * NN * DH];
__device__ __nv_bfloat16 g_ql[BB * HH * NN * DH];
__device__ __nv_bfloat16 g_kh[BB * HH * NN * DH];
__device__ __nv_bfloat16 g_kl[BB * HH * NN * DH];
__device__ __nv_bfloat16 g_vh[BB * HH * NN * DH];
__device__ __nv_bfloat16 g_vl[BB * HH * NN * DH];
__device__ float g_bqkv[3 * DD];
__device__ int   g_gidx[BB * NN];    // compacted key indices (padded with 0)
__device__ int   g_cnt[BB];          // unmasked key count per batch
__device__ float g_padbias[BB * NN]; // 0 for j<cnt, -1e30 beyond (tile padding)

// ---------------------------------------------------------------------------
// Helpers
// ---------------------------------------------------------------------------
__device__ __forceinline__ uint32_t s2u(const void* p) {
    uint32_t a;
    asm("{ .reg .u64 t; cvta.to.shared.u64 t, %1; cvt.u32.u64 %0, t; }"
        : "=r"(a) : "l"(p));
    return a;
}

__device__ __forceinline__ void cpa16(uint32_t dst, const void* src) {
    asm volatile("cp.async.cg.shared.global [%0], [%1], 16;"
                 :: "r"(dst), "l"(src) : "memory");
}
#define CP_COMMIT() asm volatile("cp.async.commit_group;" ::: "memory")
#define CP_WAIT(N)  asm volatile("cp.async.wait_group %0;" :: "n"(N) : "memory")

__device__ __forceinline__ void ldsm4(uint32_t& r0, uint32_t& r1,
                                      uint32_t& r2, uint32_t& r3,
                                      uint32_t addr) {
    asm volatile("ldmatrix.sync.aligned.m8n8.x4.shared.b16 {%0,%1,%2,%3}, [%4];"
                 : "=r"(r0), "=r"(r1), "=r"(r2), "=r"(r3) : "r"(addr));
}

__device__ __forceinline__ void ldsm4t(uint32_t& r0, uint32_t& r1,
                                       uint32_t& r2, uint32_t& r3,
                                       uint32_t addr) {
    asm volatile("ldmatrix.sync.aligned.m8n8.x4.trans.shared.b16 {%0,%1,%2,%3}, [%4];"
                 : "=r"(r0), "=r"(r1), "=r"(r2), "=r"(r3) : "r"(addr));
}

__device__ __forceinline__ void mma16816(float* c, const uint32_t* a,
                                         uint32_t b0, uint32_t b1) {
    asm volatile(
        "mma.sync.aligned.m16n8k16.row.col.f32.bf16.bf16.f32 "
        "{%0,%1,%2,%3}, {%4,%5,%6,%7}, {%8,%9}, {%0,%1,%2,%3};"
        : "+f"(c[0]), "+f"(c[1]), "+f"(c[2]), "+f"(c[3])
        : "r"(a[0]), "r"(a[1]), "r"(a[2]), "r"(a[3]), "r"(b0), "r"(b1));
}

// hi/lo bf16 split of a float pair -> two packed bf16x2 regs
__device__ __forceinline__ void hl_pack(float a, float b, uint32_t& hi, uint32_t& lo) {
    __nv_bfloat162 h = __float22bfloat162_rn(make_float2(a, b));
    float2 f = __bfloat1622float2(h);
    __nv_bfloat162 l = __float22bfloat162_rn(make_float2(a - f.x, b - f.y));
    hi = *reinterpret_cast<uint32_t*>(&h);
    lo = *reinterpret_cast<uint32_t*>(&l);
}

__device__ __forceinline__ void hl2_store(float a, float b,
                                          __nv_bfloat16* hip, __nv_bfloat16* lop) {
    uint32_t hi, lo;
    hl_pack(a, b, hi, lo);
    *(uint32_t*)hip = hi;
    *(uint32_t*)lop = lo;
}

__device__ __forceinline__ void hl4_store(float4 v, __nv_bfloat16* hip,
                                          __nv_bfloat16* lop) {
    hl2_store(v.x, v.y, hip, lop);
    hl2_store(v.z, v.w, hip + 2, lop + 2);
}

// ---------------------------------------------------------------------------
// Kernel 0: mask preprocessing (compaction) + bias concat
// ---------------------------------------------------------------------------
__global__ __launch_bounds__(256)
void prep_kernel(const void* __restrict__ mask,
                 const float* __restrict__ bq,
                 const float* __restrict__ bk,
                 const float* __restrict__ bv)
{
    __shared__ int s_packed;
    __shared__ int s_cnt[4];
    if (threadIdx.x == 0) s_packed = 0;
    __syncthreads();

    const unsigned* mw = (const unsigned*)mask;
    int bad = 0;
    for (int i = threadIdx.x; i < 2048; i += 256)
        if (mw[i] > 1u) bad = 1;
    if (bad) atomicOr(&s_packed, 1);
    __syncthreads();
    const bool packed = (s_packed != 0);

    const int* mi = (const int*)mask;
    const unsigned char* mb = (const unsigned char*)mask;

    // Per-batch compaction: warp w handles batch w via ballot scan.
    const int warp = threadIdx.x >> 5, lane = threadIdx.x & 31;
    if (warp < 4) {
        int cnt = 0;
        for (int base = 0; base < NN; base += 32) {
            const int i = warp * NN + base + lane;
            const int on = packed ? (int)mb[i] : mi[i];
            const unsigned bal = __ballot_sync(0xffffffffu, on != 0);
            if (on)
                g_gidx[warp * NN + cnt + __popc(bal & ((1u << lane) - 1))] = base + lane;
            cnt += __popc(bal);
        }
        if (lane == 0) s_cnt[warp] = cnt;
    }
    __syncthreads();

    // Pad index list + build compacted-position bias
    for (int i = threadIdx.x; i < BB * NN; i += 256) {
        const int bb = i >> 11, j = i & 2047;
        const int cnt = s_cnt[bb];
        g_padbias[i] = (j < cnt) ? 0.0f : -1e30f;
        if (j >= cnt) g_gidx[i] = 0;
    }
    if (threadIdx.x < 4) g_cnt[threadIdx.x] = s_cnt[threadIdx.x];

    for (int i = threadIdx.x; i < DD; i += 256) {
        g_bqkv[i]          = bq[i];
        g_bqkv[DD + i]     = bk[i];
        g_bqkv[2 * DD + i] = bv[i];
    }
}

// ---------------------------------------------------------------------------
// Kernel W: split all four W[1024x1024] into hi/lo bf16 (grid.y = slot)
// ---------------------------------------------------------------------------
__global__ __launch_bounds__(256)
void wconv_kernel(const float* __restrict__ W0, const float* __restrict__ W1,
                  const float* __restrict__ W2, const float* __restrict__ W3)
{
    const int slot = blockIdx.y;
    const float* W = (slot == 0) ? W0 : (slot == 1) ? W1 : (slot == 2) ? W2 : W3;
    const size_t i = ((size_t)blockIdx.x * 256 + threadIdx.x) * 4;
    float4 v = *(const float4*)(W + i);
    const size_t off = (size_t)slot * DD * DD + i;
    hl4_store(v, g_whi + off, g_wlo + off);
}

// ---------------------------------------------------------------------------
// Kernel 1: row LayerNorm over D=1024 -> hi/lo bf16
// ---------------------------------------------------------------------------
__global__ __launch_bounds__(256)
void ln_x_kernel(const float* __restrict__ x,
                 const float* __restrict__ w,
                 const float* __restrict__ b)
{
    __shared__ float red_s[8];
    __shared__ float red_q[8];
    __shared__ float stats[2];
    const int row = blockIdx.x;
    const int t = threadIdx.x;
    const int lane = t & 31, warp = t >> 5;

    const float* xr = x + (long)row * DD;
    float4 xv = *(const float4*)(xr + t * 4);
    float sum = xv.x + xv.y + xv.z + xv.w;
    float ssq = fmaf(xv.x, xv.x, fmaf(xv.y, xv.y, fmaf(xv.z, xv.z, xv.w * xv.w)));
    #pragma unroll
    for (int o = 16; o > 0; o >>= 1) {
        sum += __shfl_xor_sync(0xffffffffu, sum, o);
        ssq += __shfl_xor_sync(0xffffffffu, ssq, o);
    }
    if (lane == 0) { red_s[warp] = sum; red_q[warp] = ssq; }
    __syncthreads();
    if (warp == 0) {
        float a = (lane < 8) ? red_s[lane] : 0.0f;
        float c = (lane < 8) ? red_q[lane] : 0.0f;
        #pragma unroll
        for (int o = 4; o > 0; o >>= 1) {
            a += __shfl_xor_sync(0xffffffffu, a, o);
            c += __shfl_xor_sync(0xffffffffu, c, o);
        }
        if (lane == 0) { stats[0] = a * (1.0f / DD); stats[1] = c * (1.0f / DD); }
    }
    __syncthreads();
    const float mean = stats[0];
    const float var = stats[1] - mean * mean;
    const float rstd = rsqrtf(var + LN_EPS);

    float4 wv = *(const float4*)(w + t * 4);
    float4 bv = *(const float4*)(b + t * 4);
    float4 ov;
    ov.x = (xv.x - mean) * rstd * wv.x + bv.x;
    ov.y = (xv.y - mean) * rstd * wv.y + bv.y;
    ov.z = (xv.z - mean) * rstd * wv.z + bv.z;
    ov.w = (xv.w - mean) * rstd * wv.w + bv.w;
    const size_t off = (size_t)row * DD + t * 4;
    hl4_store(ov, g_xn_hi + off, g_xn_lo + off);
}

// ---------------------------------------------------------------------------
// Kernel 2: HMMA bf16x3 GEMM, cp.async double-buffered, K-slab 32.
// 128x128 CTA tile, 8 warps (4M x 2N), warp tile 32x64, 256 threads,
// launch_bounds(256,2) -> 16 warps/SM.
// ---------------------------------------------------------------------------
#define KSL 32
#define SST2 40
#define BUF2 (128 * SST2)
#define STAGE_ELE (4 * BUF2)
#define GEMM_SMEM2 (2 * STAGE_ELE * 2)

template<int MODE>
__global__ __launch_bounds__(256, 2)
void gemm_mma2(float* __restrict__ Cout)
{
    extern __shared__ __nv_bfloat16 smg[];
    const uint32_t u0 = s2u(smg);

    const int tid = threadIdx.x;
    const int wid = tid >> 5, lane = tid & 31;
    const int wm = (wid & 3) << 5;
    const int wn = (wid >> 2) << 6;
    const int bm = blockIdx.y << 7;
    const int bn = blockIdx.x << 7;

    const __nv_bfloat16* gAh = (MODE == 0) ? g_ao_hi : g_xn_hi;
    const __nv_bfloat16* gAl = (MODE == 0) ? g_ao_lo : g_xn_lo;
    const __nv_bfloat16* gBh = (MODE == 0) ? (g_whi + (size_t)3 * DD * DD) : g_whi;
    const __nv_bfloat16* gBl = (MODE == 0) ? (g_wlo + (size_t)3 * DD * DD) : g_wlo;

    float acc[2][8][4];
    #pragma unroll
    for (int i = 0; i < 2; i++)
        #pragma unroll
        for (int j = 0; j < 8; j++)
            #pragma unroll
            for (int k = 0; k < 4; k++) acc[i][j][k] = 0.0f;

    const int lrow = tid >> 1;
    const int lhalf = (tid & 1) << 4;
    const __nv_bfloat16* pAh = gAh + (size_t)(bm + lrow) * DD + lhalf;
    const __nv_bfloat16* pAl = gAl + (size_t)(bm + lrow) * DD + lhalf;
    const __nv_bfloat16* pBh = gBh + (size_t)(bn + lrow) * DD + lhalf;
    const __nv_bfloat16* pBl = gBl + (size_t)(bn + lrow) * DD + lhalf;
    const uint32_t dbase = u0 + (lrow * SST2 + lhalf) * 2;

    const int aRow = (lane & 7) + ((lane & 8) ? 8 : 0);
    const int aK   = (lane & 16) ? 8 : 0;
    const int bRow = (lane & 7) + ((lane & 16) ? 8 : 0);
    const int bK   = (lane & 8) ? 8 : 0;

    #define ISSUE_STAGE(kt, stg) do {                                        \
        const uint32_t d_ = dbase + (stg) * (STAGE_ELE * 2);                  \
        cpa16(d_ + 0 * BUF2 * 2,      pAh + (kt));                            \
        cpa16(d_ + 0 * BUF2 * 2 + 16, pAh + (kt) + 8);                        \
        cpa16(d_ + 1 * BUF2 * 2,      pAl + (kt));                            \
        cpa16(d_ + 1 * BUF2 * 2 + 16, pAl + (kt) + 8);                        \
        cpa16(d_ + 2 * BUF2 * 2,      pBh + (kt));                            \
        cpa16(d_ + 2 * BUF2 * 2 + 16, pBh + (kt) + 8);                        \
        cpa16(d_ + 3 * BUF2 * 2,      pBl + (kt));                            \
        cpa16(d_ + 3 * BUF2 * 2 + 16, pBl + (kt) + 8);                        \
        CP_COMMIT();                                                          \
    } while (0)

    ISSUE_STAGE(0, 0);

    const int NSLAB = DD / KSL;
    for (int s = 0; s < NSLAB; s++) {
        if (s + 1 < NSLAB) {
            ISSUE_STAGE((s + 1) * KSL, (s + 1) & 1);
            CP_WAIT(1);
        } else {
            CP_WAIT(0);
        }
        __syncthreads();

        const uint32_t sb = u0 + (s & 1) * (STAGE_ELE * 2);
        const uint32_t aAh = sb + ((wm + aRow) * SST2 + aK) * 2;
        const uint32_t aAl = aAh + BUF2 * 2;
        const uint32_t aBh = sb + 2 * BUF2 * 2 + ((wn + bRow) * SST2 + bK) * 2;
        const uint32_t aBl = aBh + BUF2 * 2;

        #pragma unroll
        for (int k16 = 0; k16 < 2; k16++) {
            const uint32_t koff = (k16 << 4) * 2;
            uint32_t ah[2][4], al[2][4];
            #pragma unroll
            for (int mt = 0; mt < 2; mt++) {
                const uint32_t moff = (mt << 4) * SST2 * 2;
                ldsm4(ah[mt][0], ah[mt][1], ah[mt][2], ah[mt][3], aAh + moff + koff);
                ldsm4(al[mt][0], al[mt][1], al[mt][2], al[mt][3], aAl + moff + koff);
            }
            #pragma unroll
            for (int p = 0; p < 4; p++) {
                const uint32_t noff = (p << 4) * SST2 * 2;
                uint32_t bh0, bh1, bh2, bh3, bl0, bl1, bl2, bl3;
                ldsm4(bh0, bh1, bh2, bh3, aBh + noff + koff);
                ldsm4(bl0, bl1, bl2, bl3, aBl + noff + koff);
                #pragma unroll
                for (int mt = 0; mt < 2; mt++) {
                    mma16816(acc[mt][2 * p + 0], ah[mt], bh0, bh1);
                    mma16816(acc[mt][2 * p + 1], ah[mt], bh2, bh3);
                }
                #pragma unroll
                for (int mt = 0; mt < 2; mt++) {
                    mma16816(acc[mt][2 * p + 0], ah[mt], bl0, bl1);
                    mma16816(acc[mt][2 * p + 1], ah[mt], bl2, bl3);
                }
                #pragma unroll
                for (int mt = 0; mt < 2; mt++) {
                    mma16816(acc[mt][2 * p + 0], al[mt], bh0, bh1);
                    mma16816(acc[mt][2 * p + 1], al[mt], bh2, bh3);
                }
            }
        }
        __syncthreads();
    }
    #undef ISSUE_STAGE

    // Epilogue
    const int g = lane >> 2, tq = lane & 3;
    #pragma unroll
    for (int mt = 0; mt < 2; mt++) {
        #pragma unroll
        for (int nt = 0; nt < 8; nt++) {
            const int c = bn + wn + nt * 8 + 2 * tq;
            #pragma unroll
            for (int half = 0; half < 2; half++) {
                const int r = bm + wm + mt * 16 + g + half * 8;
                float2 v;
                v.x = acc[mt][nt][2 * half + 0];
                v.y = acc[mt][nt][2 * half + 1];
                if (MODE == 0) {
                    *(float2*)(Cout + (size_t)r * DD + c) = v;
                } else {
                    const float2 bv = *(const float2*)(g_bqkv + c);
                    v.x += bv.x; v.y += bv.y;
                    const int which = c >> 10;
                    const int cc = c & 1023;
                    const int h = cc >> 6;
                    const size_t idx = ((((size_t)((r >> 11) * HH + h)) * NN
                                        + (r & 2047)) << 6) + (cc & 63);
                    if (which == 0)      *(float2*)(g_q + idx) = v;
                    else if (which == 1) *(float2*)(g_k + idx) = v;
                    else                 hl2_store(v.x, v.y, g_vh + idx, g_vl + idx);
                }
            }
        }
    }
}

// ---------------------------------------------------------------------------
// Kernel 3: per-head LayerNorm over DH=64 -> hi/lo bf16 (grid.y: 0=q, 1=k)
// ---------------------------------------------------------------------------
__global__ __launch_bounds__(256)
void headln_kernel(const float* __restrict__ qw, const float* __restrict__ qb,
                   const float* __restrict__ kw, const float* __restrict__ kb)
{
    const int isq = (blockIdx.y == 0);
    const float* base = isq ? g_q : g_k;
    __nv_bfloat16* oh = isq ? g_qh : g_kh;
    __nv_bfloat16* ol = isq ? g_ql : g_kl;
    const float* w = isq ? qw : kw;
    const float* b = isq ? qb : kb;
    const float sc = isq ? 0.125f : 1.0f;

    const int warp = threadIdx.x >> 5;
    const int lane = threadIdx.x & 31;
    const long row = (long)blockIdx.x * 8 + warp;
    const float* p = base + row * DH;

    float2 xv = *(const float2*)(p + lane * 2);
    float sum = xv.x + xv.y;
    float ssq = fmaf(xv.x, xv.x, xv.y * xv.y);
    #pragma unroll
    for (int o = 16; o > 0; o >>= 1) {
        sum += __shfl_xor_sync(0xffffffffu, sum, o);
        ssq += __shfl_xor_sync(0xffffffffu, ssq, o);
    }
    const float mean = sum * (1.0f / DH);
    const float var = ssq * (1.0f / DH) - mean * mean;
    const float rstd = rsqrtf(var + LN_EPS);

    float2 wv = *(const float2*)(w + lane * 2);
    float2 bv = *(const float2*)(b + lane * 2);
    float a = ((xv.x - mean) * rstd * wv.x + bv.x) * sc;
    float c = ((xv.y - mean) * rstd * wv.y + bv.y) * sc;
    hl2_store(a, c, oh + row * DH + lane * 2, ol + row * DH + lane * 2);
}

// ---------------------------------------------------------------------------
// Kernel 4: tensor-core flash attention over COMPACTED keys
// (bf16x3 QK^T and PV), cp.async double-buffered gathered K/V + bias tiles.
// grid (16, 16, 4): 128 queries x one (b,h) per CTA; 8 warps x 16 q-rows.
// ---------------------------------------------------------------------------
#define ASTR 72
#define ATT_STAGE (4 * 64 * ASTR)
#define ATT_SMEM (2 * ATT_STAGE * 2 + 2 * 64 * 4)

__global__ __launch_bounds__(256)
void attn_mma_kernel()
{
    extern __shared__ __nv_bfloat16 sma[];
    const uint32_t u0 = s2u(sma);
    float* mbs = (float*)(sma + 2 * ATT_STAGE);
    const uint32_t mb_u = u0 + 2 * ATT_STAGE * 2;

    const int tid = threadIdx.x, wid = tid >> 5, lane = tid & 31;
    const int bq = blockIdx.x << 7;
    const int h = blockIdx.y, b = blockIdx.z;
    const size_t head_off = ((size_t)(b * HH + h)) * NN;

    const int aRow = (lane & 7) + ((lane & 8) ? 8 : 0);
    const int aK   = (lane & 16) ? 8 : 0;
    const int bRow = (lane & 7) + ((lane & 16) ? 8 : 0);
    const int bK   = (lane & 8) ? 8 : 0;
    const int vRow = (lane & 7) + ((lane & 8) ? 8 : 0);
    const int vCol = (lane & 16) ? 8 : 0;

    // ---- Phase 1: stage Q hi then Q lo through rows [0,128) (two passes)
    uint32_t qh[4][4], ql[4][4];
    {
        const int r = tid >> 1;
        const int c = (tid & 1) << 5;
        const uint32_t qb = u0 + ((wid * 16 + aRow) * ASTR + aK) * 2;

        const __nv_bfloat16* sh = g_qh + (head_off + bq + r) * DH + c;
        #pragma unroll
        for (int i = 0; i < 4; i++)
            *(uint4*)(sma + r * ASTR + c + i * 8) = *(const uint4*)(sh + i * 8);
        __syncthreads();
        #pragma unroll
        for (int k = 0; k < 4; k++)
            ldsm4(qh[k][0], qh[k][1], qh[k][2], qh[k][3], qb + (k * 16) * 2);
        __syncthreads();

        const __nv_bfloat16* sl = g_ql + (head_off + bq + r) * DH + c;
        #pragma unroll
        for (int i = 0; i < 4; i++)
            *(uint4*)(sma + r * ASTR + c + i * 8) = *(const uint4*)(sl + i * 8);
        __syncthreads();
        #pragma unroll
        for (int k = 0; k < 4; k++)
            ldsm4(ql[k][0], ql[k][1], ql[k][2], ql[k][3], qb + (k * 16) * 2);
        __syncthreads();
    }

    float o[8][4];
    #pragma unroll
    for (int i = 0; i < 8; i++)
        #pragma unroll
        for (int j = 0; j < 4; j++) o[i][j] = 0.0f;
    float m0 = -1e30f, m1 = -1e30f, l0 = 0.0f, l1 = 0.0f;

    const float* mrow = g_padbias + b * NN;   // bias by compacted position
    const int* gidx = g_gidx + b * NN;        // gather indices
    const int cnt = g_cnt[b];
    const int NT = (cnt + 63) >> 6;           // tiles over compacted keys
    const int tq2 = (lane & 3) * 2;

    const int ldr = tid >> 2;
    const int ldc = (tid & 3) << 4;
    const uint32_t sdst = u0 + (ldr * ASTR + ldc) * 2;

    #define ISSUE_ATT(kt, stg) do {                                           \
        const uint32_t d_ = sdst + (stg) * (ATT_STAGE * 2);                    \
        const int srow_ = gidx[(kt) + ldr];                                    \
        const size_t gi_ = (head_off + srow_) * DH + ldc;                      \
        cpa16(d_ + 0 * 64 * ASTR * 2,      g_kh + gi_);                        \
        cpa16(d_ + 0 * 64 * ASTR * 2 + 16, g_kh + gi_ + 8);                    \
        cpa16(d_ + 1 * 64 * ASTR * 2,      g_kl + gi_);                        \
        cpa16(d_ + 1 * 64 * ASTR * 2 + 16, g_kl + gi_ + 8);                    \
        cpa16(d_ + 2 * 64 * ASTR * 2,      g_vh + gi_);                        \
        cpa16(d_ + 2 * 64 * ASTR * 2 + 16, g_vh + gi_ + 8);                    \
        cpa16(d_ + 3 * 64 * ASTR * 2,      g_vl + gi_);                        \
        cpa16(d_ + 3 * 64 * ASTR * 2 + 16, g_vl + gi_ + 8);                    \
        if (tid < 16)                                                          \
            cpa16(mb_u + (stg) * 256 + tid * 16, mrow + (kt) + tid * 4);       \
        CP_COMMIT();                                                           \
    } while (0)

    ISSUE_ATT(0, 0);

    for (int ti = 0; ti < NT; ti++) {
        if (ti + 1 < NT) {
            ISSUE_ATT((ti + 1) * 64, (ti + 1) & 1);
            CP_WAIT(1);
        } else {
            CP_WAIT(0);
        }
        __syncthreads();

        const uint32_t sb = u0 + (ti & 1) * (ATT_STAGE * 2);
        const uint32_t Kh = sb;
        const uint32_t Kl = sb + 64 * ASTR * 2;
        const uint32_t Vh = sb + 2 * 64 * ASTR * 2;
        const uint32_t Vl = sb + 3 * 64 * ASTR * 2;
        const float* mb = mbs + (ti & 1) * 64;

        // S = Q K^T  (bf16x3), pass-major
        float s[8][4];
        #pragma unroll
        for (int i = 0; i < 8; i++)
            #pragma unroll
            for (int j = 0; j < 4; j++) s[i][j] = 0.0f;

        #pragma unroll
        for (int k = 0; k < 4; k++) {
            uint32_t kh[4][4], kl[4][4];
            #pragma unroll
            for (int p = 0; p < 4; p++) {
                const uint32_t nb = ((p * 16 + bRow) * ASTR + k * 16 + bK) * 2;
                ldsm4(kh[p][0], kh[p][1], kh[p][2], kh[p][3], Kh + nb);
                ldsm4(kl[p][0], kl[p][1], kl[p][2], kl[p][3], Kl + nb);
            }
            #pragma unroll
            for (int p = 0; p < 4; p++) {
                mma16816(s[2 * p + 0], qh[k], kh[p][0], kh[p][1]);
                mma16816(s[2 * p + 1], qh[k], kh[p][2], kh[p][3]);
            }
            #pragma unroll
            for (int p = 0; p < 4; p++) {
                mma16816(s[2 * p + 0], qh[k], kl[p][0], kl[p][1]);
                mma16816(s[2 * p + 1], qh[k], kl[p][2], kl[p][3]);
            }
            #pragma unroll
            for (int p = 0; p < 4; p++) {
                mma16816(s[2 * p + 0], ql[k], kh[p][0], kh[p][1]);
                mma16816(s[2 * p + 1], ql[k], kh[p][2], kh[p][3]);
            }
        }

        // bias (tile padding) + online softmax
        float mx0 = -1e30f, mx1 = -1e30f;
        #pragma unroll
        for (int nt = 0; nt < 8; nt++) {
            const float b0 = mb[nt * 8 + tq2];
            const float b1 = mb[nt * 8 + tq2 + 1];
            s[nt][0] += b0; s[nt][1] += b1;
            s[nt][2] += b0; s[nt][3] += b1;
            mx0 = fmaxf(mx0, fmaxf(s[nt][0], s[nt][1]));
            mx1 = fmaxf(mx1, fmaxf(s[nt][2], s[nt][3]));
        }
        mx0 = fmaxf(mx0, __shfl_xor_sync(0xffffffffu, mx0, 1));
        mx0 = fmaxf(mx0, __shfl_xor_sync(0xffffffffu, mx0, 2));
        mx1 = fmaxf(mx1, __shfl_xor_sync(0xffffffffu, mx1, 1));
        mx1 = fmaxf(mx1, __shfl_xor_sync(0xffffffffu, mx1, 2));
        const float mn0 = fmaxf(m0, mx0), mn1 = fmaxf(m1, mx1);
        const float sc0 = __expf(m0 - mn0), sc1 = __expf(m1 - mn1);
        m0 = mn0; m1 = mn1;
        float ps0 = 0.0f, ps1 = 0.0f;
        #pragma unroll
        for (int nt = 0; nt < 8; nt++) {
            s[nt][0] = __expf(s[nt][0] - m0);
            s[nt][1] = __expf(s[nt][1] - m0);
            s[nt][2] = __expf(s[nt][2] - m1);
            s[nt][3] = __expf(s[nt][3] - m1);
            ps0 += s[nt][0] + s[nt][1];
            ps1 += s[nt][2] + s[nt][3];
        }
        ps0 += __shfl_xor_sync(0xffffffffu, ps0, 1);
        ps0 += __shfl_xor_sync(0xffffffffu, ps0, 2);
        ps1 += __shfl_xor_sync(0xffffffffu, ps1, 1);
        ps1 += __shfl_xor_sync(0xffffffffu, ps1, 2);
        l0 = l0 * sc0 + ps0;
        l1 = l1 * sc1 + ps1;
        #pragma unroll
        for (int nt = 0; nt < 8; nt++) {
            o[nt][0] *= sc0; o[nt][1] *= sc0;
            o[nt][2] *= sc1; o[nt][3] *= sc1;
        }

        // O += P V   (P hi/lo x V hi/lo, 3 passes; p in pairs)
        #pragma unroll
        for (int jj = 0; jj < 4; jj++) {
            uint32_t ph[4], pl[4];
            hl_pack(s[2 * jj][0],     s[2 * jj][1],     ph[0], pl[0]);
            hl_pack(s[2 * jj][2],     s[2 * jj][3],     ph[1], pl[1]);
            hl_pack(s[2 * jj + 1][0], s[2 * jj + 1][1], ph[2], pl[2]);
            hl_pack(s[2 * jj + 1][2], s[2 * jj + 1][3], ph[3], pl[3]);
            #pragma unroll
            for (int pp = 0; pp < 2; pp++) {
                uint32_t vh[2][4], vl[2][4];
                #pragma unroll
                for (int q = 0; q < 2; q++) {
                    const int p = pp * 2 + q;
                    const uint32_t off = ((jj * 16 + vRow) * ASTR + p * 16 + vCol) * 2;
                    ldsm4t(vh[q][0], vh[q][1], vh[q][2], vh[q][3], Vh + off);
                    ldsm4t(vl[q][0], vl[q][1], vl[q][2], vl[q][3], Vl + off);
                }
                #pragma unroll
                for (int q = 0; q < 2; q++) {
                    const int p = pp * 2 + q;
                    mma16816(o[2 * p + 0], ph, vh[q][0], vh[q][1]);
                    mma16816(o[2 * p + 1], ph, vh[q][2], vh[q][3]);
                }
                #pragma unroll
                for (int q = 0; q < 2; q++) {
                    const int p = pp * 2 + q;
                    mma16816(o[2 * p + 0], ph, vl[q][0], vl[q][1]);
                    mma16816(o[2 * p + 1], ph, vl[q][2], vl[q][3]);
                }
                #pragma unroll
                for (int q = 0; q < 2; q++) {
                    const int p = pp * 2 + q;
                    mma16816(o[2 * p + 0], pl, vh[q][0], vh[q][1]);
                    mma16816(o[2 * p + 1], pl, vh[q][2], vh[q][3]);
                }
            }
        }
        __syncthreads();
    }
    #undef ISSUE_ATT

    // epilogue -> g_ao hi/lo   [b, n, h*64+dh]
    const float inv0 = 1.0f / l0, inv1 = 1.0f / l1;
    const int g = lane >> 2;
    const int q0 = bq + wid * 16 + g;
    const size_t ob = ((size_t)(b * NN) + q0) * DD + h * DH;
    #pragma unroll
    for (int nt = 0; nt < 8; nt++) {
        const int dh = nt * 8 + tq2;
        hl2_store(o[nt][0] * inv0, o[nt][1] * inv0, g_ao_hi + ob + dh, g_ao_lo + ob + dh);
        hl2_store(o[nt][2] * inv1, o[nt][3] * inv1,
                  g_ao_hi + ob + 8 * DD + dh, g_ao_lo + ob + 8 * DD + dh);
    }
}

// ---------------------------------------------------------------------------
// Launch
// ---------------------------------------------------------------------------
extern "C" void kernel_launch(void* const* d_in, const int* in_sizes, int n_in,
                              void* d_out, int out_size)
{
    const float* x       = (const float*)d_in[0];
    const void*  mask    = (const void*)d_in[1];
    const float* norm_w  = (const float*)d_in[2];
    const float* norm_b  = (const float*)d_in[3];
    const float* qn_w    = (const float*)d_in[4];
    const float* qn_b    = (const float*)d_in[5];
    const float* kn_w    = (const float*)d_in[6];
    const float* kn_b    = (const float*)d_in[7];
    const float* Wq      = (const float*)d_in[8];
    const float* bq      = (const float*)d_in[9];
    const float* Wk      = (const float*)d_in[10];
    const float* bk      = (const float*)d_in[11];
    const float* Wv      = (const float*)d_in[12];
    const float* bv      = (const float*)d_in[13];
    const float* Wo      = (const float*)d_in[14];
    float* out = (float*)d_out;

    static bool attr_done = false;
    if (!attr_done) {
        cudaFuncSetAttribute(gemm_mma2<0>, cudaFuncAttributeMaxDynamicSharedMemorySize, GEMM_SMEM2);
        cudaFuncSetAttribute(gemm_mma2<4>, cudaFuncAttributeMaxDynamicSharedMemorySize, GEMM_SMEM2);
        cudaFuncSetAttribute(attn_mma_kernel, cudaFuncAttributeMaxDynamicSharedMemorySize, ATT_SMEM);
        attr_done = true;
    }

    // 0. Mask compaction + bias concat; W -> hi/lo bf16
    prep_kernel<<<1, 256>>>(mask, bq, bk, bv);
    wconv_kernel<<<dim3(1024, 4), 256>>>(Wq, Wk, Wv, Wo);

    // 1. LN(x) -> hi/lo bf16
    ln_x_kernel<<<BN, 256>>>(x, norm_w, norm_b);

    // 2. Fused QKV projection (cp.async pipelined HMMA bf16x3)
    gemm_mma2<4><<<dim3(3 * DD / 128, BN / 128), 256, GEMM_SMEM2>>>(nullptr);

    // 3. Per-head LN -> q/k hi/lo bf16 (q scaled by DH^-0.5)
    headln_kernel<<<dim3((BB * HH * NN) / 8, 2), 256>>>(qn_w, qn_b, kn_w, kn_b);

    // 4. Tensor-core flash attention over compacted keys -> g_ao hi/lo
    attn_mma_kernel<<<dim3(NN / 128, HH, BB), 256, ATT_SMEM>>>();

    // 5. Output projection -> d_out
    gemm_mma2<0><<<dim3(DD / 128, BN / 128), 256, GEMM_SMEM2>>>(out);
}

// round 13
// speedup vs baseline: 1.4864x; 1.0177x over previous
#include <cuda_runtime.h>
#include <cuda_bf16.h>
#include <cstdint>

// Problem constants
#define BB 4
#define NN 2048
#define DD 1024
#define HH 16
#define DH 64
#define BN (BB*NN)          // 8192
#define LN_EPS 1e-5f

// ---------------------------------------------------------------------------
// Device scratch (no allocation allowed)
// ---------------------------------------------------------------------------
__device__ __nv_bfloat16 g_xn_hi[BN * DD];
__device__ __nv_bfloat16 g_xn_lo[BN * DD];
__device__ __nv_bfloat16 g_ao_hi[BN * DD];
__device__ __nv_bfloat16 g_ao_lo[BN * DD];
__device__ __nv_bfloat16 g_whi[4 * DD * DD];
__device__ __nv_bfloat16 g_wlo[4 * DD * DD];
__device__ __nv_bfloat16 g_qh[BB * HH * NN * DH];
__device__ __nv_bfloat16 g_ql[BB * HH * NN * DH];
__device__ __nv_bfloat16 g_kh[BB * HH * NN * DH];
__device__ __nv_bfloat16 g_kl[BB * HH * NN * DH];
__device__ __nv_bfloat16 g_vh[BB * HH * NN * DH];
__device__ __nv_bfloat16 g_vl[BB * HH * NN * DH];
__device__ float g_bqkv[3 * DD];
__device__ int   g_gidx[BB * NN];    // compacted key indices (padded with 0)
__device__ int   g_cnt[BB];          // unmasked key count per batch
__device__ float g_padbias[BB * NN]; // 0 for j<cnt, -1e30 beyond (tile padding)

// ---------------------------------------------------------------------------
// Helpers
// ---------------------------------------------------------------------------
__device__ __forceinline__ uint32_t s2u(const void* p) {
    uint32_t a;
    asm("{ .reg .u64 t; cvta.to.shared.u64 t, %1; cvt.u32.u64 %0, t; }"
        : "=r"(a) : "l"(p));
    return a;
}

__device__ __forceinline__ void cpa16(uint32_t dst, const void* src) {
    asm volatile("cp.async.cg.shared.global [%0], [%1], 16;"
                 :: "r"(dst), "l"(src) : "memory");
}
#define CP_COMMIT() asm volatile("cp.async.commit_group;" ::: "memory")
#define CP_WAIT(N)  asm volatile("cp.async.wait_group %0;" :: "n"(N) : "memory")

__device__ __forceinline__ void ldsm4(uint32_t& r0, uint32_t& r1,
                                      uint32_t& r2, uint32_t& r3,
                                      uint32_t addr) {
    asm volatile("ldmatrix.sync.aligned.m8n8.x4.shared.b16 {%0,%1,%2,%3}, [%4];"
                 : "=r"(r0), "=r"(r1), "=r"(r2), "=r"(r3) : "r"(addr));
}

__device__ __forceinline__ void ldsm4t(uint32_t& r0, uint32_t& r1,
                                       uint32_t& r2, uint32_t& r3,
                                       uint32_t addr) {
    asm volatile("ldmatrix.sync.aligned.m8n8.x4.trans.shared.b16 {%0,%1,%2,%3}, [%4];"
                 : "=r"(r0), "=r"(r1), "=r"(r2), "=r"(r3) : "r"(addr));
}

__device__ __forceinline__ void mma16816(float* c, const uint32_t* a,
                                         uint32_t b0, uint32_t b1) {
    asm volatile(
        "mma.sync.aligned.m16n8k16.row.col.f32.bf16.bf16.f32 "
        "{%0,%1,%2,%3}, {%4,%5,%6,%7}, {%8,%9}, {%0,%1,%2,%3};"
        : "+f"(c[0]), "+f"(c[1]), "+f"(c[2]), "+f"(c[3])
        : "r"(a[0]), "r"(a[1]), "r"(a[2]), "r"(a[3]), "r"(b0), "r"(b1));
}

// hi/lo bf16 split of a float pair -> two packed bf16x2 regs
__device__ __forceinline__ void hl_pack(float a, float b, uint32_t& hi, uint32_t& lo) {
    __nv_bfloat162 h = __float22bfloat162_rn(make_float2(a, b));
    float2 f = __bfloat1622float2(h);
    __nv_bfloat162 l = __float22bfloat162_rn(make_float2(a - f.x, b - f.y));
    hi = *reinterpret_cast<uint32_t*>(&h);
    lo = *reinterpret_cast<uint32_t*>(&l);
}

__device__ __forceinline__ void hl2_store(float a, float b,
                                          __nv_bfloat16* hip, __nv_bfloat16* lop) {
    uint32_t hi, lo;
    hl_pack(a, b, hi, lo);
    *(uint32_t*)hip = hi;
    *(uint32_t*)lop = lo;
}

__device__ __forceinline__ void hl4_store(float4 v, __nv_bfloat16* hip,
                                          __nv_bfloat16* lop) {
    hl2_store(v.x, v.y, hip, lop);
    hl2_store(v.z, v.w, hip + 2, lop + 2);
}

// ---------------------------------------------------------------------------
// Kernel 0: mask preprocessing (compaction) + bias concat
// ---------------------------------------------------------------------------
__global__ __launch_bounds__(256)
void prep_kernel(const void* __restrict__ mask,
                 const float* __restrict__ bq,
                 const float* __restrict__ bk,
                 const float* __restrict__ bv)
{
    __shared__ int s_packed;
    __shared__ int s_cnt[4];
    if (threadIdx.x == 0) s_packed = 0;
    __syncthreads();

    const unsigned* mw = (const unsigned*)mask;
    int bad = 0;
    for (int i = threadIdx.x; i < 2048; i += 256)
        if (mw[i] > 1u) bad = 1;
    if (bad) atomicOr(&s_packed, 1);
    __syncthreads();
    const bool packed = (s_packed != 0);

    const int* mi = (const int*)mask;
    const unsigned char* mb = (const unsigned char*)mask;

    // Per-batch compaction: warp w handles batch w via ballot scan.
    const int warp = threadIdx.x >> 5, lane = threadIdx.x & 31;
    if (warp < 4) {
        int cnt = 0;
        for (int base = 0; base < NN; base += 32) {
            const int i = warp * NN + base + lane;
            const int on = packed ? (int)mb[i] : mi[i];
            const unsigned bal = __ballot_sync(0xffffffffu, on != 0);
            if (on)
                g_gidx[warp * NN + cnt + __popc(bal & ((1u << lane) - 1))] = base + lane;
            cnt += __popc(bal);
        }
        if (lane == 0) s_cnt[warp] = cnt;
    }
    __syncthreads();

    for (int i = threadIdx.x; i < BB * NN; i += 256) {
        const int bb = i >> 11, j = i & 2047;
        const int cnt = s_cnt[bb];
        g_padbias[i] = (j < cnt) ? 0.0f : -1e30f;
        if (j >= cnt) g_gidx[i] = 0;
    }
    if (threadIdx.x < 4) g_cnt[threadIdx.x] = s_cnt[threadIdx.x];

    for (int i = threadIdx.x; i < DD; i += 256) {
        g_bqkv[i]          = bq[i];
        g_bqkv[DD + i]     = bk[i];
        g_bqkv[2 * DD + i] = bv[i];
    }
}

// ---------------------------------------------------------------------------
// Kernel W: split all four W[1024x1024] into hi/lo bf16 (grid.y = slot)
// ---------------------------------------------------------------------------
__global__ __launch_bounds__(256)
void wconv_kernel(const float* __restrict__ W0, const float* __restrict__ W1,
                  const float* __restrict__ W2, const float* __restrict__ W3)
{
    const int slot = blockIdx.y;
    const float* W = (slot == 0) ? W0 : (slot == 1) ? W1 : (slot == 2) ? W2 : W3;
    const size_t i = ((size_t)blockIdx.x * 256 + threadIdx.x) * 4;
    float4 v = *(const float4*)(W + i);
    const size_t off = (size_t)slot * DD * DD + i;
    hl4_store(v, g_whi + off, g_wlo + off);
}

// ---------------------------------------------------------------------------
// Kernel 1: row LayerNorm over D=1024 -> hi/lo bf16
// ---------------------------------------------------------------------------
__global__ __launch_bounds__(256)
void ln_x_kernel(const float* __restrict__ x,
                 const float* __restrict__ w,
                 const float* __restrict__ b)
{
    __shared__ float red_s[8];
    __shared__ float red_q[8];
    __shared__ float stats[2];
    const int row = blockIdx.x;
    const int t = threadIdx.x;
    const int lane = t & 31, warp = t >> 5;

    const float* xr = x + (long)row * DD;
    float4 xv = *(const float4*)(xr + t * 4);
    float sum = xv.x + xv.y + xv.z + xv.w;
    float ssq = fmaf(xv.x, xv.x, fmaf(xv.y, xv.y, fmaf(xv.z, xv.z, xv.w * xv.w)));
    #pragma unroll
    for (int o = 16; o > 0; o >>= 1) {
        sum += __shfl_xor_sync(0xffffffffu, sum, o);
        ssq += __shfl_xor_sync(0xffffffffu, ssq, o);
    }
    if (lane == 0) { red_s[warp] = sum; red_q[warp] = ssq; }
    __syncthreads();
    if (warp == 0) {
        float a = (lane < 8) ? red_s[lane] : 0.0f;
        float c = (lane < 8) ? red_q[lane] : 0.0f;
        #pragma unroll
        for (int o = 4; o > 0; o >>= 1) {
            a += __shfl_xor_sync(0xffffffffu, a, o);
            c += __shfl_xor_sync(0xffffffffu, c, o);
        }
        if (lane == 0) { stats[0] = a * (1.0f / DD); stats[1] = c * (1.0f / DD); }
    }
    __syncthreads();
    const float mean = stats[0];
    const float var = stats[1] - mean * mean;
    const float rstd = rsqrtf(var + LN_EPS);

    float4 wv = *(const float4*)(w + t * 4);
    float4 bv = *(const float4*)(b + t * 4);
    float4 ov;
    ov.x = (xv.x - mean) * rstd * wv.x + bv.x;
    ov.y = (xv.y - mean) * rstd * wv.y + bv.y;
    ov.z = (xv.z - mean) * rstd * wv.z + bv.z;
    ov.w = (xv.w - mean) * rstd * wv.w + bv.w;
    const size_t off = (size_t)row * DD + t * 4;
    hl4_store(ov, g_xn_hi + off, g_xn_lo + off);
}

// ---------------------------------------------------------------------------
// Kernel 2: HMMA bf16x3 GEMM, cp.async double-buffered, K-slab 32.
// 128x128 CTA tile, 8 warps (4M x 2N), warp tile 32x64, 256 threads.
// MODE 0: A=g_ao(hi/lo), B=Wo slot3, C=Cout plain (grid 8x64).
// MODE 4: fused QKV+headLN: q,k get per-head LN in the epilogue (quad-reduce
//         over DH=64, which aligns with the warp's 64-wide N slab) -> hi/lo;
//         v -> hi/lo with bias.
// ---------------------------------------------------------------------------
#define KSL 32
#define SST2 40
#define BUF2 (128 * SST2)
#define STAGE_ELE (4 * BUF2)
#define GEMM_SMEM2 (2 * STAGE_ELE * 2)

template<int MODE>
__global__ __launch_bounds__(256, 2)
void gemm_mma2(float* __restrict__ Cout,
               const float* __restrict__ qn_w, const float* __restrict__ qn_b,
               const float* __restrict__ kn_w, const float* __restrict__ kn_b)
{
    extern __shared__ __nv_bfloat16 smg[];
    const uint32_t u0 = s2u(smg);

    const int tid = threadIdx.x;
    const int wid = tid >> 5, lane = tid & 31;
    const int wm = (wid & 3) << 5;
    const int wn = (wid >> 2) << 6;
    const int bm = blockIdx.y << 7;
    const int bn = blockIdx.x << 7;

    const __nv_bfloat16* gAh = (MODE == 0) ? g_ao_hi : g_xn_hi;
    const __nv_bfloat16* gAl = (MODE == 0) ? g_ao_lo : g_xn_lo;
    const __nv_bfloat16* gBh = (MODE == 0) ? (g_whi + (size_t)3 * DD * DD) : g_whi;
    const __nv_bfloat16* gBl = (MODE == 0) ? (g_wlo + (size_t)3 * DD * DD) : g_wlo;

    float acc[2][8][4];
    #pragma unroll
    for (int i = 0; i < 2; i++)
        #pragma unroll
        for (int j = 0; j < 8; j++)
            #pragma unroll
            for (int k = 0; k < 4; k++) acc[i][j][k] = 0.0f;

    const int lrow = tid >> 1;
    const int lhalf = (tid & 1) << 4;
    const __nv_bfloat16* pAh = gAh + (size_t)(bm + lrow) * DD + lhalf;
    const __nv_bfloat16* pAl = gAl + (size_t)(bm + lrow) * DD + lhalf;
    const __nv_bfloat16* pBh = gBh + (size_t)(bn + lrow) * DD + lhalf;
    const __nv_bfloat16* pBl = gBl + (size_t)(bn + lrow) * DD + lhalf;
    const uint32_t dbase = u0 + (lrow * SST2 + lhalf) * 2;

    const int aRow = (lane & 7) + ((lane & 8) ? 8 : 0);
    const int aK   = (lane & 16) ? 8 : 0;
    const int bRow = (lane & 7) + ((lane & 16) ? 8 : 0);
    const int bK   = (lane & 8) ? 8 : 0;

    #define ISSUE_STAGE(kt, stg) do {                                        \
        const uint32_t d_ = dbase + (stg) * (STAGE_ELE * 2);                  \
        cpa16(d_ + 0 * BUF2 * 2,      pAh + (kt));                            \
        cpa16(d_ + 0 * BUF2 * 2 + 16, pAh + (kt) + 8);                        \
        cpa16(d_ + 1 * BUF2 * 2,      pAl + (kt));                            \
        cpa16(d_ + 1 * BUF2 * 2 + 16, pAl + (kt) + 8);                        \
        cpa16(d_ + 2 * BUF2 * 2,      pBh + (kt));                            \
        cpa16(d_ + 2 * BUF2 * 2 + 16, pBh + (kt) + 8);                        \
        cpa16(d_ + 3 * BUF2 * 2,      pBl + (kt));                            \
        cpa16(d_ + 3 * BUF2 * 2 + 16, pBl + (kt) + 8);                        \
        CP_COMMIT();                                                          \
    } while (0)

    ISSUE_STAGE(0, 0);

    const int NSLAB = DD / KSL;
    for (int s = 0; s < NSLAB; s++) {
        if (s + 1 < NSLAB) {
            ISSUE_STAGE((s + 1) * KSL, (s + 1) & 1);
            CP_WAIT(1);
        } else {
            CP_WAIT(0);
        }
        __syncthreads();

        const uint32_t sb = u0 + (s & 1) * (STAGE_ELE * 2);
        const uint32_t aAh = sb + ((wm + aRow) * SST2 + aK) * 2;
        const uint32_t aAl = aAh + BUF2 * 2;
        const uint32_t aBh = sb + 2 * BUF2 * 2 + ((wn + bRow) * SST2 + bK) * 2;
        const uint32_t aBl = aBh + BUF2 * 2;

        #pragma unroll
        for (int k16 = 0; k16 < 2; k16++) {
            const uint32_t koff = (k16 << 4) * 2;
            uint32_t ah[2][4], al[2][4];
            #pragma unroll
            for (int mt = 0; mt < 2; mt++) {
                const uint32_t moff = (mt << 4) * SST2 * 2;
                ldsm4(ah[mt][0], ah[mt][1], ah[mt][2], ah[mt][3], aAh + moff + koff);
                ldsm4(al[mt][0], al[mt][1], al[mt][2], al[mt][3], aAl + moff + koff);
            }
            #pragma unroll
            for (int p = 0; p < 4; p++) {
                const uint32_t noff = (p << 4) * SST2 * 2;
                uint32_t bh0, bh1, bh2, bh3, bl0, bl1, bl2, bl3;
                ldsm4(bh0, bh1, bh2, bh3, aBh + noff + koff);
                ldsm4(bl0, bl1, bl2, bl3, aBl + noff + koff);
                #pragma unroll
                for (int mt = 0; mt < 2; mt++) {
                    mma16816(acc[mt][2 * p + 0], ah[mt], bh0, bh1);
                    mma16816(acc[mt][2 * p + 1], ah[mt], bh2, bh3);
                }
                #pragma unroll
                for (int mt = 0; mt < 2; mt++) {
                    mma16816(acc[mt][2 * p + 0], ah[mt], bl0, bl1);
                    mma16816(acc[mt][2 * p + 1], ah[mt], bl2, bl3);
                }
                #pragma unroll
                for (int mt = 0; mt < 2; mt++) {
                    mma16816(acc[mt][2 * p + 0], al[mt], bh0, bh1);
                    mma16816(acc[mt][2 * p + 1], al[mt], bh2, bh3);
                }
            }
        }
        __syncthreads();
    }
    #undef ISSUE_STAGE

    // Epilogue
    const int g = lane >> 2, tq = lane & 3;
    if (MODE == 0) {
        #pragma unroll
        for (int mt = 0; mt < 2; mt++)
            #pragma unroll
            for (int nt = 0; nt < 8; nt++) {
                const int c = bn + wn + nt * 8 + 2 * tq;
                #pragma unroll
                for (int half = 0; half < 2; half++) {
                    const int r = bm + wm + mt * 16 + g + half * 8;
                    float2 v;
                    v.x = acc[mt][nt][2 * half + 0];
                    v.y = acc[mt][nt][2 * half + 1];
                    *(float2*)(Cout + (size_t)r * DD + c) = v;
                }
            }
    } else {
        const int which = (bn + wn) >> 10;           // constant per warp
        const int h = ((bn + wn) & 1023) >> 6;       // head index
        if (which < 2) {
            // q or k: fused per-head LayerNorm over DH=64 (quad reduce)
            const float* wvec = which ? kn_w : qn_w;
            const float* bvec = which ? kn_b : qn_b;
            __nv_bfloat16* oh = which ? g_kh : g_qh;
            __nv_bfloat16* ol = which ? g_kl : g_ql;
            const float sc = which ? 1.0f : 0.125f;
            #pragma unroll
            for (int mt = 0; mt < 2; mt++)
                #pragma unroll
                for (int half = 0; half < 2; half++) {
                    const int r = bm + wm + mt * 16 + g + half * 8;
                    float v[16];
                    float sum = 0.0f, ssq = 0.0f;
                    #pragma unroll
                    for (int nt = 0; nt < 8; nt++) {
                        const int c = bn + wn + nt * 8 + 2 * tq;
                        const float2 bb = *(const float2*)(g_bqkv + c);
                        const float a0 = acc[mt][nt][2 * half + 0] + bb.x;
                        const float a1 = acc[mt][nt][2 * half + 1] + bb.y;
                        v[2 * nt + 0] = a0;
                        v[2 * nt + 1] = a1;
                        sum += a0 + a1;
                        ssq = fmaf(a0, a0, fmaf(a1, a1, ssq));
                    }
                    sum += __shfl_xor_sync(0xffffffffu, sum, 1);
                    sum += __shfl_xor_sync(0xffffffffu, sum, 2);
                    ssq += __shfl_xor_sync(0xffffffffu, ssq, 1);
                    ssq += __shfl_xor_sync(0xffffffffu, ssq, 2);
                    const float mean = sum * (1.0f / DH);
                    const float var = ssq * (1.0f / DH) - mean * mean;
                    const float rstd = rsqrtf(var + LN_EPS);
                    const size_t rowoff =
                        ((((size_t)((r >> 11) * HH + h)) * NN + (r & 2047)) << 6);
                    #pragma unroll
                    for (int nt = 0; nt < 8; nt++) {
                        const int dh = nt * 8 + 2 * tq;
                        const float2 wv = *(const float2*)(wvec + dh);
                        const float2 b2 = *(const float2*)(bvec + dh);
                        const float a = ((v[2 * nt + 0] - mean) * rstd * wv.x + b2.x) * sc;
                        const float c2 = ((v[2 * nt + 1] - mean) * rstd * wv.y + b2.y) * sc;
                        hl2_store(a, c2, oh + rowoff + dh, ol + rowoff + dh);
                    }
                }
        } else {
            // v: bias + hi/lo store
            #pragma unroll
            for (int mt = 0; mt < 2; mt++)
                #pragma unroll
                for (int nt = 0; nt < 8; nt++) {
                    const int c = bn + wn + nt * 8 + 2 * tq;
                    const float2 bb = *(const float2*)(g_bqkv + c);
                    #pragma unroll
                    for (int half = 0; half < 2; half++) {
                        const int r = bm + wm + mt * 16 + g + half * 8;
                        const float a0 = acc[mt][nt][2 * half + 0] + bb.x;
                        const float a1 = acc[mt][nt][2 * half + 1] + bb.y;
                        const size_t idx =
                            ((((size_t)((r >> 11) * HH + h)) * NN + (r & 2047)) << 6)
                            + ((c & 1023) & 63);
                        hl2_store(a0, a1, g_vh + idx, g_vl + idx);
                    }
                }
        }
    }
}

// ---------------------------------------------------------------------------
// Kernel 4: tensor-core flash attention over COMPACTED keys
// (bf16x3 QK^T and PV), cp.async double-buffered gathered K/V + bias tiles.
// grid (16, 16, 4): 128 queries x one (b,h) per CTA; 8 warps x 16 q-rows.
// ---------------------------------------------------------------------------
#define ASTR 72
#define ATT_STAGE (4 * 64 * ASTR)
#define ATT_SMEM (2 * ATT_STAGE * 2 + 2 * 64 * 4)

__global__ __launch_bounds__(256)
void attn_mma_kernel()
{
    extern __shared__ __nv_bfloat16 sma[];
    const uint32_t u0 = s2u(sma);
    float* mbs = (float*)(sma + 2 * ATT_STAGE);
    const uint32_t mb_u = u0 + 2 * ATT_STAGE * 2;

    const int tid = threadIdx.x, wid = tid >> 5, lane = tid & 31;
    const int bq = blockIdx.x << 7;
    const int h = blockIdx.y, b = blockIdx.z;
    const size_t head_off = ((size_t)(b * HH + h)) * NN;

    const int aRow = (lane & 7) + ((lane & 8) ? 8 : 0);
    const int aK   = (lane & 16) ? 8 : 0;
    const int bRow = (lane & 7) + ((lane & 16) ? 8 : 0);
    const int bK   = (lane & 8) ? 8 : 0;
    const int vRow = (lane & 7) + ((lane & 8) ? 8 : 0);
    const int vCol = (lane & 16) ? 8 : 0;

    // ---- Phase 1: stage Q hi then Q lo through rows [0,128) (two passes)
    uint32_t qh[4][4], ql[4][4];
    {
        const int r = tid >> 1;
        const int c = (tid & 1) << 5;
        const uint32_t qb = u0 + ((wid * 16 + aRow) * ASTR + aK) * 2;

        const __nv_bfloat16* sh = g_qh + (head_off + bq + r) * DH + c;
        #pragma unroll
        for (int i = 0; i < 4; i++)
            *(uint4*)(sma + r * ASTR + c + i * 8) = *(const uint4*)(sh + i * 8);
        __syncthreads();
        #pragma unroll
        for (int k = 0; k < 4; k++)
            ldsm4(qh[k][0], qh[k][1], qh[k][2], qh[k][3], qb + (k * 16) * 2);
        __syncthreads();

        const __nv_bfloat16* sl = g_ql + (head_off + bq + r) * DH + c;
        #pragma unroll
        for (int i = 0; i < 4; i++)
            *(uint4*)(sma + r * ASTR + c + i * 8) = *(const uint4*)(sl + i * 8);
        __syncthreads();
        #pragma unroll
        for (int k = 0; k < 4; k++)
            ldsm4(ql[k][0], ql[k][1], ql[k][2], ql[k][3], qb + (k * 16) * 2);
        __syncthreads();
    }

    float o[8][4];
    #pragma unroll
    for (int i = 0; i < 8; i++)
        #pragma unroll
        for (int j = 0; j < 4; j++) o[i][j] = 0.0f;
    float m0 = -1e30f, m1 = -1e30f, l0 = 0.0f, l1 = 0.0f;

    const float* mrow = g_padbias + b * NN;
    const int* gidx = g_gidx + b * NN;
    const int cnt = g_cnt[b];
    const int NT = (cnt + 63) >> 6;
    const int tq2 = (lane & 3) * 2;

    const int ldr = tid >> 2;
    const int ldc = (tid & 3) << 4;
    const uint32_t sdst = u0 + (ldr * ASTR + ldc) * 2;

    #define ISSUE_ATT(kt, stg) do {                                           \
        const uint32_t d_ = sdst + (stg) * (ATT_STAGE * 2);                    \
        const int srow_ = gidx[(kt) + ldr];                                    \
        const size_t gi_ = (head_off + srow_) * DH + ldc;                      \
        cpa16(d_ + 0 * 64 * ASTR * 2,      g_kh + gi_);                        \
        cpa16(d_ + 0 * 64 * ASTR * 2 + 16, g_kh + gi_ + 8);                    \
        cpa16(d_ + 1 * 64 * ASTR * 2,      g_kl + gi_);                        \
        cpa16(d_ + 1 * 64 * ASTR * 2 + 16, g_kl + gi_ + 8);                    \
        cpa16(d_ + 2 * 64 * ASTR * 2,      g_vh + gi_);                        \
        cpa16(d_ + 2 * 64 * ASTR * 2 + 16, g_vh + gi_ + 8);                    \
        cpa16(d_ + 3 * 64 * ASTR * 2,      g_vl + gi_);                        \
        cpa16(d_ + 3 * 64 * ASTR * 2 + 16, g_vl + gi_ + 8);                    \
        if (tid < 16)                                                          \
            cpa16(mb_u + (stg) * 256 + tid * 16, mrow + (kt) + tid * 4);       \
        CP_COMMIT();                                                           \
    } while (0)

    ISSUE_ATT(0, 0);

    for (int ti = 0; ti < NT; ti++) {
        if (ti + 1 < NT) {
            ISSUE_ATT((ti + 1) * 64, (ti + 1) & 1);
            CP_WAIT(1);
        } else {
            CP_WAIT(0);
        }
        __syncthreads();

        const uint32_t sb = u0 + (ti & 1) * (ATT_STAGE * 2);
        const uint32_t Kh = sb;
        const uint32_t Kl = sb + 64 * ASTR * 2;
        const uint32_t Vh = sb + 2 * 64 * ASTR * 2;
        const uint32_t Vl = sb + 3 * 64 * ASTR * 2;
        const float* mb = mbs + (ti & 1) * 64;

        // S = Q K^T  (bf16x3), pass-major
        float s[8][4];
        #pragma unroll
        for (int i = 0; i < 8; i++)
            #pragma unroll
            for (int j = 0; j < 4; j++) s[i][j] = 0.0f;

        #pragma unroll
        for (int k = 0; k < 4; k++) {
            uint32_t kh[4][4], kl[4][4];
            #pragma unroll
            for (int p = 0; p < 4; p++) {
                const uint32_t nb = ((p * 16 + bRow) * ASTR + k * 16 + bK) * 2;
                ldsm4(kh[p][0], kh[p][1], kh[p][2], kh[p][3], Kh + nb);
                ldsm4(kl[p][0], kl[p][1], kl[p][2], kl[p][3], Kl + nb);
            }
            #pragma unroll
            for (int p = 0; p < 4; p++) {
                mma16816(s[2 * p + 0], qh[k], kh[p][0], kh[p][1]);
                mma16816(s[2 * p + 1], qh[k], kh[p][2], kh[p][3]);
            }
            #pragma unroll
            for (int p = 0; p < 4; p++) {
                mma16816(s[2 * p + 0], qh[k], kl[p][0], kl[p][1]);
                mma16816(s[2 * p + 1], qh[k], kl[p][2], kl[p][3]);
            }
            #pragma unroll
            for (int p = 0; p < 4; p++) {
                mma16816(s[2 * p + 0], ql[k], kh[p][0], kh[p][1]);
                mma16816(s[2 * p + 1], ql[k], kh[p][2], kh[p][3]);
            }
        }

        // bias (tile padding) + online softmax
        float mx0 = -1e30f, mx1 = -1e30f;
        #pragma unroll
        for (int nt = 0; nt < 8; nt++) {
            const float b0 = mb[nt * 8 + tq2];
            const float b1 = mb[nt * 8 + tq2 + 1];
            s[nt][0] += b0; s[nt][1] += b1;
            s[nt][2] += b0; s[nt][3] += b1;
            mx0 = fmaxf(mx0, fmaxf(s[nt][0], s[nt][1]));
            mx1 = fmaxf(mx1, fmaxf(s[nt][2], s[nt][3]));
        }
        mx0 = fmaxf(mx0, __shfl_xor_sync(0xffffffffu, mx0, 1));
        mx0 = fmaxf(mx0, __shfl_xor_sync(0xffffffffu, mx0, 2));
        mx1 = fmaxf(mx1, __shfl_xor_sync(0xffffffffu, mx1, 1));
        mx1 = fmaxf(mx1, __shfl_xor_sync(0xffffffffu, mx1, 2));
        const float mn0 = fmaxf(m0, mx0), mn1 = fmaxf(m1, mx1);
        const float sc0 = __expf(m0 - mn0), sc1 = __expf(m1 - mn1);
        m0 = mn0; m1 = mn1;
        float ps0 = 0.0f, ps1 = 0.0f;
        #pragma unroll
        for (int nt = 0; nt < 8; nt++) {
            s[nt][0] = __expf(s[nt][0] - m0);
            s[nt][1] = __expf(s[nt][1] - m0);
            s[nt][2] = __expf(s[nt][2] - m1);
            s[nt][3] = __expf(s[nt][3] - m1);
            ps0 += s[nt][0] + s[nt][1];
            ps1 += s[nt][2] + s[nt][3];
        }
        ps0 += __shfl_xor_sync(0xffffffffu, ps0, 1);
        ps0 += __shfl_xor_sync(0xffffffffu, ps0, 2);
        ps1 += __shfl_xor_sync(0xffffffffu, ps1, 1);
        ps1 += __shfl_xor_sync(0xffffffffu, ps1, 2);
        l0 = l0 * sc0 + ps0;
        l1 = l1 * sc1 + ps1;
        #pragma unroll
        for (int nt = 0; nt < 8; nt++) {
            o[nt][0] *= sc0; o[nt][1] *= sc0;
            o[nt][2] *= sc1; o[nt][3] *= sc1;
        }

        // O += P V   (P hi/lo x V hi/lo, 3 passes; p in pairs)
        #pragma unroll
        for (int jj = 0; jj < 4; jj++) {
            uint32_t ph[4], pl[4];
            hl_pack(s[2 * jj][0],     s[2 * jj][1],     ph[0], pl[0]);
            hl_pack(s[2 * jj][2],     s[2 * jj][3],     ph[1], pl[1]);
            hl_pack(s[2 * jj + 1][0], s[2 * jj + 1][1], ph[2], pl[2]);
            hl_pack(s[2 * jj + 1][2], s[2 * jj + 1][3], ph[3], pl[3]);
            #pragma unroll
            for (int pp = 0; pp < 2; pp++) {
                uint32_t vh[2][4], vl[2][4];
                #pragma unroll
                for (int q = 0; q < 2; q++) {
                    const int p = pp * 2 + q;
                    const uint32_t off = ((jj * 16 + vRow) * ASTR + p * 16 + vCol) * 2;
                    ldsm4t(vh[q][0], vh[q][1], vh[q][2], vh[q][3], Vh + off);
                    ldsm4t(vl[q][0], vl[q][1], vl[q][2], vl[q][3], Vl + off);
                }
                #pragma unroll
                for (int q = 0; q < 2; q++) {
                    const int p = pp * 2 + q;
                    mma16816(o[2 * p + 0], ph, vh[q][0], vh[q][1]);
                    mma16816(o[2 * p + 1], ph, vh[q][2], vh[q][3]);
                }
                #pragma unroll
                for (int q = 0; q < 2; q++) {
                    const int p = pp * 2 + q;
                    mma16816(o[2 * p + 0], ph, vl[q][0], vl[q][1]);
                    mma16816(o[2 * p + 1], ph, vl[q][2], vl[q][3]);
                }
                #pragma unroll
                for (int q = 0; q < 2; q++) {
                    const int p = pp * 2 + q;
                    mma16816(o[2 * p + 0], pl, vh[q][0], vh[q][1]);
                    mma16816(o[2 * p + 1], pl, vh[q][2], vh[q][3]);
                }
            }
        }
        __syncthreads();
    }
    #undef ISSUE_ATT

    // epilogue -> g_ao hi/lo   [b, n, h*64+dh]
    const float inv0 = 1.0f / l0, inv1 = 1.0f / l1;
    const int g = lane >> 2;
    const int q0 = bq + wid * 16 + g;
    const size_t ob = ((size_t)(b * NN) + q0) * DD + h * DH;
    #pragma unroll
    for (int nt = 0; nt < 8; nt++) {
        const int dh = nt * 8 + tq2;
        hl2_store(o[nt][0] * inv0, o[nt][1] * inv0, g_ao_hi + ob + dh, g_ao_lo + ob + dh);
        hl2_store(o[nt][2] * inv1, o[nt][3] * inv1,
                  g_ao_hi + ob + 8 * DD + dh, g_ao_lo + ob + 8 * DD + dh);
    }
}

// ---------------------------------------------------------------------------
// Launch
// ---------------------------------------------------------------------------
extern "C" void kernel_launch(void* const* d_in, const int* in_sizes, int n_in,
                              void* d_out, int out_size)
{
    const float* x       = (const float*)d_in[0];
    const void*  mask    = (const void*)d_in[1];
    const float* norm_w  = (const float*)d_in[2];
    const float* norm_b  = (const float*)d_in[3];
    const float* qn_w    = (const float*)d_in[4];
    const float* qn_b    = (const float*)d_in[5];
    const float* kn_w    = (const float*)d_in[6];
    const float* kn_b    = (const float*)d_in[7];
    const float* Wq      = (const float*)d_in[8];
    const float* bq      = (const float*)d_in[9];
    const float* Wk      = (const float*)d_in[10];
    const float* bk      = (const float*)d_in[11];
    const float* Wv      = (const float*)d_in[12];
    const float* bv      = (const float*)d_in[13];
    const float* Wo      = (const float*)d_in[14];
    float* out = (float*)d_out;

    static bool attr_done = false;
    if (!attr_done) {
        cudaFuncSetAttribute(gemm_mma2<0>, cudaFuncAttributeMaxDynamicSharedMemorySize, GEMM_SMEM2);
        cudaFuncSetAttribute(gemm_mma2<4>, cudaFuncAttributeMaxDynamicSharedMemorySize, GEMM_SMEM2);
        cudaFuncSetAttribute(attn_mma_kernel, cudaFuncAttributeMaxDynamicSharedMemorySize, ATT_SMEM);
        attr_done = true;
    }

    // 0. Mask compaction + bias concat; W -> hi/lo bf16
    prep_kernel<<<1, 256>>>(mask, bq, bk, bv);
    wconv_kernel<<<dim3(1024, 4), 256>>>(Wq, Wk, Wv, Wo);

    // 1. LN(x) -> hi/lo bf16
    ln_x_kernel<<<BN, 256>>>(x, norm_w, norm_b);

    // 2. Fused QKV projection + head-LN epilogue (cp.async pipelined bf16x3)
    gemm_mma2<4><<<dim3(3 * DD / 128, BN / 128), 256, GEMM_SMEM2>>>(
        nullptr, qn_w, qn_b, kn_w, kn_b);

    // 3. Tensor-core flash attention over compacted keys -> g_ao hi/lo
    attn_mma_kernel<<<dim3(NN / 128, HH, BB), 256, ATT_SMEM>>>();

    // 4. Output projection -> d_out
    gemm_mma2<0><<<dim3(DD / 128, BN / 128), 256, GEMM_SMEM2>>>(
        out, nullptr, nullptr, nullptr, nullptr);
}

// round 14
// speedup vs baseline: 1.6798x; 1.1301x over previous
#include <cuda_runtime.h>
#include <cuda_bf16.h>
#include <cstdint>

// Problem constants
#define BB 4
#define NN 2048
#define DD 1024
#define HH 16
#define DH 64
#define BN (BB*NN)          // 8192
#define LN_EPS 1e-5f

// ---------------------------------------------------------------------------
// Device scratch (no allocation allowed)
// ---------------------------------------------------------------------------
__device__ __nv_bfloat16 g_xn_hi[BN * DD];
__device__ __nv_bfloat16 g_xn_lo[BN * DD];
__device__ __nv_bfloat16 g_ao_hi[BN * DD];
__device__ __nv_bfloat16 g_ao_lo[BN * DD];
__device__ __nv_bfloat16 g_whi[4 * DD * DD];
__device__ __nv_bfloat16 g_wlo[4 * DD * DD];
__device__ __nv_bfloat16 g_qh[BB * HH * NN * DH];
__device__ __nv_bfloat16 g_ql[BB * HH * NN * DH];
__device__ __nv_bfloat16 g_kh[BB * HH * NN * DH];   // compacted key order
__device__ __nv_bfloat16 g_kl[BB * HH * NN * DH];
__device__ __nv_bfloat16 g_vh[BB * HH * NN * DH];
__device__ __nv_bfloat16 g_vl[BB * HH * NN * DH];
__device__ float g_bqkv[3 * DD];
__device__ int   g_gidx[BB * NN];    // compacted->original index (pad 0)
__device__ int   g_cnt[BB];          // unmasked key count per batch
__device__ float g_padbias[BB * NN]; // 0 for j<cnt, -1e30 beyond

// ---------------------------------------------------------------------------
// Helpers
// ---------------------------------------------------------------------------
__device__ __forceinline__ uint32_t s2u(const void* p) {
    uint32_t a;
    asm("{ .reg .u64 t; cvta.to.shared.u64 t, %1; cvt.u32.u64 %0, t; }"
        : "=r"(a) : "l"(p));
    return a;
}

__device__ __forceinline__ void cpa16(uint32_t dst, const void* src) {
    asm volatile("cp.async.cg.shared.global [%0], [%1], 16;"
                 :: "r"(dst), "l"(src) : "memory");
}
#define CP_COMMIT() asm volatile("cp.async.commit_group;" ::: "memory")
#define CP_WAIT(N)  asm volatile("cp.async.wait_group %0;" :: "n"(N) : "memory")

__device__ __forceinline__ void ldsm4(uint32_t& r0, uint32_t& r1,
                                      uint32_t& r2, uint32_t& r3,
                                      uint32_t addr) {
    asm volatile("ldmatrix.sync.aligned.m8n8.x4.shared.b16 {%0,%1,%2,%3}, [%4];"
                 : "=r"(r0), "=r"(r1), "=r"(r2), "=r"(r3) : "r"(addr));
}

__device__ __forceinline__ void ldsm4t(uint32_t& r0, uint32_t& r1,
                                       uint32_t& r2, uint32_t& r3,
                                       uint32_t addr) {
    asm volatile("ldmatrix.sync.aligned.m8n8.x4.trans.shared.b16 {%0,%1,%2,%3}, [%4];"
                 : "=r"(r0), "=r"(r1), "=r"(r2), "=r"(r3) : "r"(addr));
}

__device__ __forceinline__ void mma16816(float* c, const uint32_t* a,
                                         uint32_t b0, uint32_t b1) {
    asm volatile(
        "mma.sync.aligned.m16n8k16.row.col.f32.bf16.bf16.f32 "
        "{%0,%1,%2,%3}, {%4,%5,%6,%7}, {%8,%9}, {%0,%1,%2,%3};"
        : "+f"(c[0]), "+f"(c[1]), "+f"(c[2]), "+f"(c[3])
        : "r"(a[0]), "r"(a[1]), "r"(a[2]), "r"(a[3]), "r"(b0), "r"(b1));
}

// hi/lo bf16 split of a float pair -> two packed bf16x2 regs
__device__ __forceinline__ void hl_pack(float a, float b, uint32_t& hi, uint32_t& lo) {
    __nv_bfloat162 h = __float22bfloat162_rn(make_float2(a, b));
    float2 f = __bfloat1622float2(h);
    __nv_bfloat162 l = __float22bfloat162_rn(make_float2(a - f.x, b - f.y));
    hi = *reinterpret_cast<uint32_t*>(&h);
    lo = *reinterpret_cast<uint32_t*>(&l);
}

__device__ __forceinline__ void hl2_store(float a, float b,
                                          __nv_bfloat16* hip, __nv_bfloat16* lop) {
    uint32_t hi, lo;
    hl_pack(a, b, hi, lo);
    *(uint32_t*)hip = hi;
    *(uint32_t*)lop = lo;
}

__device__ __forceinline__ void hl4_store(float4 v, __nv_bfloat16* hip,
                                          __nv_bfloat16* lop) {
    hl2_store(v.x, v.y, hip, lop);
    hl2_store(v.z, v.w, hip + 2, lop + 2);
}

// ---------------------------------------------------------------------------
// Kernel 0: mask preprocessing (compaction) + bias concat
// ---------------------------------------------------------------------------
__global__ __launch_bounds__(256)
void prep_kernel(const void* __restrict__ mask,
                 const float* __restrict__ bq,
                 const float* __restrict__ bk,
                 const float* __restrict__ bv)
{
    __shared__ int s_packed;
    __shared__ int s_cnt[4];
    if (threadIdx.x == 0) s_packed = 0;
    __syncthreads();

    const unsigned* mw = (const unsigned*)mask;
    int bad = 0;
    for (int i = threadIdx.x; i < 2048; i += 256)
        if (mw[i] > 1u) bad = 1;
    if (bad) atomicOr(&s_packed, 1);
    __syncthreads();
    const bool packed = (s_packed != 0);

    const int* mi = (const int*)mask;
    const unsigned char* mb = (const unsigned char*)mask;

    const int warp = threadIdx.x >> 5, lane = threadIdx.x & 31;
    if (warp < 4) {
        int cnt = 0;
        for (int base = 0; base < NN; base += 32) {
            const int i = warp * NN + base + lane;
            const int on = packed ? (int)mb[i] : mi[i];
            const unsigned bal = __ballot_sync(0xffffffffu, on != 0);
            if (on)
                g_gidx[warp * NN + cnt + __popc(bal & ((1u << lane) - 1))] = base + lane;
            cnt += __popc(bal);
        }
        if (lane == 0) s_cnt[warp] = cnt;
    }
    __syncthreads();

    for (int i = threadIdx.x; i < BB * NN; i += 256) {
        const int bb = i >> 11, j = i & 2047;
        const int cnt = s_cnt[bb];
        g_padbias[i] = (j < cnt) ? 0.0f : -1e30f;
        if (j >= cnt) g_gidx[i] = 0;
    }
    if (threadIdx.x < 4) g_cnt[threadIdx.x] = s_cnt[threadIdx.x];

    for (int i = threadIdx.x; i < DD; i += 256) {
        g_bqkv[i]          = bq[i];
        g_bqkv[DD + i]     = bk[i];
        g_bqkv[2 * DD + i] = bv[i];
    }
}

// ---------------------------------------------------------------------------
// Kernel W: split all four W[1024x1024] into hi/lo bf16 (grid.y = slot)
// ---------------------------------------------------------------------------
__global__ __launch_bounds__(256)
void wconv_kernel(const float* __restrict__ W0, const float* __restrict__ W1,
                  const float* __restrict__ W2, const float* __restrict__ W3)
{
    const int slot = blockIdx.y;
    const float* W = (slot == 0) ? W0 : (slot == 1) ? W1 : (slot == 2) ? W2 : W3;
    const size_t i = ((size_t)blockIdx.x * 256 + threadIdx.x) * 4;
    float4 v = *(const float4*)(W + i);
    const size_t off = (size_t)slot * DD * DD + i;
    hl4_store(v, g_whi + off, g_wlo + off);
}

// ---------------------------------------------------------------------------
// Kernel 1: row LayerNorm over D=1024 -> hi/lo bf16
// ---------------------------------------------------------------------------
__global__ __launch_bounds__(256)
void ln_x_kernel(const float* __restrict__ x,
                 const float* __restrict__ w,
                 const float* __restrict__ b)
{
    __shared__ float red_s[8];
    __shared__ float red_q[8];
    __shared__ float stats[2];
    const int row = blockIdx.x;
    const int t = threadIdx.x;
    const int lane = t & 31, warp = t >> 5;

    const float* xr = x + (long)row * DD;
    float4 xv = *(const float4*)(xr + t * 4);
    float sum = xv.x + xv.y + xv.z + xv.w;
    float ssq = fmaf(xv.x, xv.x, fmaf(xv.y, xv.y, fmaf(xv.z, xv.z, xv.w * xv.w)));
    #pragma unroll
    for (int o = 16; o > 0; o >>= 1) {
        sum += __shfl_xor_sync(0xffffffffu, sum, o);
        ssq += __shfl_xor_sync(0xffffffffu, ssq, o);
    }
    if (lane == 0) { red_s[warp] = sum; red_q[warp] = ssq; }
    __syncthreads();
    if (warp == 0) {
        float a = (lane < 8) ? red_s[lane] : 0.0f;
        float c = (lane < 8) ? red_q[lane] : 0.0f;
        #pragma unroll
        for (int o = 4; o > 0; o >>= 1) {
            a += __shfl_xor_sync(0xffffffffu, a, o);
            c += __shfl_xor_sync(0xffffffffu, c, o);
        }
        if (lane == 0) { stats[0] = a * (1.0f / DD); stats[1] = c * (1.0f / DD); }
    }
    __syncthreads();
    const float mean = stats[0];
    const float var = stats[1] - mean * mean;
    const float rstd = rsqrtf(var + LN_EPS);

    float4 wv = *(const float4*)(w + t * 4);
    float4 bv = *(const float4*)(b + t * 4);
    float4 ov;
    ov.x = (xv.x - mean) * rstd * wv.x + bv.x;
    ov.y = (xv.y - mean) * rstd * wv.y + bv.y;
    ov.z = (xv.z - mean) * rstd * wv.z + bv.z;
    ov.w = (xv.w - mean) * rstd * wv.w + bv.w;
    const size_t off = (size_t)row * DD + t * 4;
    hl4_store(ov, g_xn_hi + off, g_xn_lo + off);
}

// ---------------------------------------------------------------------------
// Kernel 2: HMMA bf16x3 GEMM, cp.async double-buffered, K-slab 32.
// 128x128 CTA tile, 8 warps (4M x 2N), warp tile 32x64, 256 threads.
// MODE 0: out-proj.  A=g_ao, B=slot3, plain fp32 out. grid (8,64).
// MODE 1: Q proj.    A=g_xn (all rows), B=slot0, head-LN(q) epilogue. grid (8,64).
// MODE 5: KV proj.   A=g_xn GATHERED by g_gidx (compacted rows), B=slots1-2,
//         head-LN(k) / bias(v) epilogue at COMPACTED positions; early-exit
//         for tiles past cnt[b]. grid (16,64).
// ---------------------------------------------------------------------------
#define KSL 32
#define SST2 40
#define BUF2 (128 * SST2)
#define STAGE_ELE (4 * BUF2)
#define GEMM_SMEM2 (2 * STAGE_ELE * 2)

template<int MODE>
__global__ __launch_bounds__(256, 2)
void gemm_mma2(float* __restrict__ Cout,
               const float* __restrict__ qn_w, const float* __restrict__ qn_b,
               const float* __restrict__ kn_w, const float* __restrict__ kn_b)
{
    const int bm = blockIdx.y << 7;
    const int bn = blockIdx.x << 7;
    if (MODE == 5) {
        if ((bm & 2047) >= g_cnt[bm >> 11]) return;   // whole tile is padding
    }

    extern __shared__ __nv_bfloat16 smg[];
    const uint32_t u0 = s2u(smg);

    const int tid = threadIdx.x;
    const int wid = tid >> 5, lane = tid & 31;
    const int wm = (wid & 3) << 5;
    const int wn = (wid >> 2) << 6;

    const __nv_bfloat16* gAh = (MODE == 0) ? g_ao_hi : g_xn_hi;
    const __nv_bfloat16* gAl = (MODE == 0) ? g_ao_lo : g_xn_lo;
    const __nv_bfloat16* gBh = (MODE == 0) ? (g_whi + (size_t)3 * DD * DD)
                              : (MODE == 1) ? g_whi
                              : (g_whi + (size_t)1 * DD * DD);
    const __nv_bfloat16* gBl = (MODE == 0) ? (g_wlo + (size_t)3 * DD * DD)
                              : (MODE == 1) ? g_wlo
                              : (g_wlo + (size_t)1 * DD * DD);

    float acc[2][8][4];
    #pragma unroll
    for (int i = 0; i < 2; i++)
        #pragma unroll
        for (int j = 0; j < 8; j++)
            #pragma unroll
            for (int k = 0; k < 4; k++) acc[i][j][k] = 0.0f;

    const int lrow = tid >> 1;
    const int lhalf = (tid & 1) << 4;
    int arow;
    if (MODE == 5) arow = (bm & ~2047) + g_gidx[bm + lrow];
    else           arow = bm + lrow;
    const __nv_bfloat16* pAh = gAh + (size_t)arow * DD + lhalf;
    const __nv_bfloat16* pAl = gAl + (size_t)arow * DD + lhalf;
    const __nv_bfloat16* pBh = gBh + (size_t)(bn + lrow) * DD + lhalf;
    const __nv_bfloat16* pBl = gBl + (size_t)(bn + lrow) * DD + lhalf;
    const uint32_t dbase = u0 + (lrow * SST2 + lhalf) * 2;

    const int aRow = (lane & 7) + ((lane & 8) ? 8 : 0);
    const int aK   = (lane & 16) ? 8 : 0;
    const int bRow = (lane & 7) + ((lane & 16) ? 8 : 0);
    const int bK   = (lane & 8) ? 8 : 0;

    #define ISSUE_STAGE(kt, stg) do {                                        \
        const uint32_t d_ = dbase + (stg) * (STAGE_ELE * 2);                  \
        cpa16(d_ + 0 * BUF2 * 2,      pAh + (kt));                            \
        cpa16(d_ + 0 * BUF2 * 2 + 16, pAh + (kt) + 8);                        \
        cpa16(d_ + 1 * BUF2 * 2,      pAl + (kt));                            \
        cpa16(d_ + 1 * BUF2 * 2 + 16, pAl + (kt) + 8);                        \
        cpa16(d_ + 2 * BUF2 * 2,      pBh + (kt));                            \
        cpa16(d_ + 2 * BUF2 * 2 + 16, pBh + (kt) + 8);                        \
        cpa16(d_ + 3 * BUF2 * 2,      pBl + (kt));                            \
        cpa16(d_ + 3 * BUF2 * 2 + 16, pBl + (kt) + 8);                        \
        CP_COMMIT();                                                          \
    } while (0)

    ISSUE_STAGE(0, 0);

    const int NSLAB = DD / KSL;
    for (int s = 0; s < NSLAB; s++) {
        if (s + 1 < NSLAB) {
            ISSUE_STAGE((s + 1) * KSL, (s + 1) & 1);
            CP_WAIT(1);
        } else {
            CP_WAIT(0);
        }
        __syncthreads();

        const uint32_t sb = u0 + (s & 1) * (STAGE_ELE * 2);
        const uint32_t aAh = sb + ((wm + aRow) * SST2 + aK) * 2;
        const uint32_t aAl = aAh + BUF2 * 2;
        const uint32_t aBh = sb + 2 * BUF2 * 2 + ((wn + bRow) * SST2 + bK) * 2;
        const uint32_t aBl = aBh + BUF2 * 2;

        #pragma unroll
        for (int k16 = 0; k16 < 2; k16++) {
            const uint32_t koff = (k16 << 4) * 2;
            uint32_t ah[2][4], al[2][4];
            #pragma unroll
            for (int mt = 0; mt < 2; mt++) {
                const uint32_t moff = (mt << 4) * SST2 * 2;
                ldsm4(ah[mt][0], ah[mt][1], ah[mt][2], ah[mt][3], aAh + moff + koff);
                ldsm4(al[mt][0], al[mt][1], al[mt][2], al[mt][3], aAl + moff + koff);
            }
            #pragma unroll
            for (int p = 0; p < 4; p++) {
                const uint32_t noff = (p << 4) * SST2 * 2;
                uint32_t bh0, bh1, bh2, bh3, bl0, bl1, bl2, bl3;
                ldsm4(bh0, bh1, bh2, bh3, aBh + noff + koff);
                ldsm4(bl0, bl1, bl2, bl3, aBl + noff + koff);
                #pragma unroll
                for (int mt = 0; mt < 2; mt++) {
                    mma16816(acc[mt][2 * p + 0], ah[mt], bh0, bh1);
                    mma16816(acc[mt][2 * p + 1], ah[mt], bh2, bh3);
                }
                #pragma unroll
                for (int mt = 0; mt < 2; mt++) {
                    mma16816(acc[mt][2 * p + 0], ah[mt], bl0, bl1);
                    mma16816(acc[mt][2 * p + 1], ah[mt], bl2, bl3);
                }
                #pragma unroll
                for (int mt = 0; mt < 2; mt++) {
                    mma16816(acc[mt][2 * p + 0], al[mt], bh0, bh1);
                    mma16816(acc[mt][2 * p + 1], al[mt], bh2, bh3);
                }
            }
        }
        __syncthreads();
    }
    #undef ISSUE_STAGE

    // Epilogue
    const int g = lane >> 2, tq = lane & 3;
    if (MODE == 0) {
        #pragma unroll
        for (int mt = 0; mt < 2; mt++)
            #pragma unroll
            for (int nt = 0; nt < 8; nt++) {
                const int c = bn + wn + nt * 8 + 2 * tq;
                #pragma unroll
                for (int half = 0; half < 2; half++) {
                    const int r = bm + wm + mt * 16 + g + half * 8;
                    float2 v;
                    v.x = acc[mt][nt][2 * half + 0];
                    v.y = acc[mt][nt][2 * half + 1];
                    *(float2*)(Cout + (size_t)r * DD + c) = v;
                }
            }
    } else {
        const int which = (MODE == 1) ? 0 : ((bn + wn) >> 10);  // 0=LN, 1=V
        const int h = ((bn + wn) & 1023) >> 6;
        const float* biasb = (MODE == 1) ? g_bqkv : (g_bqkv + DD);
        if (which == 0) {
            const float* wvec = (MODE == 1) ? qn_w : kn_w;
            const float* bvec = (MODE == 1) ? qn_b : kn_b;
            __nv_bfloat16* oh = (MODE == 1) ? g_qh : g_kh;
            __nv_bfloat16* ol = (MODE == 1) ? g_ql : g_kl;
            const float sc = (MODE == 1) ? 0.125f : 1.0f;
            #pragma unroll
            for (int mt = 0; mt < 2; mt++)
                #pragma unroll
                for (int half = 0; half < 2; half++) {
                    const int r = bm + wm + mt * 16 + g + half * 8;
                    float v[16];
                    float sum = 0.0f, ssq = 0.0f;
                    #pragma unroll
                    for (int nt = 0; nt < 8; nt++) {
                        const int c = bn + wn + nt * 8 + 2 * tq;
                        const float2 bb = *(const float2*)(biasb + c);
                        const float a0 = acc[mt][nt][2 * half + 0] + bb.x;
                        const float a1 = acc[mt][nt][2 * half + 1] + bb.y;
                        v[2 * nt + 0] = a0;
                        v[2 * nt + 1] = a1;
                        sum += a0 + a1;
                        ssq = fmaf(a0, a0, fmaf(a1, a1, ssq));
                    }
                    sum += __shfl_xor_sync(0xffffffffu, sum, 1);
                    sum += __shfl_xor_sync(0xffffffffu, sum, 2);
                    ssq += __shfl_xor_sync(0xffffffffu, ssq, 1);
                    ssq += __shfl_xor_sync(0xffffffffu, ssq, 2);
                    const float mean = sum * (1.0f / DH);
                    const float var = ssq * (1.0f / DH) - mean * mean;
                    const float rstd = rsqrtf(var + LN_EPS);
                    const size_t rowoff =
                        ((((size_t)((r >> 11) * HH + h)) * NN + (r & 2047)) << 6);
                    #pragma unroll
                    for (int nt = 0; nt < 8; nt++) {
                        const int dh = nt * 8 + 2 * tq;
                        const float2 wv = *(const float2*)(wvec + dh);
                        const float2 b2 = *(const float2*)(bvec + dh);
                        const float a = ((v[2 * nt + 0] - mean) * rstd * wv.x + b2.x) * sc;
                        const float c2 = ((v[2 * nt + 1] - mean) * rstd * wv.y + b2.y) * sc;
                        hl2_store(a, c2, oh + rowoff + dh, ol + rowoff + dh);
                    }
                }
        } else {
            // v: bias + hi/lo store at compacted rows
            #pragma unroll
            for (int mt = 0; mt < 2; mt++)
                #pragma unroll
                for (int nt = 0; nt < 8; nt++) {
                    const int c = bn + wn + nt * 8 + 2 * tq;
                    const float2 bb = *(const float2*)(biasb + c);
                    #pragma unroll
                    for (int half = 0; half < 2; half++) {
                        const int r = bm + wm + mt * 16 + g + half * 8;
                        const float a0 = acc[mt][nt][2 * half + 0] + bb.x;
                        const float a1 = acc[mt][nt][2 * half + 1] + bb.y;
                        const size_t idx =
                            ((((size_t)((r >> 11) * HH + h)) * NN + (r & 2047)) << 6)
                            + (c & 63);
                        hl2_store(a0, a1, g_vh + idx, g_vl + idx);
                    }
                }
        }
    }
}

// ---------------------------------------------------------------------------
// Kernel 4: tensor-core flash attention over COMPACTED keys (contiguous K/V)
// (bf16x3 QK^T and PV), cp.async double-buffered tiles.
// grid (16, 16, 4): 128 queries x one (b,h) per CTA; 8 warps x 16 q-rows.
// ---------------------------------------------------------------------------
#define ASTR 72
#define ATT_STAGE (4 * 64 * ASTR)
#define ATT_SMEM (2 * ATT_STAGE * 2 + 2 * 64 * 4)

__global__ __launch_bounds__(256)
void attn_mma_kernel()
{
    extern __shared__ __nv_bfloat16 sma[];
    const uint32_t u0 = s2u(sma);
    float* mbs = (float*)(sma + 2 * ATT_STAGE);
    const uint32_t mb_u = u0 + 2 * ATT_STAGE * 2;

    const int tid = threadIdx.x, wid = tid >> 5, lane = tid & 31;
    const int bq = blockIdx.x << 7;
    const int h = blockIdx.y, b = blockIdx.z;
    const size_t head_off = ((size_t)(b * HH + h)) * NN;

    const int aRow = (lane & 7) + ((lane & 8) ? 8 : 0);
    const int aK   = (lane & 16) ? 8 : 0;
    const int bRow = (lane & 7) + ((lane & 16) ? 8 : 0);
    const int bK   = (lane & 8) ? 8 : 0;
    const int vRow = (lane & 7) + ((lane & 8) ? 8 : 0);
    const int vCol = (lane & 16) ? 8 : 0;

    // ---- Phase 1: stage Q hi then Q lo through rows [0,128) (two passes)
    uint32_t qh[4][4], ql[4][4];
    {
        const int r = tid >> 1;
        const int c = (tid & 1) << 5;
        const uint32_t qb = u0 + ((wid * 16 + aRow) * ASTR + aK) * 2;

        const __nv_bfloat16* sh = g_qh + (head_off + bq + r) * DH + c;
        #pragma unroll
        for (int i = 0; i < 4; i++)
            *(uint4*)(sma + r * ASTR + c + i * 8) = *(const uint4*)(sh + i * 8);
        __syncthreads();
        #pragma unroll
        for (int k = 0; k < 4; k++)
            ldsm4(qh[k][0], qh[k][1], qh[k][2], qh[k][3], qb + (k * 16) * 2);
        __syncthreads();

        const __nv_bfloat16* sl = g_ql + (head_off + bq + r) * DH + c;
        #pragma unroll
        for (int i = 0; i < 4; i++)
            *(uint4*)(sma + r * ASTR + c + i * 8) = *(const uint4*)(sl + i * 8);
        __syncthreads();
        #pragma unroll
        for (int k = 0; k < 4; k++)
            ldsm4(ql[k][0], ql[k][1], ql[k][2], ql[k][3], qb + (k * 16) * 2);
        __syncthreads();
    }

    float o[8][4];
    #pragma unroll
    for (int i = 0; i < 8; i++)
        #pragma unroll
        for (int j = 0; j < 4; j++) o[i][j] = 0.0f;
    float m0 = -1e30f, m1 = -1e30f, l0 = 0.0f, l1 = 0.0f;

    const float* mrow = g_padbias + b * NN;
    const int cnt = g_cnt[b];
    const int NT = (cnt + 63) >> 6;
    const int tq2 = (lane & 3) * 2;

    const int ldr = tid >> 2;
    const int ldc = (tid & 3) << 4;
    const uint32_t sdst = u0 + (ldr * ASTR + ldc) * 2;

    #define ISSUE_ATT(kt, stg) do {                                           \
        const uint32_t d_ = sdst + (stg) * (ATT_STAGE * 2);                    \
        const size_t gi_ = (head_off + (kt) + ldr) * DH + ldc;                 \
        cpa16(d_ + 0 * 64 * ASTR * 2,      g_kh + gi_);                        \
        cpa16(d_ + 0 * 64 * ASTR * 2 + 16, g_kh + gi_ + 8);                    \
        cpa16(d_ + 1 * 64 * ASTR * 2,      g_kl + gi_);                        \
        cpa16(d_ + 1 * 64 * ASTR * 2 + 16, g_kl + gi_ + 8);                    \
        cpa16(d_ + 2 * 64 * ASTR * 2,      g_vh + gi_);                        \
        cpa16(d_ + 2 * 64 * ASTR * 2 + 16, g_vh + gi_ + 8);                    \
        cpa16(d_ + 3 * 64 * ASTR * 2,      g_vl + gi_);                        \
        cpa16(d_ + 3 * 64 * ASTR * 2 + 16, g_vl + gi_ + 8);                    \
        if (tid < 16)                                                          \
            cpa16(mb_u + (stg) * 256 + tid * 16, mrow + (kt) + tid * 4);       \
        CP_COMMIT();                                                           \
    } while (0)

    ISSUE_ATT(0, 0);

    for (int ti = 0; ti < NT; ti++) {
        if (ti + 1 < NT) {
            ISSUE_ATT((ti + 1) * 64, (ti + 1) & 1);
            CP_WAIT(1);
        } else {
            CP_WAIT(0);
        }
        __syncthreads();

        const uint32_t sb = u0 + (ti & 1) * (ATT_STAGE * 2);
        const uint32_t Kh = sb;
        const uint32_t Kl = sb + 64 * ASTR * 2;
        const uint32_t Vh = sb + 2 * 64 * ASTR * 2;
        const uint32_t Vl = sb + 3 * 64 * ASTR * 2;
        const float* mb = mbs + (ti & 1) * 64;

        // S = Q K^T  (bf16x3), pass-major
        float s[8][4];
        #pragma unroll
        for (int i = 0; i < 8; i++)
            #pragma unroll
            for (int j = 0; j < 4; j++) s[i][j] = 0.0f;

        #pragma unroll
        for (int k = 0; k < 4; k++) {
            uint32_t kh[4][4], kl[4][4];
            #pragma unroll
            for (int p = 0; p < 4; p++) {
                const uint32_t nb = ((p * 16 + bRow) * ASTR + k * 16 + bK) * 2;
                ldsm4(kh[p][0], kh[p][1], kh[p][2], kh[p][3], Kh + nb);
                ldsm4(kl[p][0], kl[p][1], kl[p][2], kl[p][3], Kl + nb);
            }
            #pragma unroll
            for (int p = 0; p < 4; p++) {
                mma16816(s[2 * p + 0], qh[k], kh[p][0], kh[p][1]);
                mma16816(s[2 * p + 1], qh[k], kh[p][2], kh[p][3]);
            }
            #pragma unroll
            for (int p = 0; p < 4; p++) {
                mma16816(s[2 * p + 0], qh[k], kl[p][0], kl[p][1]);
                mma16816(s[2 * p + 1], qh[k], kl[p][2], kl[p][3]);
            }
            #pragma unroll
            for (int p = 0; p < 4; p++) {
                mma16816(s[2 * p + 0], ql[k], kh[p][0], kh[p][1]);
                mma16816(s[2 * p + 1], ql[k], kh[p][2], kh[p][3]);
            }
        }

        // bias (tile padding) + online softmax
        float mx0 = -1e30f, mx1 = -1e30f;
        #pragma unroll
        for (int nt = 0; nt < 8; nt++) {
            const float b0 = mb[nt * 8 + tq2];
            const float b1 = mb[nt * 8 + tq2 + 1];
            s[nt][0] += b0; s[nt][1] += b1;
            s[nt][2] += b0; s[nt][3] += b1;
            mx0 = fmaxf(mx0, fmaxf(s[nt][0], s[nt][1]));
            mx1 = fmaxf(mx1, fmaxf(s[nt][2], s[nt][3]));
        }
        mx0 = fmaxf(mx0, __shfl_xor_sync(0xffffffffu, mx0, 1));
        mx0 = fmaxf(mx0, __shfl_xor_sync(0xffffffffu, mx0, 2));
        mx1 = fmaxf(mx1, __shfl_xor_sync(0xffffffffu, mx1, 1));
        mx1 = fmaxf(mx1, __shfl_xor_sync(0xffffffffu, mx1, 2));
        const float mn0 = fmaxf(m0, mx0), mn1 = fmaxf(m1, mx1);
        const float sc0 = __expf(m0 - mn0), sc1 = __expf(m1 - mn1);
        m0 = mn0; m1 = mn1;
        float ps0 = 0.0f, ps1 = 0.0f;
        #pragma unroll
        for (int nt = 0; nt < 8; nt++) {
            s[nt][0] = __expf(s[nt][0] - m0);
            s[nt][1] = __expf(s[nt][1] - m0);
            s[nt][2] = __expf(s[nt][2] - m1);
            s[nt][3] = __expf(s[nt][3] - m1);
            ps0 += s[nt][0] + s[nt][1];
            ps1 += s[nt][2] + s[nt][3];
        }
        ps0 += __shfl_xor_sync(0xffffffffu, ps0, 1);
        ps0 += __shfl_xor_sync(0xffffffffu, ps0, 2);
        ps1 += __shfl_xor_sync(0xffffffffu, ps1, 1);
        ps1 += __shfl_xor_sync(0xffffffffu, ps1, 2);
        l0 = l0 * sc0 + ps0;
        l1 = l1 * sc1 + ps1;
        #pragma unroll
        for (int nt = 0; nt < 8; nt++) {
            o[nt][0] *= sc0; o[nt][1] *= sc0;
            o[nt][2] *= sc1; o[nt][3] *= sc1;
        }

        // O += P V   (P hi/lo x V hi/lo, 3 passes; p in pairs)
        #pragma unroll
        for (int jj = 0; jj < 4; jj++) {
            uint32_t ph[4], pl[4];
            hl_pack(s[2 * jj][0],     s[2 * jj][1],     ph[0], pl[0]);
            hl_pack(s[2 * jj][2],     s[2 * jj][3],     ph[1], pl[1]);
            hl_pack(s[2 * jj + 1][0], s[2 * jj + 1][1], ph[2], pl[2]);
            hl_pack(s[2 * jj + 1][2], s[2 * jj + 1][3], ph[3], pl[3]);
            #pragma unroll
            for (int pp = 0; pp < 2; pp++) {
                uint32_t vh[2][4], vl[2][4];
                #pragma unroll
                for (int q = 0; q < 2; q++) {
                    const int p = pp * 2 + q;
                    const uint32_t off = ((jj * 16 + vRow) * ASTR + p * 16 + vCol) * 2;
                    ldsm4t(vh[q][0], vh[q][1], vh[q][2], vh[q][3], Vh + off);
                    ldsm4t(vl[q][0], vl[q][1], vl[q][2], vl[q][3], Vl + off);
                }
                #pragma unroll
                for (int q = 0; q < 2; q++) {
                    const int p = pp * 2 + q;
                    mma16816(o[2 * p + 0], ph, vh[q][0], vh[q][1]);
                    mma16816(o[2 * p + 1], ph, vh[q][2], vh[q][3]);
                }
                #pragma unroll
                for (int q = 0; q < 2; q++) {
                    const int p = pp * 2 + q;
                    mma16816(o[2 * p + 0], ph, vl[q][0], vl[q][1]);
                    mma16816(o[2 * p + 1], ph, vl[q][2], vl[q][3]);
                }
                #pragma unroll
                for (int q = 0; q < 2; q++) {
                    const int p = pp * 2 + q;
                    mma16816(o[2 * p + 0], pl, vh[q][0], vh[q][1]);
                    mma16816(o[2 * p + 1], pl, vh[q][2], vh[q][3]);
                }
            }
        }
        __syncthreads();
    }
    #undef ISSUE_ATT

    // epilogue -> g_ao hi/lo   [b, n, h*64+dh]
    const float inv0 = 1.0f / l0, inv1 = 1.0f / l1;
    const int g = lane >> 2;
    const int q0 = bq + wid * 16 + g;
    const size_t ob = ((size_t)(b * NN) + q0) * DD + h * DH;
    #pragma unroll
    for (int nt = 0; nt < 8; nt++) {
        const int dh = nt * 8 + tq2;
        hl2_store(o[nt][0] * inv0, o[nt][1] * inv0, g_ao_hi + ob + dh, g_ao_lo + ob + dh);
        hl2_store(o[nt][2] * inv1, o[nt][3] * inv1,
                  g_ao_hi + ob + 8 * DD + dh, g_ao_lo + ob + 8 * DD + dh);
    }
}

// ---------------------------------------------------------------------------
// Launch
// ---------------------------------------------------------------------------
extern "C" void kernel_launch(void* const* d_in, const int* in_sizes, int n_in,
                              void* d_out, int out_size)
{
    const float* x       = (const float*)d_in[0];
    const void*  mask    = (const void*)d_in[1];
    const float* norm_w  = (const float*)d_in[2];
    const float* norm_b  = (const float*)d_in[3];
    const float* qn_w    = (const float*)d_in[4];
    const float* qn_b    = (const float*)d_in[5];
    const float* kn_w    = (const float*)d_in[6];
    const float* kn_b    = (const float*)d_in[7];
    const float* Wq      = (const float*)d_in[8];
    const float* bq      = (const float*)d_in[9];
    const float* Wk      = (const float*)d_in[10];
    const float* bk      = (const float*)d_in[11];
    const float* Wv      = (const float*)d_in[12];
    const float* bv      = (const float*)d_in[13];
    const float* Wo      = (const float*)d_in[14];
    float* out = (float*)d_out;

    static bool attr_done = false;
    if (!attr_done) {
        cudaFuncSetAttribute(gemm_mma2<0>, cudaFuncAttributeMaxDynamicSharedMemorySize, GEMM_SMEM2);
        cudaFuncSetAttribute(gemm_mma2<1>, cudaFuncAttributeMaxDynamicSharedMemorySize, GEMM_SMEM2);
        cudaFuncSetAttribute(gemm_mma2<5>, cudaFuncAttributeMaxDynamicSharedMemorySize, GEMM_SMEM2);
        cudaFuncSetAttribute(attn_mma_kernel, cudaFuncAttributeMaxDynamicSharedMemorySize, ATT_SMEM);
        attr_done = true;
    }

    // 0. Mask compaction + bias concat; W -> hi/lo bf16
    prep_kernel<<<1, 256>>>(mask, bq, bk, bv);
    wconv_kernel<<<dim3(1024, 4), 256>>>(Wq, Wk, Wv, Wo);

    // 1. LN(x) -> hi/lo bf16
    ln_x_kernel<<<BN, 256>>>(x, norm_w, norm_b);

    // 2a. Q projection + head-LN (all rows)
    gemm_mma2<1><<<dim3(DD / 128, BN / 128), 256, GEMM_SMEM2>>>(
        nullptr, qn_w, qn_b, kn_w, kn_b);
    // 2b. KV projection over compacted rows (gathered A; early-exit past cnt)
    gemm_mma2<5><<<dim3(2 * DD / 128, BN / 128), 256, GEMM_SMEM2>>>(
        nullptr, qn_w, qn_b, kn_w, kn_b);

    // 3. Tensor-core flash attention over compacted keys -> g_ao hi/lo
    attn_mma_kernel<<<dim3(NN / 128, HH, BB), 256, ATT_SMEM>>>();

    // 4. Output projection -> d_out
    gemm_mma2<0><<<dim3(DD / 128, BN / 128), 256, GEMM_SMEM2>>>(
        out, nullptr, nullptr, nullptr, nullptr);
}

// round 15
// speedup vs baseline: 1.6926x; 1.0076x over previous
#include <cuda_runtime.h>
#include <cuda_bf16.h>
#include <cstdint>

// Problem constants
#define BB 4
#define NN 2048
#define DD 1024
#define HH 16
#define DH 64
#define BN (BB*NN)          // 8192
#define LN_EPS 1e-5f

// ---------------------------------------------------------------------------
// Device scratch (no allocation allowed)
// ---------------------------------------------------------------------------
__device__ __nv_bfloat16 g_xn_hi[BN * DD];
__device__ __nv_bfloat16 g_xn_lo[BN * DD];
__device__ __nv_bfloat16 g_ao_hi[BN * DD];
__device__ __nv_bfloat16 g_ao_lo[BN * DD];
__device__ __nv_bfloat16 g_whi[4 * DD * DD];
__device__ __nv_bfloat16 g_wlo[4 * DD * DD];
__device__ __nv_bfloat16 g_qh[BB * HH * NN * DH];
__device__ __nv_bfloat16 g_ql[BB * HH * NN * DH];
__device__ __nv_bfloat16 g_kh[BB * HH * NN * DH];   // compacted key order
__device__ __nv_bfloat16 g_kl[BB * HH * NN * DH];
__device__ __nv_bfloat16 g_vh[BB * HH * NN * DH];
__device__ __nv_bfloat16 g_vl[BB * HH * NN * DH];
__device__ float g_bqkv[3 * DD];
__device__ int   g_gidx[BB * NN];    // compacted->original index (pad 0)
__device__ int   g_cnt[BB];          // unmasked key count per batch
__device__ float g_padbias[BB * NN]; // 0 for j<cnt, -1e30 beyond

// ---------------------------------------------------------------------------
// Helpers
// ---------------------------------------------------------------------------
__device__ __forceinline__ uint32_t s2u(const void* p) {
    uint32_t a;
    asm("{ .reg .u64 t; cvta.to.shared.u64 t, %1; cvt.u32.u64 %0, t; }"
        : "=r"(a) : "l"(p));
    return a;
}

__device__ __forceinline__ void cpa16(uint32_t dst, const void* src) {
    asm volatile("cp.async.cg.shared.global [%0], [%1], 16;"
                 :: "r"(dst), "l"(src) : "memory");
}
#define CP_COMMIT() asm volatile("cp.async.commit_group;" ::: "memory")
#define CP_WAIT(N)  asm volatile("cp.async.wait_group %0;" :: "n"(N) : "memory")

__device__ __forceinline__ void ldsm4(uint32_t& r0, uint32_t& r1,
                                      uint32_t& r2, uint32_t& r3,
                                      uint32_t addr) {
    asm volatile("ldmatrix.sync.aligned.m8n8.x4.shared.b16 {%0,%1,%2,%3}, [%4];"
                 : "=r"(r0), "=r"(r1), "=r"(r2), "=r"(r3) : "r"(addr));
}

__device__ __forceinline__ void ldsm4t(uint32_t& r0, uint32_t& r1,
                                       uint32_t& r2, uint32_t& r3,
                                       uint32_t addr) {
    asm volatile("ldmatrix.sync.aligned.m8n8.x4.trans.shared.b16 {%0,%1,%2,%3}, [%4];"
                 : "=r"(r0), "=r"(r1), "=r"(r2), "=r"(r3) : "r"(addr));
}

__device__ __forceinline__ void mma16816(float* c, const uint32_t* a,
                                         uint32_t b0, uint32_t b1) {
    asm volatile(
        "mma.sync.aligned.m16n8k16.row.col.f32.bf16.bf16.f32 "
        "{%0,%1,%2,%3}, {%4,%5,%6,%7}, {%8,%9}, {%0,%1,%2,%3};"
        : "+f"(c[0]), "+f"(c[1]), "+f"(c[2]), "+f"(c[3])
        : "r"(a[0]), "r"(a[1]), "r"(a[2]), "r"(a[3]), "r"(b0), "r"(b1));
}

// hi/lo bf16 split of a float pair -> two packed bf16x2 regs
__device__ __forceinline__ void hl_pack(float a, float b, uint32_t& hi, uint32_t& lo) {
    __nv_bfloat162 h = __float22bfloat162_rn(make_float2(a, b));
    float2 f = __bfloat1622float2(h);
    __nv_bfloat162 l = __float22bfloat162_rn(make_float2(a - f.x, b - f.y));
    hi = *reinterpret_cast<uint32_t*>(&h);
    lo = *reinterpret_cast<uint32_t*>(&l);
}

__device__ __forceinline__ void hl2_store(float a, float b,
                                          __nv_bfloat16* hip, __nv_bfloat16* lop) {
    uint32_t hi, lo;
    hl_pack(a, b, hi, lo);
    *(uint32_t*)hip = hi;
    *(uint32_t*)lop = lo;
}

__device__ __forceinline__ void hl4_store(float4 v, __nv_bfloat16* hip,
                                          __nv_bfloat16* lop) {
    hl2_store(v.x, v.y, hip, lop);
    hl2_store(v.z, v.w, hip + 2, lop + 2);
}

// ---------------------------------------------------------------------------
// Kernel 0: mask preprocessing (compaction) + bias concat
// ---------------------------------------------------------------------------
__global__ __launch_bounds__(256)
void prep_kernel(const void* __restrict__ mask,
                 const float* __restrict__ bq,
                 const float* __restrict__ bk,
                 const float* __restrict__ bv)
{
    __shared__ int s_packed;
    __shared__ int s_cnt[4];
    if (threadIdx.x == 0) s_packed = 0;
    __syncthreads();

    const unsigned* mw = (const unsigned*)mask;
    int bad = 0;
    for (int i = threadIdx.x; i < 2048; i += 256)
        if (mw[i] > 1u) bad = 1;
    if (bad) atomicOr(&s_packed, 1);
    __syncthreads();
    const bool packed = (s_packed != 0);

    const int* mi = (const int*)mask;
    const unsigned char* mb = (const unsigned char*)mask;

    const int warp = threadIdx.x >> 5, lane = threadIdx.x & 31;
    if (warp < 4) {
        int cnt = 0;
        for (int base = 0; base < NN; base += 32) {
            const int i = warp * NN + base + lane;
            const int on = packed ? (int)mb[i] : mi[i];
            const unsigned bal = __ballot_sync(0xffffffffu, on != 0);
            if (on)
                g_gidx[warp * NN + cnt + __popc(bal & ((1u << lane) - 1))] = base + lane;
            cnt += __popc(bal);
        }
        if (lane == 0) s_cnt[warp] = cnt;
    }
    __syncthreads();

    for (int i = threadIdx.x; i < BB * NN; i += 256) {
        const int bb = i >> 11, j = i & 2047;
        const int cnt = s_cnt[bb];
        g_padbias[i] = (j < cnt) ? 0.0f : -1e30f;
        if (j >= cnt) g_gidx[i] = 0;
    }
    if (threadIdx.x < 4) g_cnt[threadIdx.x] = s_cnt[threadIdx.x];

    for (int i = threadIdx.x; i < DD; i += 256) {
        g_bqkv[i]          = bq[i];
        g_bqkv[DD + i]     = bk[i];
        g_bqkv[2 * DD + i] = bv[i];
    }
}

// ---------------------------------------------------------------------------
// Kernel 1: fused wconv (blocks [0,4096)) + row-LN of x (blocks [4096,12288))
// ---------------------------------------------------------------------------
__global__ __launch_bounds__(256)
void wconv_ln_kernel(const float* __restrict__ x,
                     const float* __restrict__ w,
                     const float* __restrict__ b,
                     const float* __restrict__ W0, const float* __restrict__ W1,
                     const float* __restrict__ W2, const float* __restrict__ W3)
{
    const int blk = blockIdx.x;
    if (blk < 4096) {
        const int slot = blk >> 10;
        const float* W = (slot == 0) ? W0 : (slot == 1) ? W1 : (slot == 2) ? W2 : W3;
        const size_t i = ((size_t)(blk & 1023) * 256 + threadIdx.x) * 4;
        float4 v = *(const float4*)(W + i);
        const size_t off = (size_t)slot * DD * DD + i;
        hl4_store(v, g_whi + off, g_wlo + off);
        return;
    }

    __shared__ float red_s[8];
    __shared__ float red_q[8];
    __shared__ float stats[2];
    const int row = blk - 4096;
    const int t = threadIdx.x;
    const int lane = t & 31, warp = t >> 5;

    const float* xr = x + (long)row * DD;
    float4 xv = *(const float4*)(xr + t * 4);
    float sum = xv.x + xv.y + xv.z + xv.w;
    float ssq = fmaf(xv.x, xv.x, fmaf(xv.y, xv.y, fmaf(xv.z, xv.z, xv.w * xv.w)));
    #pragma unroll
    for (int o = 16; o > 0; o >>= 1) {
        sum += __shfl_xor_sync(0xffffffffu, sum, o);
        ssq += __shfl_xor_sync(0xffffffffu, ssq, o);
    }
    if (lane == 0) { red_s[warp] = sum; red_q[warp] = ssq; }
    __syncthreads();
    if (warp == 0) {
        float a = (lane < 8) ? red_s[lane] : 0.0f;
        float c = (lane < 8) ? red_q[lane] : 0.0f;
        #pragma unroll
        for (int o = 4; o > 0; o >>= 1) {
            a += __shfl_xor_sync(0xffffffffu, a, o);
            c += __shfl_xor_sync(0xffffffffu, c, o);
        }
        if (lane == 0) { stats[0] = a * (1.0f / DD); stats[1] = c * (1.0f / DD); }
    }
    __syncthreads();
    const float mean = stats[0];
    const float var = stats[1] - mean * mean;
    const float rstd = rsqrtf(var + LN_EPS);

    float4 wv = *(const float4*)(w + t * 4);
    float4 bv = *(const float4*)(b + t * 4);
    float4 ov;
    ov.x = (xv.x - mean) * rstd * wv.x + bv.x;
    ov.y = (xv.y - mean) * rstd * wv.y + bv.y;
    ov.z = (xv.z - mean) * rstd * wv.z + bv.z;
    ov.w = (xv.w - mean) * rstd * wv.w + bv.w;
    const size_t off = (size_t)row * DD + t * 4;
    hl4_store(ov, g_xn_hi + off, g_xn_lo + off);
}

// ---------------------------------------------------------------------------
// Kernel 2: HMMA bf16x3 GEMM, cp.async double-buffered, K-slab 32.
// 128x128 CTA tile, 8 warps (4M x 2N), warp tile 32x64, 256 threads.
// MODE 0: out-proj.  A=g_ao, B=slot3, plain fp32 out. grid (8,64).
// MODE 6: fused Q+KV proj. grid (24,64): bn<1024 -> Q path (direct rows,
//         head-LN(q)); bn>=1024 -> KV path (rows gathered via g_gidx,
//         compacted outputs, early-exit past cnt[b]); head-LN(k) / bias(v).
// ---------------------------------------------------------------------------
#define KSL 32
#define SST2 40
#define BUF2 (128 * SST2)
#define STAGE_ELE (4 * BUF2)
#define GEMM_SMEM2 (2 * STAGE_ELE * 2)

template<int MODE>
__global__ __launch_bounds__(256, 2)
void gemm_mma2(float* __restrict__ Cout,
               const float* __restrict__ qn_w, const float* __restrict__ qn_b,
               const float* __restrict__ kn_w, const float* __restrict__ kn_b)
{
    const int bm = blockIdx.y << 7;
    const int bn = blockIdx.x << 7;
    const bool isKV = (MODE == 6) && (bn >= 1024);
    if (MODE == 6 && isKV) {
        if ((bm & 2047) >= g_cnt[bm >> 11]) return;   // whole tile is padding
    }

    extern __shared__ __nv_bfloat16 smg[];
    const uint32_t u0 = s2u(smg);

    const int tid = threadIdx.x;
    const int wid = tid >> 5, lane = tid & 31;
    const int wm = (wid & 3) << 5;
    const int wn = (wid >> 2) << 6;

    const __nv_bfloat16* gAh = (MODE == 0) ? g_ao_hi : g_xn_hi;
    const __nv_bfloat16* gAl = (MODE == 0) ? g_ao_lo : g_xn_lo;
    const __nv_bfloat16* gBh = (MODE == 0) ? (g_whi + (size_t)3 * DD * DD) : g_whi;
    const __nv_bfloat16* gBl = (MODE == 0) ? (g_wlo + (size_t)3 * DD * DD) : g_wlo;

    float acc[2][8][4];
    #pragma unroll
    for (int i = 0; i < 2; i++)
        #pragma unroll
        for (int j = 0; j < 8; j++)
            #pragma unroll
            for (int k = 0; k < 4; k++) acc[i][j][k] = 0.0f;

    const int lrow = tid >> 1;
    const int lhalf = (tid & 1) << 4;
    int arow;
    if (MODE == 6 && isKV) arow = (bm & ~2047) + g_gidx[bm + lrow];
    else                   arow = bm + lrow;
    const __nv_bfloat16* pAh = gAh + (size_t)arow * DD + lhalf;
    const __nv_bfloat16* pAl = gAl + (size_t)arow * DD + lhalf;
    const __nv_bfloat16* pBh = gBh + (size_t)(bn + lrow) * DD + lhalf;
    const __nv_bfloat16* pBl = gBl + (size_t)(bn + lrow) * DD + lhalf;
    const uint32_t dbase = u0 + (lrow * SST2 + lhalf) * 2;

    const int aRow = (lane & 7) + ((lane & 8) ? 8 : 0);
    const int aK   = (lane & 16) ? 8 : 0;
    const int bRow = (lane & 7) + ((lane & 16) ? 8 : 0);
    const int bK   = (lane & 8) ? 8 : 0;

    #define ISSUE_STAGE(kt, stg) do {                                        \
        const uint32_t d_ = dbase + (stg) * (STAGE_ELE * 2);                  \
        cpa16(d_ + 0 * BUF2 * 2,      pAh + (kt));                            \
        cpa16(d_ + 0 * BUF2 * 2 + 16, pAh + (kt) + 8);                        \
        cpa16(d_ + 1 * BUF2 * 2,      pAl + (kt));                            \
        cpa16(d_ + 1 * BUF2 * 2 + 16, pAl + (kt) + 8);                        \
        cpa16(d_ + 2 * BUF2 * 2,      pBh + (kt));                            \
        cpa16(d_ + 2 * BUF2 * 2 + 16, pBh + (kt) + 8);                        \
        cpa16(d_ + 3 * BUF2 * 2,      pBl + (kt));                            \
        cpa16(d_ + 3 * BUF2 * 2 + 16, pBl + (kt) + 8);                        \
        CP_COMMIT();                                                          \
    } while (0)

    ISSUE_STAGE(0, 0);

    const int NSLAB = DD / KSL;
    for (int s = 0; s < NSLAB; s++) {
        if (s + 1 < NSLAB) {
            ISSUE_STAGE((s + 1) * KSL, (s + 1) & 1);
            CP_WAIT(1);
        } else {
            CP_WAIT(0);
        }
        __syncthreads();

        const uint32_t sb = u0 + (s & 1) * (STAGE_ELE * 2);
        const uint32_t aAh = sb + ((wm + aRow) * SST2 + aK) * 2;
        const uint32_t aAl = aAh + BUF2 * 2;
        const uint32_t aBh = sb + 2 * BUF2 * 2 + ((wn + bRow) * SST2 + bK) * 2;
        const uint32_t aBl = aBh + BUF2 * 2;

        #pragma unroll
        for (int k16 = 0; k16 < 2; k16++) {
            const uint32_t koff = (k16 << 4) * 2;
            uint32_t ah[2][4], al[2][4];
            #pragma unroll
            for (int mt = 0; mt < 2; mt++) {
                const uint32_t moff = (mt << 4) * SST2 * 2;
                ldsm4(ah[mt][0], ah[mt][1], ah[mt][2], ah[mt][3], aAh + moff + koff);
                ldsm4(al[mt][0], al[mt][1], al[mt][2], al[mt][3], aAl + moff + koff);
            }
            #pragma unroll
            for (int p = 0; p < 4; p++) {
                const uint32_t noff = (p << 4) * SST2 * 2;
                uint32_t bh0, bh1, bh2, bh3, bl0, bl1, bl2, bl3;
                ldsm4(bh0, bh1, bh2, bh3, aBh + noff + koff);
                ldsm4(bl0, bl1, bl2, bl3, aBl + noff + koff);
                #pragma unroll
                for (int mt = 0; mt < 2; mt++) {
                    mma16816(acc[mt][2 * p + 0], ah[mt], bh0, bh1);
                    mma16816(acc[mt][2 * p + 1], ah[mt], bh2, bh3);
                }
                #pragma unroll
                for (int mt = 0; mt < 2; mt++) {
                    mma16816(acc[mt][2 * p + 0], ah[mt], bl0, bl1);
                    mma16816(acc[mt][2 * p + 1], ah[mt], bl2, bl3);
                }
                #pragma unroll
                for (int mt = 0; mt < 2; mt++) {
                    mma16816(acc[mt][2 * p + 0], al[mt], bh0, bh1);
                    mma16816(acc[mt][2 * p + 1], al[mt], bh2, bh3);
                }
            }
        }
        __syncthreads();
    }
    #undef ISSUE_STAGE

    // Epilogue
    const int g = lane >> 2, tq = lane & 3;
    if (MODE == 0) {
        #pragma unroll
        for (int mt = 0; mt < 2; mt++)
            #pragma unroll
            for (int nt = 0; nt < 8; nt++) {
                const int c = bn + wn + nt * 8 + 2 * tq;
                #pragma unroll
                for (int half = 0; half < 2; half++) {
                    const int r = bm + wm + mt * 16 + g + half * 8;
                    float2 v;
                    v.x = acc[mt][nt][2 * half + 0];
                    v.y = acc[mt][nt][2 * half + 1];
                    *(float2*)(Cout + (size_t)r * DD + c) = v;
                }
            }
    } else {
        const int which = (bn + wn) >> 10;            // 0=q, 1=k, 2=v
        const int h = ((bn + wn) & 1023) >> 6;
        if (which < 2) {
            const float* wvec = which ? kn_w : qn_w;
            const float* bvec = which ? kn_b : qn_b;
            __nv_bfloat16* oh = which ? g_kh : g_qh;
            __nv_bfloat16* ol = which ? g_kl : g_ql;
            const float sc = which ? 1.0f : 0.125f;
            #pragma unroll
            for (int mt = 0; mt < 2; mt++)
                #pragma unroll
                for (int half = 0; half < 2; half++) {
                    const int r = bm + wm + mt * 16 + g + half * 8;
                    float v[16];
                    float sum = 0.0f, ssq = 0.0f;
                    #pragma unroll
                    for (int nt = 0; nt < 8; nt++) {
                        const int c = bn + wn + nt * 8 + 2 * tq;
                        const float2 bb = *(const float2*)(g_bqkv + c);
                        const float a0 = acc[mt][nt][2 * half + 0] + bb.x;
                        const float a1 = acc[mt][nt][2 * half + 1] + bb.y;
                        v[2 * nt + 0] = a0;
                        v[2 * nt + 1] = a1;
                        sum += a0 + a1;
                        ssq = fmaf(a0, a0, fmaf(a1, a1, ssq));
                    }
                    sum += __shfl_xor_sync(0xffffffffu, sum, 1);
                    sum += __shfl_xor_sync(0xffffffffu, sum, 2);
                    ssq += __shfl_xor_sync(0xffffffffu, ssq, 1);
                    ssq += __shfl_xor_sync(0xffffffffu, ssq, 2);
                    const float mean = sum * (1.0f / DH);
                    const float var = ssq * (1.0f / DH) - mean * mean;
                    const float rstd = rsqrtf(var + LN_EPS);
                    const size_t rowoff =
                        ((((size_t)((r >> 11) * HH + h)) * NN + (r & 2047)) << 6);
                    #pragma unroll
                    for (int nt = 0; nt < 8; nt++) {
                        const int dh = nt * 8 + 2 * tq;
                        const float2 wv = *(const float2*)(wvec + dh);
                        const float2 b2 = *(const float2*)(bvec + dh);
                        const float a = ((v[2 * nt + 0] - mean) * rstd * wv.x + b2.x) * sc;
                        const float c2 = ((v[2 * nt + 1] - mean) * rstd * wv.y + b2.y) * sc;
                        hl2_store(a, c2, oh + rowoff + dh, ol + rowoff + dh);
                    }
                }
        } else {
            #pragma unroll
            for (int mt = 0; mt < 2; mt++)
                #pragma unroll
                for (int nt = 0; nt < 8; nt++) {
                    const int c = bn + wn + nt * 8 + 2 * tq;
                    const float2 bb = *(const float2*)(g_bqkv + c);
                    #pragma unroll
                    for (int half = 0; half < 2; half++) {
                        const int r = bm + wm + mt * 16 + g + half * 8;
                        const float a0 = acc[mt][nt][2 * half + 0] + bb.x;
                        const float a1 = acc[mt][nt][2 * half + 1] + bb.y;
                        const size_t idx =
                            ((((size_t)((r >> 11) * HH + h)) * NN + (r & 2047)) << 6)
                            + ((c & 1023) & 63);
                        hl2_store(a0, a1, g_vh + idx, g_vl + idx);
                    }
                }
        }
    }
}

// ---------------------------------------------------------------------------
// Kernel 4: tensor-core flash attention over COMPACTED keys (contiguous K/V)
// (bf16x3 QK^T and PV), cp.async double-buffered tiles.
// grid (16, 16, 4): 128 queries x one (b,h) per CTA; 8 warps x 16 q-rows.
// ---------------------------------------------------------------------------
#define ASTR 72
#define ATT_STAGE (4 * 64 * ASTR)
#define ATT_SMEM (2 * ATT_STAGE * 2 + 2 * 64 * 4)

__global__ __launch_bounds__(256)
void attn_mma_kernel()
{
    extern __shared__ __nv_bfloat16 sma[];
    const uint32_t u0 = s2u(sma);
    float* mbs = (float*)(sma + 2 * ATT_STAGE);
    const uint32_t mb_u = u0 + 2 * ATT_STAGE * 2;

    const int tid = threadIdx.x, wid = tid >> 5, lane = tid & 31;
    const int bq = blockIdx.x << 7;
    const int h = blockIdx.y, b = blockIdx.z;
    const size_t head_off = ((size_t)(b * HH + h)) * NN;

    const int aRow = (lane & 7) + ((lane & 8) ? 8 : 0);
    const int aK   = (lane & 16) ? 8 : 0;
    const int bRow = (lane & 7) + ((lane & 16) ? 8 : 0);
    const int bK   = (lane & 8) ? 8 : 0;
    const int vRow = (lane & 7) + ((lane & 8) ? 8 : 0);
    const int vCol = (lane & 16) ? 8 : 0;

    // ---- Phase 1: stage Q hi then Q lo through rows [0,128) (two passes)
    uint32_t qh[4][4], ql[4][4];
    {
        const int r = tid >> 1;
        const int c = (tid & 1) << 5;
        const uint32_t qb = u0 + ((wid * 16 + aRow) * ASTR + aK) * 2;

        const __nv_bfloat16* sh = g_qh + (head_off + bq + r) * DH + c;
        #pragma unroll
        for (int i = 0; i < 4; i++)
            *(uint4*)(sma + r * ASTR + c + i * 8) = *(const uint4*)(sh + i * 8);
        __syncthreads();
        #pragma unroll
        for (int k = 0; k < 4; k++)
            ldsm4(qh[k][0], qh[k][1], qh[k][2], qh[k][3], qb + (k * 16) * 2);
        __syncthreads();

        const __nv_bfloat16* sl = g_ql + (head_off + bq + r) * DH + c;
        #pragma unroll
        for (int i = 0; i < 4; i++)
            *(uint4*)(sma + r * ASTR + c + i * 8) = *(const uint4*)(sl + i * 8);
        __syncthreads();
        #pragma unroll
        for (int k = 0; k < 4; k++)
            ldsm4(ql[k][0], ql[k][1], ql[k][2], ql[k][3], qb + (k * 16) * 2);
        __syncthreads();
    }

    float o[8][4];
    #pragma unroll
    for (int i = 0; i < 8; i++)
        #pragma unroll
        for (int j = 0; j < 4; j++) o[i][j] = 0.0f;
    float m0 = -1e30f, m1 = -1e30f, l0 = 0.0f, l1 = 0.0f;

    const float* mrow = g_padbias + b * NN;
    const int cnt = g_cnt[b];
    const int NT = (cnt + 63) >> 6;
    const int tq2 = (lane & 3) * 2;

    const int ldr = tid >> 2;
    const int ldc = (tid & 3) << 4;
    const uint32_t sdst = u0 + (ldr * ASTR + ldc) * 2;

    #define ISSUE_ATT(kt, stg) do {                                           \
        const uint32_t d_ = sdst + (stg) * (ATT_STAGE * 2);                    \
        const size_t gi_ = (head_off + (kt) + ldr) * DH + ldc;                 \
        cpa16(d_ + 0 * 64 * ASTR * 2,      g_kh + gi_);                        \
        cpa16(d_ + 0 * 64 * ASTR * 2 + 16, g_kh + gi_ + 8);                    \
        cpa16(d_ + 1 * 64 * ASTR * 2,      g_kl + gi_);                        \
        cpa16(d_ + 1 * 64 * ASTR * 2 + 16, g_kl + gi_ + 8);                    \
        cpa16(d_ + 2 * 64 * ASTR * 2,      g_vh + gi_);                        \
        cpa16(d_ + 2 * 64 * ASTR * 2 + 16, g_vh + gi_ + 8);                    \
        cpa16(d_ + 3 * 64 * ASTR * 2,      g_vl + gi_);                        \
        cpa16(d_ + 3 * 64 * ASTR * 2 + 16, g_vl + gi_ + 8);                    \
        if (tid < 16)                                                          \
            cpa16(mb_u + (stg) * 256 + tid * 16, mrow + (kt) + tid * 4);       \
        CP_COMMIT();                                                           \
    } while (0)

    ISSUE_ATT(0, 0);

    for (int ti = 0; ti < NT; ti++) {
        if (ti + 1 < NT) {
            ISSUE_ATT((ti + 1) * 64, (ti + 1) & 1);
            CP_WAIT(1);
        } else {
            CP_WAIT(0);
        }
        __syncthreads();

        const uint32_t sb = u0 + (ti & 1) * (ATT_STAGE * 2);
        const uint32_t Kh = sb;
        const uint32_t Kl = sb + 64 * ASTR * 2;
        const uint32_t Vh = sb + 2 * 64 * ASTR * 2;
        const uint32_t Vl = sb + 3 * 64 * ASTR * 2;
        const float* mb = mbs + (ti & 1) * 64;

        // S = Q K^T  (bf16x3), pass-major
        float s[8][4];
        #pragma unroll
        for (int i = 0; i < 8; i++)
            #pragma unroll
            for (int j = 0; j < 4; j++) s[i][j] = 0.0f;

        #pragma unroll
        for (int k = 0; k < 4; k++) {
            uint32_t kh[4][4], kl[4][4];
            #pragma unroll
            for (int p = 0; p < 4; p++) {
                const uint32_t nb = ((p * 16 + bRow) * ASTR + k * 16 + bK) * 2;
                ldsm4(kh[p][0], kh[p][1], kh[p][2], kh[p][3], Kh + nb);
                ldsm4(kl[p][0], kl[p][1], kl[p][2], kl[p][3], Kl + nb);
            }
            #pragma unroll
            for (int p = 0; p < 4; p++) {
                mma16816(s[2 * p + 0], qh[k], kh[p][0], kh[p][1]);
                mma16816(s[2 * p + 1], qh[k], kh[p][2], kh[p][3]);
            }
            #pragma unroll
            for (int p = 0; p < 4; p++) {
                mma16816(s[2 * p + 0], qh[k], kl[p][0], kl[p][1]);
                mma16816(s[2 * p + 1], qh[k], kl[p][2], kl[p][3]);
            }
            #pragma unroll
            for (int p = 0; p < 4; p++) {
                mma16816(s[2 * p + 0], ql[k], kh[p][0], kh[p][1]);
                mma16816(s[2 * p + 1], ql[k], kh[p][2], kh[p][3]);
            }
        }

        // bias (tile padding) + online softmax
        float mx0 = -1e30f, mx1 = -1e30f;
        #pragma unroll
        for (int nt = 0; nt < 8; nt++) {
            const float b0 = mb[nt * 8 + tq2];
            const float b1 = mb[nt * 8 + tq2 + 1];
            s[nt][0] += b0; s[nt][1] += b1;
            s[nt][2] += b0; s[nt][3] += b1;
            mx0 = fmaxf(mx0, fmaxf(s[nt][0], s[nt][1]));
            mx1 = fmaxf(mx1, fmaxf(s[nt][2], s[nt][3]));
        }
        mx0 = fmaxf(mx0, __shfl_xor_sync(0xffffffffu, mx0, 1));
        mx0 = fmaxf(mx0, __shfl_xor_sync(0xffffffffu, mx0, 2));
        mx1 = fmaxf(mx1, __shfl_xor_sync(0xffffffffu, mx1, 1));
        mx1 = fmaxf(mx1, __shfl_xor_sync(0xffffffffu, mx1, 2));
        const float mn0 = fmaxf(m0, mx0), mn1 = fmaxf(m1, mx1);
        const float sc0 = __expf(m0 - mn0), sc1 = __expf(m1 - mn1);
        m0 = mn0; m1 = mn1;
        float ps0 = 0.0f, ps1 = 0.0f;
        #pragma unroll
        for (int nt = 0; nt < 8; nt++) {
            s[nt][0] = __expf(s[nt][0] - m0);
            s[nt][1] = __expf(s[nt][1] - m0);
            s[nt][2] = __expf(s[nt][2] - m1);
            s[nt][3] = __expf(s[nt][3] - m1);
            ps0 += s[nt][0] + s[nt][1];
            ps1 += s[nt][2] + s[nt][3];
        }
        ps0 += __shfl_xor_sync(0xffffffffu, ps0, 1);
        ps0 += __shfl_xor_sync(0xffffffffu, ps0, 2);
        ps1 += __shfl_xor_sync(0xffffffffu, ps1, 1);
        ps1 += __shfl_xor_sync(0xffffffffu, ps1, 2);
        l0 = l0 * sc0 + ps0;
        l1 = l1 * sc1 + ps1;
        #pragma unroll
        for (int nt = 0; nt < 8; nt++) {
            o[nt][0] *= sc0; o[nt][1] *= sc0;
            o[nt][2] *= sc1; o[nt][3] *= sc1;
        }

        // O += P V   (P hi/lo x V hi/lo, 3 passes; p in pairs)
        #pragma unroll
        for (int jj = 0; jj < 4; jj++) {
            uint32_t ph[4], pl[4];
            hl_pack(s[2 * jj][0],     s[2 * jj][1],     ph[0], pl[0]);
            hl_pack(s[2 * jj][2],     s[2 * jj][3],     ph[1], pl[1]);
            hl_pack(s[2 * jj + 1][0], s[2 * jj + 1][1], ph[2], pl[2]);
            hl_pack(s[2 * jj + 1][2], s[2 * jj + 1][3], ph[3], pl[3]);
            #pragma unroll
            for (int pp = 0; pp < 2; pp++) {
                uint32_t vh[2][4], vl[2][4];
                #pragma unroll
                for (int q = 0; q < 2; q++) {
                    const int p = pp * 2 + q;
                    const uint32_t off = ((jj * 16 + vRow) * ASTR + p * 16 + vCol) * 2;
                    ldsm4t(vh[q][0], vh[q][1], vh[q][2], vh[q][3], Vh + off);
                    ldsm4t(vl[q][0], vl[q][1], vl[q][2], vl[q][3], Vl + off);
                }
                #pragma unroll
                for (int q = 0; q < 2; q++) {
                    const int p = pp * 2 + q;
                    mma16816(o[2 * p + 0], ph, vh[q][0], vh[q][1]);
                    mma16816(o[2 * p + 1], ph, vh[q][2], vh[q][3]);
                }
                #pragma unroll
                for (int q = 0; q < 2; q++) {
                    const int p = pp * 2 + q;
                    mma16816(o[2 * p + 0], ph, vl[q][0], vl[q][1]);
                    mma16816(o[2 * p + 1], ph, vl[q][2], vl[q][3]);
                }
                #pragma unroll
                for (int q = 0; q < 2; q++) {
                    const int p = pp * 2 + q;
                    mma16816(o[2 * p + 0], pl, vh[q][0], vh[q][1]);
                    mma16816(o[2 * p + 1], pl, vh[q][2], vh[q][3]);
                }
            }
        }
        __syncthreads();
    }
    #undef ISSUE_ATT

    // epilogue -> g_ao hi/lo   [b, n, h*64+dh]
    const float inv0 = 1.0f / l0, inv1 = 1.0f / l1;
    const int g = lane >> 2;
    const int q0 = bq + wid * 16 + g;
    const size_t ob = ((size_t)(b * NN) + q0) * DD + h * DH;
    #pragma unroll
    for (int nt = 0; nt < 8; nt++) {
        const int dh = nt * 8 + tq2;
        hl2_store(o[nt][0] * inv0, o[nt][1] * inv0, g_ao_hi + ob + dh, g_ao_lo + ob + dh);
        hl2_store(o[nt][2] * inv1, o[nt][3] * inv1,
                  g_ao_hi + ob + 8 * DD + dh, g_ao_lo + ob + 8 * DD + dh);
    }
}

// ---------------------------------------------------------------------------
// Launch
// ---------------------------------------------------------------------------
extern "C" void kernel_launch(void* const* d_in, const int* in_sizes, int n_in,
                              void* d_out, int out_size)
{
    const float* x       = (const float*)d_in[0];
    const void*  mask    = (const void*)d_in[1];
    const float* norm_w  = (const float*)d_in[2];
    const float* norm_b  = (const float*)d_in[3];
    const float* qn_w    = (const float*)d_in[4];
    const float* qn_b    = (const float*)d_in[5];
    const float* kn_w    = (const float*)d_in[6];
    const float* kn_b    = (const float*)d_in[7];
    const float* Wq      = (const float*)d_in[8];
    const float* bq      = (const float*)d_in[9];
    const float* Wk      = (const float*)d_in[10];
    const float* bk      = (const float*)d_in[11];
    const float* Wv      = (const float*)d_in[12];
    const float* bv      = (const float*)d_in[13];
    const float* Wo      = (const float*)d_in[14];
    float* out = (float*)d_out;

    static bool attr_done = false;
    if (!attr_done) {
        cudaFuncSetAttribute(gemm_mma2<0>, cudaFuncAttributeMaxDynamicSharedMemorySize, GEMM_SMEM2);
        cudaFuncSetAttribute(gemm_mma2<6>, cudaFuncAttributeMaxDynamicSharedMemorySize, GEMM_SMEM2);
        cudaFuncSetAttribute(attn_mma_kernel, cudaFuncAttributeMaxDynamicSharedMemorySize, ATT_SMEM);
        attr_done = true;
    }

    // 0. Mask compaction + bias concat
    prep_kernel<<<1, 256>>>(mask, bq, bk, bv);

    // 1. Fused W-conversion + LN(x)
    wconv_ln_kernel<<<4096 + BN, 256>>>(x, norm_w, norm_b, Wq, Wk, Wv, Wo);

    // 2. Fused Q+KV projection (Q: all rows; KV: compacted rows, early-exit)
    gemm_mma2<6><<<dim3(3 * DD / 128, BN / 128), 256, GEMM_SMEM2>>>(
        nullptr, qn_w, qn_b, kn_w, kn_b);

    // 3. Tensor-core flash attention over compacted keys -> g_ao hi/lo
    attn_mma_kernel<<<dim3(NN / 128, HH, BB), 256, ATT_SMEM>>>();

    // 4. Output projection -> d_out
    gemm_mma2<0><<<dim3(DD / 128, BN / 128), 256, GEMM_SMEM2>>>(
        out, nullptr, nullptr, nullptr, nullptr);
}

// round 16
// speedup vs baseline: 1.7065x; 1.0082x over previous
#include <cuda_runtime.h>
#include <cuda_bf16.h>
#include <cstdint>

// Problem constants
#define BB 4
#define NN 2048
#define DD 1024
#define HH 16
#define DH 64
#define BN (BB*NN)          // 8192
#define LN_EPS 1e-5f

// ---------------------------------------------------------------------------
// Device scratch (no allocation allowed)
// ---------------------------------------------------------------------------
__device__ __nv_bfloat16 g_xn_hi[BN * DD];
__device__ __nv_bfloat16 g_xn_lo[BN * DD];
__device__ __nv_bfloat16 g_ao_hi[BN * DD];
__device__ __nv_bfloat16 g_ao_lo[BN * DD];
__device__ __nv_bfloat16 g_whi[4 * DD * DD];
__device__ __nv_bfloat16 g_wlo[4 * DD * DD];
__device__ __nv_bfloat16 g_qh[BB * HH * NN * DH];
__device__ __nv_bfloat16 g_ql[BB * HH * NN * DH];
__device__ __nv_bfloat16 g_kh[BB * HH * NN * DH];   // compacted key order
__device__ __nv_bfloat16 g_kl[BB * HH * NN * DH];
__device__ __nv_bfloat16 g_vh[BB * HH * NN * DH];
__device__ __nv_bfloat16 g_vl[BB * HH * NN * DH];
__device__ float g_bqkv[3 * DD];
__device__ int   g_gidx[BB * NN];    // compacted->original index (pad 0)
__device__ int   g_cnt[BB];          // unmasked key count per batch
__device__ float g_padbias[BB * NN]; // 0 for j<cnt, -1e30 beyond

// ---------------------------------------------------------------------------
// Helpers
// ---------------------------------------------------------------------------
__device__ __forceinline__ uint32_t s2u(const void* p) {
    uint32_t a;
    asm("{ .reg .u64 t; cvta.to.shared.u64 t, %1; cvt.u32.u64 %0, t; }"
        : "=r"(a) : "l"(p));
    return a;
}

__device__ __forceinline__ void cpa16(uint32_t dst, const void* src) {
    asm volatile("cp.async.cg.shared.global [%0], [%1], 16;"
                 :: "r"(dst), "l"(src) : "memory");
}
#define CP_COMMIT() asm volatile("cp.async.commit_group;" ::: "memory")
#define CP_WAIT(N)  asm volatile("cp.async.wait_group %0;" :: "n"(N) : "memory")

__device__ __forceinline__ void ldsm4(uint32_t& r0, uint32_t& r1,
                                      uint32_t& r2, uint32_t& r3,
                                      uint32_t addr) {
    asm volatile("ldmatrix.sync.aligned.m8n8.x4.shared.b16 {%0,%1,%2,%3}, [%4];"
                 : "=r"(r0), "=r"(r1), "=r"(r2), "=r"(r3) : "r"(addr));
}

__device__ __forceinline__ void ldsm4t(uint32_t& r0, uint32_t& r1,
                                       uint32_t& r2, uint32_t& r3,
                                       uint32_t addr) {
    asm volatile("ldmatrix.sync.aligned.m8n8.x4.trans.shared.b16 {%0,%1,%2,%3}, [%4];"
                 : "=r"(r0), "=r"(r1), "=r"(r2), "=r"(r3) : "r"(addr));
}

__device__ __forceinline__ void mma16816(float* c, const uint32_t* a,
                                         uint32_t b0, uint32_t b1) {
    asm volatile(
        "mma.sync.aligned.m16n8k16.row.col.f32.bf16.bf16.f32 "
        "{%0,%1,%2,%3}, {%4,%5,%6,%7}, {%8,%9}, {%0,%1,%2,%3};"
        : "+f"(c[0]), "+f"(c[1]), "+f"(c[2]), "+f"(c[3])
        : "r"(a[0]), "r"(a[1]), "r"(a[2]), "r"(a[3]), "r"(b0), "r"(b1));
}

// hi/lo bf16 split of a float pair -> two packed bf16x2 regs
__device__ __forceinline__ void hl_pack(float a, float b, uint32_t& hi, uint32_t& lo) {
    __nv_bfloat162 h = __float22bfloat162_rn(make_float2(a, b));
    float2 f = __bfloat1622float2(h);
    __nv_bfloat162 l = __float22bfloat162_rn(make_float2(a - f.x, b - f.y));
    hi = *reinterpret_cast<uint32_t*>(&h);
    lo = *reinterpret_cast<uint32_t*>(&l);
}

__device__ __forceinline__ void hl2_store(float a, float b,
                                          __nv_bfloat16* hip, __nv_bfloat16* lop) {
    uint32_t hi, lo;
    hl_pack(a, b, hi, lo);
    *(uint32_t*)hip = hi;
    *(uint32_t*)lop = lo;
}

__device__ __forceinline__ void hl4_store(float4 v, __nv_bfloat16* hip,
                                          __nv_bfloat16* lop) {
    hl2_store(v.x, v.y, hip, lop);
    hl2_store(v.z, v.w, hip + 2, lop + 2);
}

// ---------------------------------------------------------------------------
// Kernel 0: mask preprocessing (compaction) + bias concat
// ---------------------------------------------------------------------------
__global__ __launch_bounds__(256)
void prep_kernel(const void* __restrict__ mask,
                 const float* __restrict__ bq,
                 const float* __restrict__ bk,
                 const float* __restrict__ bv)
{
    __shared__ int s_packed;
    __shared__ int s_cnt[4];
    if (threadIdx.x == 0) s_packed = 0;
    __syncthreads();

    const unsigned* mw = (const unsigned*)mask;
    int bad = 0;
    for (int i = threadIdx.x; i < 2048; i += 256)
        if (mw[i] > 1u) bad = 1;
    if (bad) atomicOr(&s_packed, 1);
    __syncthreads();
    const bool packed = (s_packed != 0);

    const int* mi = (const int*)mask;
    const unsigned char* mb = (const unsigned char*)mask;

    const int warp = threadIdx.x >> 5, lane = threadIdx.x & 31;
    if (warp < 4) {
        int cnt = 0;
        for (int base = 0; base < NN; base += 32) {
            const int i = warp * NN + base + lane;
            const int on = packed ? (int)mb[i] : mi[i];
            const unsigned bal = __ballot_sync(0xffffffffu, on != 0);
            if (on)
                g_gidx[warp * NN + cnt + __popc(bal & ((1u << lane) - 1))] = base + lane;
            cnt += __popc(bal);
        }
        if (lane == 0) s_cnt[warp] = cnt;
    }
    __syncthreads();

    for (int i = threadIdx.x; i < BB * NN; i += 256) {
        const int bb = i >> 11, j = i & 2047;
        const int cnt = s_cnt[bb];
        g_padbias[i] = (j < cnt) ? 0.0f : -1e30f;
        if (j >= cnt) g_gidx[i] = 0;
    }
    if (threadIdx.x < 4) g_cnt[threadIdx.x] = s_cnt[threadIdx.x];

    for (int i = threadIdx.x; i < DD; i += 256) {
        g_bqkv[i]          = bq[i];
        g_bqkv[DD + i]     = bk[i];
        g_bqkv[2 * DD + i] = bv[i];
    }
}

// ---------------------------------------------------------------------------
// Kernel 1: fused wconv (blocks [0,4096)) + row-LN of x (blocks [4096,12288))
// ---------------------------------------------------------------------------
__global__ __launch_bounds__(256)
void wconv_ln_kernel(const float* __restrict__ x,
                     const float* __restrict__ w,
                     const float* __restrict__ b,
                     const float* __restrict__ W0, const float* __restrict__ W1,
                     const float* __restrict__ W2, const float* __restrict__ W3)
{
    const int blk = blockIdx.x;
    if (blk < 4096) {
        const int slot = blk >> 10;
        const float* W = (slot == 0) ? W0 : (slot == 1) ? W1 : (slot == 2) ? W2 : W3;
        const size_t i = ((size_t)(blk & 1023) * 256 + threadIdx.x) * 4;
        float4 v = *(const float4*)(W + i);
        const size_t off = (size_t)slot * DD * DD + i;
        hl4_store(v, g_whi + off, g_wlo + off);
        return;
    }

    __shared__ float red_s[8];
    __shared__ float red_q[8];
    __shared__ float stats[2];
    const int row = blk - 4096;
    const int t = threadIdx.x;
    const int lane = t & 31, warp = t >> 5;

    const float* xr = x + (long)row * DD;
    float4 xv = *(const float4*)(xr + t * 4);
    float sum = xv.x + xv.y + xv.z + xv.w;
    float ssq = fmaf(xv.x, xv.x, fmaf(xv.y, xv.y, fmaf(xv.z, xv.z, xv.w * xv.w)));
    #pragma unroll
    for (int o = 16; o > 0; o >>= 1) {
        sum += __shfl_xor_sync(0xffffffffu, sum, o);
        ssq += __shfl_xor_sync(0xffffffffu, ssq, o);
    }
    if (lane == 0) { red_s[warp] = sum; red_q[warp] = ssq; }
    __syncthreads();
    if (warp == 0) {
        float a = (lane < 8) ? red_s[lane] : 0.0f;
        float c = (lane < 8) ? red_q[lane] : 0.0f;
        #pragma unroll
        for (int o = 4; o > 0; o >>= 1) {
            a += __shfl_xor_sync(0xffffffffu, a, o);
            c += __shfl_xor_sync(0xffffffffu, c, o);
        }
        if (lane == 0) { stats[0] = a * (1.0f / DD); stats[1] = c * (1.0f / DD); }
    }
    __syncthreads();
    const float mean = stats[0];
    const float var = stats[1] - mean * mean;
    const float rstd = rsqrtf(var + LN_EPS);

    float4 wv = *(const float4*)(w + t * 4);
    float4 bv = *(const float4*)(b + t * 4);
    float4 ov;
    ov.x = (xv.x - mean) * rstd * wv.x + bv.x;
    ov.y = (xv.y - mean) * rstd * wv.y + bv.y;
    ov.z = (xv.z - mean) * rstd * wv.z + bv.z;
    ov.w = (xv.w - mean) * rstd * wv.w + bv.w;
    const size_t off = (size_t)row * DD + t * 4;
    hl4_store(ov, g_xn_hi + off, g_xn_lo + off);
}

// ---------------------------------------------------------------------------
// Kernel 2: HMMA bf16x3 GEMM, cp.async double-buffered, K-slab 32.
// 128x128 CTA tile, 8 warps (4M x 2N), warp tile 32x64, 256 threads.
// MODE 0: out-proj.  A=g_ao, B=slot3, plain fp32 out. grid (8,64).
// MODE 6: fused Q+KV proj. grid (24,64): bn<1024 -> Q path (direct rows,
//         head-LN(q)); bn>=1024 -> KV path (rows gathered via g_gidx,
//         compacted outputs, early-exit past cnt[b]); head-LN(k) / bias(v).
// ---------------------------------------------------------------------------
#define KSL 32
#define SST2 40
#define BUF2 (128 * SST2)
#define STAGE_ELE (4 * BUF2)
#define GEMM_SMEM2 (2 * STAGE_ELE * 2)

template<int MODE>
__global__ __launch_bounds__(256, 2)
void gemm_mma2(float* __restrict__ Cout,
               const float* __restrict__ qn_w, const float* __restrict__ qn_b,
               const float* __restrict__ kn_w, const float* __restrict__ kn_b)
{
    const int bm = blockIdx.y << 7;
    const int bn = blockIdx.x << 7;
    const bool isKV = (MODE == 6) && (bn >= 1024);
    if (MODE == 6 && isKV) {
        if ((bm & 2047) >= g_cnt[bm >> 11]) return;   // whole tile is padding
    }

    extern __shared__ __nv_bfloat16 smg[];
    const uint32_t u0 = s2u(smg);

    const int tid = threadIdx.x;
    const int wid = tid >> 5, lane = tid & 31;
    const int wm = (wid & 3) << 5;
    const int wn = (wid >> 2) << 6;

    const __nv_bfloat16* gAh = (MODE == 0) ? g_ao_hi : g_xn_hi;
    const __nv_bfloat16* gAl = (MODE == 0) ? g_ao_lo : g_xn_lo;
    const __nv_bfloat16* gBh = (MODE == 0) ? (g_whi + (size_t)3 * DD * DD) : g_whi;
    const __nv_bfloat16* gBl = (MODE == 0) ? (g_wlo + (size_t)3 * DD * DD) : g_wlo;

    float acc[2][8][4];
    #pragma unroll
    for (int i = 0; i < 2; i++)
        #pragma unroll
        for (int j = 0; j < 8; j++)
            #pragma unroll
            for (int k = 0; k < 4; k++) acc[i][j][k] = 0.0f;

    const int lrow = tid >> 1;
    const int lhalf = (tid & 1) << 4;
    int arow;
    if (MODE == 6 && isKV) arow = (bm & ~2047) + g_gidx[bm + lrow];
    else                   arow = bm + lrow;
    const __nv_bfloat16* pAh = gAh + (size_t)arow * DD + lhalf;
    const __nv_bfloat16* pAl = gAl + (size_t)arow * DD + lhalf;
    const __nv_bfloat16* pBh = gBh + (size_t)(bn + lrow) * DD + lhalf;
    const __nv_bfloat16* pBl = gBl + (size_t)(bn + lrow) * DD + lhalf;
    const uint32_t dbase = u0 + (lrow * SST2 + lhalf) * 2;

    const int aRow = (lane & 7) + ((lane & 8) ? 8 : 0);
    const int aK   = (lane & 16) ? 8 : 0;
    const int bRow = (lane & 7) + ((lane & 16) ? 8 : 0);
    const int bK   = (lane & 8) ? 8 : 0;

    #define ISSUE_STAGE(kt, stg) do {                                        \
        const uint32_t d_ = dbase + (stg) * (STAGE_ELE * 2);                  \
        cpa16(d_ + 0 * BUF2 * 2,      pAh + (kt));                            \
        cpa16(d_ + 0 * BUF2 * 2 + 16, pAh + (kt) + 8);                        \
        cpa16(d_ + 1 * BUF2 * 2,      pAl + (kt));                            \
        cpa16(d_ + 1 * BUF2 * 2 + 16, pAl + (kt) + 8);                        \
        cpa16(d_ + 2 * BUF2 * 2,      pBh + (kt));                            \
        cpa16(d_ + 2 * BUF2 * 2 + 16, pBh + (kt) + 8);                        \
        cpa16(d_ + 3 * BUF2 * 2,      pBl + (kt));                            \
        cpa16(d_ + 3 * BUF2 * 2 + 16, pBl + (kt) + 8);                        \
        CP_COMMIT();                                                          \
    } while (0)

    ISSUE_STAGE(0, 0);

    const int NSLAB = DD / KSL;
    for (int s = 0; s < NSLAB; s++) {
        if (s + 1 < NSLAB) {
            ISSUE_STAGE((s + 1) * KSL, (s + 1) & 1);
            CP_WAIT(1);
        } else {
            CP_WAIT(0);
        }
        __syncthreads();

        const uint32_t sb = u0 + (s & 1) * (STAGE_ELE * 2);
        const uint32_t aAh = sb + ((wm + aRow) * SST2 + aK) * 2;
        const uint32_t aAl = aAh + BUF2 * 2;
        const uint32_t aBh = sb + 2 * BUF2 * 2 + ((wn + bRow) * SST2 + bK) * 2;
        const uint32_t aBl = aBh + BUF2 * 2;

        #pragma unroll
        for (int k16 = 0; k16 < 2; k16++) {
            const uint32_t koff = (k16 << 4) * 2;
            uint32_t ah[2][4], al[2][4];
            #pragma unroll
            for (int mt = 0; mt < 2; mt++) {
                const uint32_t moff = (mt << 4) * SST2 * 2;
                ldsm4(ah[mt][0], ah[mt][1], ah[mt][2], ah[mt][3], aAh + moff + koff);
                ldsm4(al[mt][0], al[mt][1], al[mt][2], al[mt][3], aAl + moff + koff);
            }
            #pragma unroll
            for (int p = 0; p < 4; p++) {
                const uint32_t noff = (p << 4) * SST2 * 2;
                uint32_t bh0, bh1, bh2, bh3, bl0, bl1, bl2, bl3;
                ldsm4(bh0, bh1, bh2, bh3, aBh + noff + koff);
                ldsm4(bl0, bl1, bl2, bl3, aBl + noff + koff);
                #pragma unroll
                for (int mt = 0; mt < 2; mt++) {
                    mma16816(acc[mt][2 * p + 0], ah[mt], bh0, bh1);
                    mma16816(acc[mt][2 * p + 1], ah[mt], bh2, bh3);
                }
                #pragma unroll
                for (int mt = 0; mt < 2; mt++) {
                    mma16816(acc[mt][2 * p + 0], ah[mt], bl0, bl1);
                    mma16816(acc[mt][2 * p + 1], ah[mt], bl2, bl3);
                }
                #pragma unroll
                for (int mt = 0; mt < 2; mt++) {
                    mma16816(acc[mt][2 * p + 0], al[mt], bh0, bh1);
                    mma16816(acc[mt][2 * p + 1], al[mt], bh2, bh3);
                }
            }
        }
        __syncthreads();
    }
    #undef ISSUE_STAGE

    // Epilogue
    const int g = lane >> 2, tq = lane & 3;
    if (MODE == 0) {
        #pragma unroll
        for (int mt = 0; mt < 2; mt++)
            #pragma unroll
            for (int nt = 0; nt < 8; nt++) {
                const int c = bn + wn + nt * 8 + 2 * tq;
                #pragma unroll
                for (int half = 0; half < 2; half++) {
                    const int r = bm + wm + mt * 16 + g + half * 8;
                    float2 v;
                    v.x = acc[mt][nt][2 * half + 0];
                    v.y = acc[mt][nt][2 * half + 1];
                    *(float2*)(Cout + (size_t)r * DD + c) = v;
                }
            }
    } else {
        const int which = (bn + wn) >> 10;            // 0=q, 1=k, 2=v
        const int h = ((bn + wn) & 1023) >> 6;
        if (which < 2) {
            const float* wvec = which ? kn_w : qn_w;
            const float* bvec = which ? kn_b : qn_b;
            __nv_bfloat16* oh = which ? g_kh : g_qh;
            __nv_bfloat16* ol = which ? g_kl : g_ql;
            const float sc = which ? 1.0f : 0.125f;
            #pragma unroll
            for (int mt = 0; mt < 2; mt++)
                #pragma unroll
                for (int half = 0; half < 2; half++) {
                    const int r = bm + wm + mt * 16 + g + half * 8;
                    float v[16];
                    float sum = 0.0f, ssq = 0.0f;
                    #pragma unroll
                    for (int nt = 0; nt < 8; nt++) {
                        const int c = bn + wn + nt * 8 + 2 * tq;
                        const float2 bb = *(const float2*)(g_bqkv + c);
                        const float a0 = acc[mt][nt][2 * half + 0] + bb.x;
                        const float a1 = acc[mt][nt][2 * half + 1] + bb.y;
                        v[2 * nt + 0] = a0;
                        v[2 * nt + 1] = a1;
                        sum += a0 + a1;
                        ssq = fmaf(a0, a0, fmaf(a1, a1, ssq));
                    }
                    sum += __shfl_xor_sync(0xffffffffu, sum, 1);
                    sum += __shfl_xor_sync(0xffffffffu, sum, 2);
                    ssq += __shfl_xor_sync(0xffffffffu, ssq, 1);
                    ssq += __shfl_xor_sync(0xffffffffu, ssq, 2);
                    const float mean = sum * (1.0f / DH);
                    const float var = ssq * (1.0f / DH) - mean * mean;
                    const float rstd = rsqrtf(var + LN_EPS);
                    const size_t rowoff =
                        ((((size_t)((r >> 11) * HH + h)) * NN + (r & 2047)) << 6);
                    #pragma unroll
                    for (int nt = 0; nt < 8; nt++) {
                        const int dh = nt * 8 + 2 * tq;
                        const float2 wv = *(const float2*)(wvec + dh);
                        const float2 b2 = *(const float2*)(bvec + dh);
                        const float a = ((v[2 * nt + 0] - mean) * rstd * wv.x + b2.x) * sc;
                        const float c2 = ((v[2 * nt + 1] - mean) * rstd * wv.y + b2.y) * sc;
                        hl2_store(a, c2, oh + rowoff + dh, ol + rowoff + dh);
                    }
                }
        } else {
            #pragma unroll
            for (int mt = 0; mt < 2; mt++)
                #pragma unroll
                for (int nt = 0; nt < 8; nt++) {
                    const int c = bn + wn + nt * 8 + 2 * tq;
                    const float2 bb = *(const float2*)(g_bqkv + c);
                    #pragma unroll
                    for (int half = 0; half < 2; half++) {
                        const int r = bm + wm + mt * 16 + g + half * 8;
                        const float a0 = acc[mt][nt][2 * half + 0] + bb.x;
                        const float a1 = acc[mt][nt][2 * half + 1] + bb.y;
                        const size_t idx =
                            ((((size_t)((r >> 11) * HH + h)) * NN + (r & 2047)) << 6)
                            + ((c & 1023) & 63);
                        hl2_store(a0, a1, g_vh + idx, g_vl + idx);
                    }
                }
        }
    }
}

// ---------------------------------------------------------------------------
// Kernel 4: tensor-core flash attention over COMPACTED keys (contiguous K/V)
// (bf16x3 QK^T and PV), cp.async double-buffered tiles.
// 512 threads / 16 warps, q-tile 256. grid (8, 16, 4).
// ---------------------------------------------------------------------------
#define ASTR 72
#define ATT_STAGE (4 * 64 * ASTR)
#define ATT_SMEM (2 * ATT_STAGE * 2 + 2 * 64 * 4)

__global__ __launch_bounds__(512, 1)
void attn_mma_kernel()
{
    extern __shared__ __nv_bfloat16 sma[];
    const uint32_t u0 = s2u(sma);
    float* mbs = (float*)(sma + 2 * ATT_STAGE);
    const uint32_t mb_u = u0 + 2 * ATT_STAGE * 2;

    const int tid = threadIdx.x, wid = tid >> 5, lane = tid & 31;
    const int bq = blockIdx.x << 8;               // 256 queries per CTA
    const int h = blockIdx.y, b = blockIdx.z;
    const size_t head_off = ((size_t)(b * HH + h)) * NN;

    const int aRow = (lane & 7) + ((lane & 8) ? 8 : 0);
    const int aK   = (lane & 16) ? 8 : 0;
    const int bRow = (lane & 7) + ((lane & 16) ? 8 : 0);
    const int bK   = (lane & 8) ? 8 : 0;
    const int vRow = (lane & 7) + ((lane & 8) ? 8 : 0);
    const int vCol = (lane & 16) ? 8 : 0;

    // ---- Phase 1: stage Q hi then Q lo through rows [0,256) (two passes)
    uint32_t qh[4][4], ql[4][4];
    {
        const int r = tid >> 1;                   // 0..255
        const int c = (tid & 1) << 5;
        const uint32_t qb = u0 + ((wid * 16 + aRow) * ASTR + aK) * 2;

        const __nv_bfloat16* sh = g_qh + (head_off + bq + r) * DH + c;
        #pragma unroll
        for (int i = 0; i < 4; i++)
            *(uint4*)(sma + r * ASTR + c + i * 8) = *(const uint4*)(sh + i * 8);
        __syncthreads();
        #pragma unroll
        for (int k = 0; k < 4; k++)
            ldsm4(qh[k][0], qh[k][1], qh[k][2], qh[k][3], qb + (k * 16) * 2);
        __syncthreads();

        const __nv_bfloat16* sl = g_ql + (head_off + bq + r) * DH + c;
        #pragma unroll
        for (int i = 0; i < 4; i++)
            *(uint4*)(sma + r * ASTR + c + i * 8) = *(const uint4*)(sl + i * 8);
        __syncthreads();
        #pragma unroll
        for (int k = 0; k < 4; k++)
            ldsm4(ql[k][0], ql[k][1], ql[k][2], ql[k][3], qb + (k * 16) * 2);
        __syncthreads();
    }

    float o[8][4];
    #pragma unroll
    for (int i = 0; i < 8; i++)
        #pragma unroll
        for (int j = 0; j < 4; j++) o[i][j] = 0.0f;
    float m0 = -1e30f, m1 = -1e30f, l0 = 0.0f, l1 = 0.0f;

    const float* mrow = g_padbias + b * NN;
    const int cnt = g_cnt[b];
    const int NT = (cnt + 63) >> 6;
    const int tq2 = (lane & 3) * 2;

    // cp.async loader: 512 threads cover 64 rows x 64 cols, one cpa16/buffer
    const int ldr = tid >> 3;                     // 0..63
    const int ldc = (tid & 7) << 3;               // 0..56 step 8
    const uint32_t sdst = u0 + (ldr * ASTR + ldc) * 2;

    #define ISSUE_ATT(kt, stg) do {                                           \
        const uint32_t d_ = sdst + (stg) * (ATT_STAGE * 2);                    \
        const size_t gi_ = (head_off + (kt) + ldr) * DH + ldc;                 \
        cpa16(d_ + 0 * 64 * ASTR * 2, g_kh + gi_);                             \
        cpa16(d_ + 1 * 64 * ASTR * 2, g_kl + gi_);                             \
        cpa16(d_ + 2 * 64 * ASTR * 2, g_vh + gi_);                             \
        cpa16(d_ + 3 * 64 * ASTR * 2, g_vl + gi_);                             \
        if (tid < 16)                                                          \
            cpa16(mb_u + (stg) * 256 + tid * 16, mrow + (kt) + tid * 4);       \
        CP_COMMIT();                                                           \
    } while (0)

    ISSUE_ATT(0, 0);

    for (int ti = 0; ti < NT; ti++) {
        if (ti + 1 < NT) {
            ISSUE_ATT((ti + 1) * 64, (ti + 1) & 1);
            CP_WAIT(1);
        } else {
            CP_WAIT(0);
        }
        __syncthreads();

        const uint32_t sb = u0 + (ti & 1) * (ATT_STAGE * 2);
        const uint32_t Kh = sb;
        const uint32_t Kl = sb + 64 * ASTR * 2;
        const uint32_t Vh = sb + 2 * 64 * ASTR * 2;
        const uint32_t Vl = sb + 3 * 64 * ASTR * 2;
        const float* mb = mbs + (ti & 1) * 64;

        // S = Q K^T  (bf16x3), per-p interleaved K loads (reg-lean)
        float s[8][4];
        #pragma unroll
        for (int i = 0; i < 8; i++)
            #pragma unroll
            for (int j = 0; j < 4; j++) s[i][j] = 0.0f;

        #pragma unroll
        for (int k = 0; k < 4; k++) {
            #pragma unroll
            for (int p = 0; p < 4; p++) {
                const uint32_t nb = ((p * 16 + bRow) * ASTR + k * 16 + bK) * 2;
                uint32_t kh0, kh1, kh2, kh3, kl0, kl1, kl2, kl3;
                ldsm4(kh0, kh1, kh2, kh3, Kh + nb);
                ldsm4(kl0, kl1, kl2, kl3, Kl + nb);
                mma16816(s[2 * p + 0], qh[k], kh0, kh1);
                mma16816(s[2 * p + 1], qh[k], kh2, kh3);
                mma16816(s[2 * p + 0], qh[k], kl0, kl1);
                mma16816(s[2 * p + 1], qh[k], kl2, kl3);
                mma16816(s[2 * p + 0], ql[k], kh0, kh1);
                mma16816(s[2 * p + 1], ql[k], kh2, kh3);
            }
        }

        // bias (tile padding) + online softmax
        float mx0 = -1e30f, mx1 = -1e30f;
        #pragma unroll
        for (int nt = 0; nt < 8; nt++) {
            const float b0 = mb[nt * 8 + tq2];
            const float b1 = mb[nt * 8 + tq2 + 1];
            s[nt][0] += b0; s[nt][1] += b1;
            s[nt][2] += b0; s[nt][3] += b1;
            mx0 = fmaxf(mx0, fmaxf(s[nt][0], s[nt][1]));
            mx1 = fmaxf(mx1, fmaxf(s[nt][2], s[nt][3]));
        }
        mx0 = fmaxf(mx0, __shfl_xor_sync(0xffffffffu, mx0, 1));
        mx0 = fmaxf(mx0, __shfl_xor_sync(0xffffffffu, mx0, 2));
        mx1 = fmaxf(mx1, __shfl_xor_sync(0xffffffffu, mx1, 1));
        mx1 = fmaxf(mx1, __shfl_xor_sync(0xffffffffu, mx1, 2));
        const float mn0 = fmaxf(m0, mx0), mn1 = fmaxf(m1, mx1);
        const float sc0 = __expf(m0 - mn0), sc1 = __expf(m1 - mn1);
        m0 = mn0; m1 = mn1;
        float ps0 = 0.0f, ps1 = 0.0f;
        #pragma unroll
        for (int nt = 0; nt < 8; nt++) {
            s[nt][0] = __expf(s[nt][0] - m0);
            s[nt][1] = __expf(s[nt][1] - m0);
            s[nt][2] = __expf(s[nt][2] - m1);
            s[nt][3] = __expf(s[nt][3] - m1);
            ps0 += s[nt][0] + s[nt][1];
            ps1 += s[nt][2] + s[nt][3];
        }
        ps0 += __shfl_xor_sync(0xffffffffu, ps0, 1);
        ps0 += __shfl_xor_sync(0xffffffffu, ps0, 2);
        ps1 += __shfl_xor_sync(0xffffffffu, ps1, 1);
        ps1 += __shfl_xor_sync(0xffffffffu, ps1, 2);
        l0 = l0 * sc0 + ps0;
        l1 = l1 * sc1 + ps1;
        #pragma unroll
        for (int nt = 0; nt < 8; nt++) {
            o[nt][0] *= sc0; o[nt][1] *= sc0;
            o[nt][2] *= sc1; o[nt][3] *= sc1;
        }

        // O += P V   (P hi/lo x V hi/lo, 3 passes; p in pairs)
        #pragma unroll
        for (int jj = 0; jj < 4; jj++) {
            uint32_t ph[4], pl[4];
            hl_pack(s[2 * jj][0],     s[2 * jj][1],     ph[0], pl[0]);
            hl_pack(s[2 * jj][2],     s[2 * jj][3],     ph[1], pl[1]);
            hl_pack(s[2 * jj + 1][0], s[2 * jj + 1][1], ph[2], pl[2]);
            hl_pack(s[2 * jj + 1][2], s[2 * jj + 1][3], ph[3], pl[3]);
            #pragma unroll
            for (int pp = 0; pp < 2; pp++) {
                uint32_t vh[2][4], vl[2][4];
                #pragma unroll
                for (int q = 0; q < 2; q++) {
                    const int p = pp * 2 + q;
                    const uint32_t off = ((jj * 16 + vRow) * ASTR + p * 16 + vCol) * 2;
                    ldsm4t(vh[q][0], vh[q][1], vh[q][2], vh[q][3], Vh + off);
                    ldsm4t(vl[q][0], vl[q][1], vl[q][2], vl[q][3], Vl + off);
                }
                #pragma unroll
                for (int q = 0; q < 2; q++) {
                    const int p = pp * 2 + q;
                    mma16816(o[2 * p + 0], ph, vh[q][0], vh[q][1]);
                    mma16816(o[2 * p + 1], ph, vh[q][2], vh[q][3]);
                }
                #pragma unroll
                for (int q = 0; q < 2; q++) {
                    const int p = pp * 2 + q;
                    mma16816(o[2 * p + 0], ph, vl[q][0], vl[q][1]);
                    mma16816(o[2 * p + 1], ph, vl[q][2], vl[q][3]);
                }
                #pragma unroll
                for (int q = 0; q < 2; q++) {
                    const int p = pp * 2 + q;
                    mma16816(o[2 * p + 0], pl, vh[q][0], vh[q][1]);
                    mma16816(o[2 * p + 1], pl, vh[q][2], vh[q][3]);
                }
            }
        }
        __syncthreads();
    }
    #undef ISSUE_ATT

    // epilogue -> g_ao hi/lo   [b, n, h*64+dh]
    const float inv0 = 1.0f / l0, inv1 = 1.0f / l1;
    const int g = lane >> 2;
    const int q0 = bq + wid * 16 + g;
    const size_t ob = ((size_t)(b * NN) + q0) * DD + h * DH;
    #pragma unroll
    for (int nt = 0; nt < 8; nt++) {
        const int dh = nt * 8 + tq2;
        hl2_store(o[nt][0] * inv0, o[nt][1] * inv0, g_ao_hi + ob + dh, g_ao_lo + ob + dh);
        hl2_store(o[nt][2] * inv1, o[nt][3] * inv1,
                  g_ao_hi + ob + 8 * DD + dh, g_ao_lo + ob + 8 * DD + dh);
    }
}

// ---------------------------------------------------------------------------
// Launch
// ---------------------------------------------------------------------------
extern "C" void kernel_launch(void* const* d_in, const int* in_sizes, int n_in,
                              void* d_out, int out_size)
{
    const float* x       = (const float*)d_in[0];
    const void*  mask    = (const void*)d_in[1];
    const float* norm_w  = (const float*)d_in[2];
    const float* norm_b  = (const float*)d_in[3];
    const float* qn_w    = (const float*)d_in[4];
    const float* qn_b    = (const float*)d_in[5];
    const float* kn_w    = (const float*)d_in[6];
    const float* kn_b    = (const float*)d_in[7];
    const float* Wq      = (const float*)d_in[8];
    const float* bq      = (const float*)d_in[9];
    const float* Wk      = (const float*)d_in[10];
    const float* bk      = (const float*)d_in[11];
    const float* Wv      = (const float*)d_in[12];
    const float* bv      = (const float*)d_in[13];
    const float* Wo      = (const float*)d_in[14];
    float* out = (float*)d_out;

    static bool attr_done = false;
    if (!attr_done) {
        cudaFuncSetAttribute(gemm_mma2<0>, cudaFuncAttributeMaxDynamicSharedMemorySize, GEMM_SMEM2);
        cudaFuncSetAttribute(gemm_mma2<6>, cudaFuncAttributeMaxDynamicSharedMemorySize, GEMM_SMEM2);
        cudaFuncSetAttribute(attn_mma_kernel, cudaFuncAttributeMaxDynamicSharedMemorySize, ATT_SMEM);
        attr_done = true;
    }

    // 0. Mask compaction + bias concat
    prep_kernel<<<1, 256>>>(mask, bq, bk, bv);

    // 1. Fused W-conversion + LN(x)
    wconv_ln_kernel<<<4096 + BN, 256>>>(x, norm_w, norm_b, Wq, Wk, Wv, Wo);

    // 2. Fused Q+KV projection (Q: all rows; KV: compacted rows, early-exit)
    gemm_mma2<6><<<dim3(3 * DD / 128, BN / 128), 256, GEMM_SMEM2>>>(
        nullptr, qn_w, qn_b, kn_w, kn_b);

    // 3. Tensor-core flash attention over compacted keys -> g_ao hi/lo
    attn_mma_kernel<<<dim3(NN / 256, HH, BB), 512, ATT_SMEM>>>();

    // 4. Output projection -> d_out
    gemm_mma2<0><<<dim3(DD / 128, BN / 128), 256, GEMM_SMEM2>>>(
        out, nullptr, nullptr, nullptr, nullptr);
}

// round 17
// speedup vs baseline: 1.8072x; 1.0590x over previous
#include <cuda_runtime.h>
#include <cuda_bf16.h>
#include <cuda_fp16.h>
#include <cstdint>

// Problem constants
#define BB 4
#define NN 2048
#define DD 1024
#define HH 16
#define DH 64
#define BN (BB*NN)          // 8192
#define LN_EPS 1e-5f
#define LOG2E 1.44269504088896340736f

// ---------------------------------------------------------------------------
// Device scratch (no allocation allowed)
// ---------------------------------------------------------------------------
__device__ __nv_bfloat16 g_xn_hi[BN * DD];
__device__ __nv_bfloat16 g_xn_lo[BN * DD];
__device__ __nv_bfloat16 g_ao_hi[BN * DD];
__device__ __nv_bfloat16 g_ao_lo[BN * DD];
__device__ __nv_bfloat16 g_whi[4 * DD * DD];
__device__ __nv_bfloat16 g_wlo[4 * DD * DD];
__device__ __nv_bfloat16 g_qh[BB * HH * NN * DH];
__device__ __nv_bfloat16 g_ql[BB * HH * NN * DH];
__device__ __nv_bfloat16 g_kh[BB * HH * NN * DH];   // compacted key order
__device__ __nv_bfloat16 g_kl[BB * HH * NN * DH];
__device__ __half        g_vf[BB * HH * NN * DH];   // V single fp16, compacted
__device__ float g_bqkv[3 * DD];
__device__ int   g_gidx[BB * NN];    // compacted->original index (pad 0)
__device__ int   g_cnt[BB];          // unmasked key count per batch
__device__ float g_padbias[BB * NN]; // 0 for j<cnt, -1e30 beyond

// ---------------------------------------------------------------------------
// Helpers
// ---------------------------------------------------------------------------
__device__ __forceinline__ uint32_t s2u(const void* p) {
    uint32_t a;
    asm("{ .reg .u64 t; cvta.to.shared.u64 t, %1; cvt.u32.u64 %0, t; }"
        : "=r"(a) : "l"(p));
    return a;
}

__device__ __forceinline__ float ex2f(float x) {
    float y;
    asm("ex2.approx.ftz.f32 %0, %1;" : "=f"(y) : "f"(x));
    return y;
}

__device__ __forceinline__ void cpa16(uint32_t dst, const void* src) {
    asm volatile("cp.async.cg.shared.global [%0], [%1], 16;"
                 :: "r"(dst), "l"(src) : "memory");
}
#define CP_COMMIT() asm volatile("cp.async.commit_group;" ::: "memory")
#define CP_WAIT(N)  asm volatile("cp.async.wait_group %0;" :: "n"(N) : "memory")

__device__ __forceinline__ void ldsm4(uint32_t& r0, uint32_t& r1,
                                      uint32_t& r2, uint32_t& r3,
                                      uint32_t addr) {
    asm volatile("ldmatrix.sync.aligned.m8n8.x4.shared.b16 {%0,%1,%2,%3}, [%4];"
                 : "=r"(r0), "=r"(r1), "=r"(r2), "=r"(r3) : "r"(addr));
}

__device__ __forceinline__ void ldsm4t(uint32_t& r0, uint32_t& r1,
                                       uint32_t& r2, uint32_t& r3,
                                       uint32_t addr) {
    asm volatile("ldmatrix.sync.aligned.m8n8.x4.trans.shared.b16 {%0,%1,%2,%3}, [%4];"
                 : "=r"(r0), "=r"(r1), "=r"(r2), "=r"(r3) : "r"(addr));
}

__device__ __forceinline__ void mma16816(float* c, const uint32_t* a,
                                         uint32_t b0, uint32_t b1) {
    asm volatile(
        "mma.sync.aligned.m16n8k16.row.col.f32.bf16.bf16.f32 "
        "{%0,%1,%2,%3}, {%4,%5,%6,%7}, {%8,%9}, {%0,%1,%2,%3};"
        : "+f"(c[0]), "+f"(c[1]), "+f"(c[2]), "+f"(c[3])
        : "r"(a[0]), "r"(a[1]), "r"(a[2]), "r"(a[3]), "r"(b0), "r"(b1));
}

__device__ __forceinline__ void mma16816h(float* c, const uint32_t* a,
                                          uint32_t b0, uint32_t b1) {
    asm volatile(
        "mma.sync.aligned.m16n8k16.row.col.f32.f16.f16.f32 "
        "{%0,%1,%2,%3}, {%4,%5,%6,%7}, {%8,%9}, {%0,%1,%2,%3};"
        : "+f"(c[0]), "+f"(c[1]), "+f"(c[2]), "+f"(c[3])
        : "r"(a[0]), "r"(a[1]), "r"(a[2]), "r"(a[3]), "r"(b0), "r"(b1));
}

// hi/lo bf16 split of a float pair -> two packed bf16x2 regs
__device__ __forceinline__ void hl_pack(float a, float b, uint32_t& hi, uint32_t& lo) {
    __nv_bfloat162 h = __float22bfloat162_rn(make_float2(a, b));
    float2 f = __bfloat1622float2(h);
    __nv_bfloat162 l = __float22bfloat162_rn(make_float2(a - f.x, b - f.y));
    hi = *reinterpret_cast<uint32_t*>(&h);
    lo = *reinterpret_cast<uint32_t*>(&l);
}

// hi/lo fp16 split of a float pair -> two packed half2 regs
__device__ __forceinline__ void hl_pack_f16(float a, float b, uint32_t& hi, uint32_t& lo) {
    __half2 h = __floats2half2_rn(a, b);
    float2 f = __half22float2(h);
    __half2 l = __floats2half2_rn(a - f.x, b - f.y);
    hi = *reinterpret_cast<uint32_t*>(&h);
    lo = *reinterpret_cast<uint32_t*>(&l);
}

__device__ __forceinline__ void hl2_store(float a, float b,
                                          __nv_bfloat16* hip, __nv_bfloat16* lop) {
    uint32_t hi, lo;
    hl_pack(a, b, hi, lo);
    *(uint32_t*)hip = hi;
    *(uint32_t*)lop = lo;
}

__device__ __forceinline__ void hl4_store(float4 v, __nv_bfloat16* hip,
                                          __nv_bfloat16* lop) {
    hl2_store(v.x, v.y, hip, lop);
    hl2_store(v.z, v.w, hip + 2, lop + 2);
}

// ---------------------------------------------------------------------------
// Kernel 0: mask preprocessing (compaction) + bias concat
// ---------------------------------------------------------------------------
__global__ __launch_bounds__(256)
void prep_kernel(const void* __restrict__ mask,
                 const float* __restrict__ bq,
                 const float* __restrict__ bk,
                 const float* __restrict__ bv)
{
    __shared__ int s_packed;
    __shared__ int s_cnt[4];
    if (threadIdx.x == 0) s_packed = 0;
    __syncthreads();

    const unsigned* mw = (const unsigned*)mask;
    int bad = 0;
    for (int i = threadIdx.x; i < 2048; i += 256)
        if (mw[i] > 1u) bad = 1;
    if (bad) atomicOr(&s_packed, 1);
    __syncthreads();
    const bool packed = (s_packed != 0);

    const int* mi = (const int*)mask;
    const unsigned char* mb = (const unsigned char*)mask;

    const int warp = threadIdx.x >> 5, lane = threadIdx.x & 31;
    if (warp < 4) {
        int cnt = 0;
        for (int base = 0; base < NN; base += 32) {
            const int i = warp * NN + base + lane;
            const int on = packed ? (int)mb[i] : mi[i];
            const unsigned bal = __ballot_sync(0xffffffffu, on != 0);
            if (on)
                g_gidx[warp * NN + cnt + __popc(bal & ((1u << lane) - 1))] = base + lane;
            cnt += __popc(bal);
        }
        if (lane == 0) s_cnt[warp] = cnt;
    }
    __syncthreads();

    for (int i = threadIdx.x; i < BB * NN; i += 256) {
        const int bb = i >> 11, j = i & 2047;
        const int cnt = s_cnt[bb];
        g_padbias[i] = (j < cnt) ? 0.0f : -1e30f;
        if (j >= cnt) g_gidx[i] = 0;
    }
    if (threadIdx.x < 4) g_cnt[threadIdx.x] = s_cnt[threadIdx.x];

    for (int i = threadIdx.x; i < DD; i += 256) {
        g_bqkv[i]          = bq[i];
        g_bqkv[DD + i]     = bk[i];
        g_bqkv[2 * DD + i] = bv[i];
    }
}

// ---------------------------------------------------------------------------
// Kernel 1: fused wconv (blocks [0,4096)) + row-LN of x (blocks [4096,12288))
// ---------------------------------------------------------------------------
__global__ __launch_bounds__(256)
void wconv_ln_kernel(const float* __restrict__ x,
                     const float* __restrict__ w,
                     const float* __restrict__ b,
                     const float* __restrict__ W0, const float* __restrict__ W1,
                     const float* __restrict__ W2, const float* __restrict__ W3)
{
    const int blk = blockIdx.x;
    if (blk < 4096) {
        const int slot = blk >> 10;
        const float* W = (slot == 0) ? W0 : (slot == 1) ? W1 : (slot == 2) ? W2 : W3;
        const size_t i = ((size_t)(blk & 1023) * 256 + threadIdx.x) * 4;
        float4 v = *(const float4*)(W + i);
        const size_t off = (size_t)slot * DD * DD + i;
        hl4_store(v, g_whi + off, g_wlo + off);
        return;
    }

    __shared__ float red_s[8];
    __shared__ float red_q[8];
    __shared__ float stats[2];
    const int row = blk - 4096;
    const int t = threadIdx.x;
    const int lane = t & 31, warp = t >> 5;

    const float* xr = x + (long)row * DD;
    float4 xv = *(const float4*)(xr + t * 4);
    float sum = xv.x + xv.y + xv.z + xv.w;
    float ssq = fmaf(xv.x, xv.x, fmaf(xv.y, xv.y, fmaf(xv.z, xv.z, xv.w * xv.w)));
    #pragma unroll
    for (int o = 16; o > 0; o >>= 1) {
        sum += __shfl_xor_sync(0xffffffffu, sum, o);
        ssq += __shfl_xor_sync(0xffffffffu, ssq, o);
    }
    if (lane == 0) { red_s[warp] = sum; red_q[warp] = ssq; }
    __syncthreads();
    if (warp == 0) {
        float a = (lane < 8) ? red_s[lane] : 0.0f;
        float c = (lane < 8) ? red_q[lane] : 0.0f;
        #pragma unroll
        for (int o = 4; o > 0; o >>= 1) {
            a += __shfl_xor_sync(0xffffffffu, a, o);
            c += __shfl_xor_sync(0xffffffffu, c, o);
        }
        if (lane == 0) { stats[0] = a * (1.0f / DD); stats[1] = c * (1.0f / DD); }
    }
    __syncthreads();
    const float mean = stats[0];
    const float var = stats[1] - mean * mean;
    const float rstd = rsqrtf(var + LN_EPS);

    float4 wv = *(const float4*)(w + t * 4);
    float4 bv = *(const float4*)(b + t * 4);
    float4 ov;
    ov.x = (xv.x - mean) * rstd * wv.x + bv.x;
    ov.y = (xv.y - mean) * rstd * wv.y + bv.y;
    ov.z = (xv.z - mean) * rstd * wv.z + bv.z;
    ov.w = (xv.w - mean) * rstd * wv.w + bv.w;
    const size_t off = (size_t)row * DD + t * 4;
    hl4_store(ov, g_xn_hi + off, g_xn_lo + off);
}

// ---------------------------------------------------------------------------
// Kernel 2: HMMA bf16x3 GEMM, cp.async double-buffered, K-slab 32.
// 128x128 CTA tile, 8 warps (4M x 2N), warp tile 32x64, 256 threads.
// MODE 0: out-proj.  A=g_ao, B=slot3, plain fp32 out. grid (8,64).
// MODE 6: fused Q+KV proj. grid (24,64): bn<1024 -> Q path (direct rows,
//         head-LN(q) with LOG2E folded); bn>=1024 -> KV path (rows gathered
//         via g_gidx, compacted out, early-exit past cnt[b]);
//         head-LN(k) hi/lo bf16; V single fp16.
// ---------------------------------------------------------------------------
#define KSL 32
#define SST2 40
#define BUF2 (128 * SST2)
#define STAGE_ELE (4 * BUF2)
#define GEMM_SMEM2 (2 * STAGE_ELE * 2)

template<int MODE>
__global__ __launch_bounds__(256, 2)
void gemm_mma2(float* __restrict__ Cout,
               const float* __restrict__ qn_w, const float* __restrict__ qn_b,
               const float* __restrict__ kn_w, const float* __restrict__ kn_b)
{
    const int bm = blockIdx.y << 7;
    const int bn = blockIdx.x << 7;
    const bool isKV = (MODE == 6) && (bn >= 1024);
    if (MODE == 6 && isKV) {
        if ((bm & 2047) >= g_cnt[bm >> 11]) return;   // whole tile is padding
    }

    extern __shared__ __nv_bfloat16 smg[];
    const uint32_t u0 = s2u(smg);

    const int tid = threadIdx.x;
    const int wid = tid >> 5, lane = tid & 31;
    const int wm = (wid & 3) << 5;
    const int wn = (wid >> 2) << 6;

    const __nv_bfloat16* gAh = (MODE == 0) ? g_ao_hi : g_xn_hi;
    const __nv_bfloat16* gAl = (MODE == 0) ? g_ao_lo : g_xn_lo;
    const __nv_bfloat16* gBh = (MODE == 0) ? (g_whi + (size_t)3 * DD * DD) : g_whi;
    const __nv_bfloat16* gBl = (MODE == 0) ? (g_wlo + (size_t)3 * DD * DD) : g_wlo;

    float acc[2][8][4];
    #pragma unroll
    for (int i = 0; i < 2; i++)
        #pragma unroll
        for (int j = 0; j < 8; j++)
            #pragma unroll
            for (int k = 0; k < 4; k++) acc[i][j][k] = 0.0f;

    const int lrow = tid >> 1;
    const int lhalf = (tid & 1) << 4;
    int arow;
    if (MODE == 6 && isKV) arow = (bm & ~2047) + g_gidx[bm + lrow];
    else                   arow = bm + lrow;
    const __nv_bfloat16* pAh = gAh + (size_t)arow * DD + lhalf;
    const __nv_bfloat16* pAl = gAl + (size_t)arow * DD + lhalf;
    const __nv_bfloat16* pBh = gBh + (size_t)(bn + lrow) * DD + lhalf;
    const __nv_bfloat16* pBl = gBl + (size_t)(bn + lrow) * DD + lhalf;
    const uint32_t dbase = u0 + (lrow * SST2 + lhalf) * 2;

    const int aRow = (lane & 7) + ((lane & 8) ? 8 : 0);
    const int aK   = (lane & 16) ? 8 : 0;
    const int bRow = (lane & 7) + ((lane & 16) ? 8 : 0);
    const int bK   = (lane & 8) ? 8 : 0;

    #define ISSUE_STAGE(kt, stg) do {                                        \
        const uint32_t d_ = dbase + (stg) * (STAGE_ELE * 2);                  \
        cpa16(d_ + 0 * BUF2 * 2,      pAh + (kt));                            \
        cpa16(d_ + 0 * BUF2 * 2 + 16, pAh + (kt) + 8);                        \
        cpa16(d_ + 1 * BUF2 * 2,      pAl + (kt));                            \
        cpa16(d_ + 1 * BUF2 * 2 + 16, pAl + (kt) + 8);                        \
        cpa16(d_ + 2 * BUF2 * 2,      pBh + (kt));                            \
        cpa16(d_ + 2 * BUF2 * 2 + 16, pBh + (kt) + 8);                        \
        cpa16(d_ + 3 * BUF2 * 2,      pBl + (kt));                            \
        cpa16(d_ + 3 * BUF2 * 2 + 16, pBl + (kt) + 8);                        \
        CP_COMMIT();                                                          \
    } while (0)

    ISSUE_STAGE(0, 0);

    const int NSLAB = DD / KSL;
    for (int s = 0; s < NSLAB; s++) {
        if (s + 1 < NSLAB) {
            ISSUE_STAGE((s + 1) * KSL, (s + 1) & 1);
            CP_WAIT(1);
        } else {
            CP_WAIT(0);
        }
        __syncthreads();

        const uint32_t sb = u0 + (s & 1) * (STAGE_ELE * 2);
        const uint32_t aAh = sb + ((wm + aRow) * SST2 + aK) * 2;
        const uint32_t aAl = aAh + BUF2 * 2;
        const uint32_t aBh = sb + 2 * BUF2 * 2 + ((wn + bRow) * SST2 + bK) * 2;
        const uint32_t aBl = aBh + BUF2 * 2;

        #pragma unroll
        for (int k16 = 0; k16 < 2; k16++) {
            const uint32_t koff = (k16 << 4) * 2;
            uint32_t ah[2][4], al[2][4];
            #pragma unroll
            for (int mt = 0; mt < 2; mt++) {
                const uint32_t moff = (mt << 4) * SST2 * 2;
                ldsm4(ah[mt][0], ah[mt][1], ah[mt][2], ah[mt][3], aAh + moff + koff);
                ldsm4(al[mt][0], al[mt][1], al[mt][2], al[mt][3], aAl + moff + koff);
            }
            #pragma unroll
            for (int p = 0; p < 4; p++) {
                const uint32_t noff = (p << 4) * SST2 * 2;
                uint32_t bh0, bh1, bh2, bh3, bl0, bl1, bl2, bl3;
                ldsm4(bh0, bh1, bh2, bh3, aBh + noff + koff);
                ldsm4(bl0, bl1, bl2, bl3, aBl + noff + koff);
                #pragma unroll
                for (int mt = 0; mt < 2; mt++) {
                    mma16816(acc[mt][2 * p + 0], ah[mt], bh0, bh1);
                    mma16816(acc[mt][2 * p + 1], ah[mt], bh2, bh3);
                }
                #pragma unroll
                for (int mt = 0; mt < 2; mt++) {
                    mma16816(acc[mt][2 * p + 0], ah[mt], bl0, bl1);
                    mma16816(acc[mt][2 * p + 1], ah[mt], bl2, bl3);
                }
                #pragma unroll
                for (int mt = 0; mt < 2; mt++) {
                    mma16816(acc[mt][2 * p + 0], al[mt], bh0, bh1);
                    mma16816(acc[mt][2 * p + 1], al[mt], bh2, bh3);
                }
            }
        }
        __syncthreads();
    }
    #undef ISSUE_STAGE

    // Epilogue
    const int g = lane >> 2, tq = lane & 3;
    if (MODE == 0) {
        #pragma unroll
        for (int mt = 0; mt < 2; mt++)
            #pragma unroll
            for (int nt = 0; nt < 8; nt++) {
                const int c = bn + wn + nt * 8 + 2 * tq;
                #pragma unroll
                for (int half = 0; half < 2; half++) {
                    const int r = bm + wm + mt * 16 + g + half * 8;
                    float2 v;
                    v.x = acc[mt][nt][2 * half + 0];
                    v.y = acc[mt][nt][2 * half + 1];
                    *(float2*)(Cout + (size_t)r * DD + c) = v;
                }
            }
    } else {
        const int which = (bn + wn) >> 10;            // 0=q, 1=k, 2=v
        const int h = ((bn + wn) & 1023) >> 6;
        if (which < 2) {
            const float* wvec = which ? kn_w : qn_w;
            const float* bvec = which ? kn_b : qn_b;
            __nv_bfloat16* oh = which ? g_kh : g_qh;
            __nv_bfloat16* ol = which ? g_kl : g_ql;
            // q scale folds DH^-0.5 and log2(e) so softmax can use ex2
            const float sc = which ? 1.0f : (0.125f * LOG2E);
            #pragma unroll
            for (int mt = 0; mt < 2; mt++)
                #pragma unroll
                for (int half = 0; half < 2; half++) {
                    const int r = bm + wm + mt * 16 + g + half * 8;
                    float v[16];
                    float sum = 0.0f, ssq = 0.0f;
                    #pragma unroll
                    for (int nt = 0; nt < 8; nt++) {
                        const int c = bn + wn + nt * 8 + 2 * tq;
                        const float2 bb = *(const float2*)(g_bqkv + c);
                        const float a0 = acc[mt][nt][2 * half + 0] + bb.x;
                        const float a1 = acc[mt][nt][2 * half + 1] + bb.y;
                        v[2 * nt + 0] = a0;
                        v[2 * nt + 1] = a1;
                        sum += a0 + a1;
                        ssq = fmaf(a0, a0, fmaf(a1, a1, ssq));
                    }
                    sum += __shfl_xor_sync(0xffffffffu, sum, 1);
                    sum += __shfl_xor_sync(0xffffffffu, sum, 2);
                    ssq += __shfl_xor_sync(0xffffffffu, ssq, 1);
                    ssq += __shfl_xor_sync(0xffffffffu, ssq, 2);
                    const float mean = sum * (1.0f / DH);
                    const float var = ssq * (1.0f / DH) - mean * mean;
                    const float rstd = rsqrtf(var + LN_EPS);
                    const size_t rowoff =
                        ((((size_t)((r >> 11) * HH + h)) * NN + (r & 2047)) << 6);
                    #pragma unroll
                    for (int nt = 0; nt < 8; nt++) {
                        const int dh = nt * 8 + 2 * tq;
                        const float2 wv = *(const float2*)(wvec + dh);
                        const float2 b2 = *(const float2*)(bvec + dh);
                        const float a = ((v[2 * nt + 0] - mean) * rstd * wv.x + b2.x) * sc;
                        const float c2 = ((v[2 * nt + 1] - mean) * rstd * wv.y + b2.y) * sc;
                        hl2_store(a, c2, oh + rowoff + dh, ol + rowoff + dh);
                    }
                }
        } else {
            // v: bias + single fp16 store at compacted rows
            #pragma unroll
            for (int mt = 0; mt < 2; mt++)
                #pragma unroll
                for (int nt = 0; nt < 8; nt++) {
                    const int c = bn + wn + nt * 8 + 2 * tq;
                    const float2 bb = *(const float2*)(g_bqkv + c);
                    #pragma unroll
                    for (int half = 0; half < 2; half++) {
                        const int r = bm + wm + mt * 16 + g + half * 8;
                        const float a0 = acc[mt][nt][2 * half + 0] + bb.x;
                        const float a1 = acc[mt][nt][2 * half + 1] + bb.y;
                        const size_t idx =
                            ((((size_t)((r >> 11) * HH + h)) * NN + (r & 2047)) << 6)
                            + ((c & 1023) & 63);
                        __half2 hv = __floats2half2_rn(a0, a1);
                        *(uint32_t*)(g_vf + idx) = *reinterpret_cast<uint32_t*>(&hv);
                    }
                }
        }
    }
}

// ---------------------------------------------------------------------------
// Kernel 4: tensor-core flash attention over COMPACTED keys (contiguous K/V)
// QK^T bf16x3; PV = P(fp16 hi/lo) x V(fp16 single), 2 passes.
// Scores are in log2 units (LOG2E folded into q) -> softmax uses ex2.
// 512 threads / 16 warps, q-tile 256. grid (8, 16, 4).
// ---------------------------------------------------------------------------
#define ASTR 72
#define ATT_STAGE (3 * 64 * ASTR)                 // Kh, Kl (bf16), Vf (fp16)
#define ATT_SMEM (2 * ATT_STAGE * 2 + 2 * 64 * 4)

__global__ __launch_bounds__(512, 1)
void attn_mma_kernel()
{
    extern __shared__ __nv_bfloat16 sma[];
    const uint32_t u0 = s2u(sma);
    float* mbs = (float*)(sma + 2 * ATT_STAGE);
    const uint32_t mb_u = u0 + 2 * ATT_STAGE * 2;

    const int tid = threadIdx.x, wid = tid >> 5, lane = tid & 31;
    const int bq = blockIdx.x << 8;               // 256 queries per CTA
    const int h = blockIdx.y, b = blockIdx.z;
    const size_t head_off = ((size_t)(b * HH + h)) * NN;

    const int aRow = (lane & 7) + ((lane & 8) ? 8 : 0);
    const int aK   = (lane & 16) ? 8 : 0;
    const int bRow = (lane & 7) + ((lane & 16) ? 8 : 0);
    const int bK   = (lane & 8) ? 8 : 0;
    const int vRow = (lane & 7) + ((lane & 8) ? 8 : 0);
    const int vCol = (lane & 16) ? 8 : 0;

    // ---- Phase 1: stage Q hi then Q lo through rows [0,256) (two passes)
    uint32_t qh[4][4], ql[4][4];
    {
        const int r = tid >> 1;                   // 0..255
        const int c = (tid & 1) << 5;
        const uint32_t qb = u0 + ((wid * 16 + aRow) * ASTR + aK) * 2;

        const __nv_bfloat16* sh = g_qh + (head_off + bq + r) * DH + c;
        #pragma unroll
        for (int i = 0; i < 4; i++)
            *(uint4*)(sma + r * ASTR + c + i * 8) = *(const uint4*)(sh + i * 8);
        __syncthreads();
        #pragma unroll
        for (int k = 0; k < 4; k++)
            ldsm4(qh[k][0], qh[k][1], qh[k][2], qh[k][3], qb + (k * 16) * 2);
        __syncthreads();

        const __nv_bfloat16* sl = g_ql + (head_off + bq + r) * DH + c;
        #pragma unroll
        for (int i = 0; i < 4; i++)
            *(uint4*)(sma + r * ASTR + c + i * 8) = *(const uint4*)(sl + i * 8);
        __syncthreads();
        #pragma unroll
        for (int k = 0; k < 4; k++)
            ldsm4(ql[k][0], ql[k][1], ql[k][2], ql[k][3], qb + (k * 16) * 2);
        __syncthreads();
    }

    float o[8][4];
    #pragma unroll
    for (int i = 0; i < 8; i++)
        #pragma unroll
        for (int j = 0; j < 4; j++) o[i][j] = 0.0f;
    float m0 = -1e30f, m1 = -1e30f, l0 = 0.0f, l1 = 0.0f;

    const float* mrow = g_padbias + b * NN;
    const int cnt = g_cnt[b];
    const int NT = (cnt + 63) >> 6;
    const int tq2 = (lane & 3) * 2;

    // cp.async loader: 512 threads cover 64 rows x 64 cols, one cpa16/buffer
    const int ldr = tid >> 3;                     // 0..63
    const int ldc = (tid & 7) << 3;               // 0..56 step 8
    const uint32_t sdst = u0 + (ldr * ASTR + ldc) * 2;

    #define ISSUE_ATT(kt, stg) do {                                           \
        const uint32_t d_ = sdst + (stg) * (ATT_STAGE * 2);                    \
        const size_t gi_ = (head_off + (kt) + ldr) * DH + ldc;                 \
        cpa16(d_ + 0 * 64 * ASTR * 2, g_kh + gi_);                             \
        cpa16(d_ + 1 * 64 * ASTR * 2, g_kl + gi_);                             \
        cpa16(d_ + 2 * 64 * ASTR * 2, g_vf + gi_);                             \
        if (tid < 16)                                                          \
            cpa16(mb_u + (stg) * 256 + tid * 16, mrow + (kt) + tid * 4);       \
        CP_COMMIT();                                                           \
    } while (0)

    ISSUE_ATT(0, 0);

    for (int ti = 0; ti < NT; ti++) {
        if (ti + 1 < NT) {
            ISSUE_ATT((ti + 1) * 64, (ti + 1) & 1);
            CP_WAIT(1);
        } else {
            CP_WAIT(0);
        }
        __syncthreads();

        const uint32_t sb = u0 + (ti & 1) * (ATT_STAGE * 2);
        const uint32_t Kh = sb;
        const uint32_t Kl = sb + 64 * ASTR * 2;
        const uint32_t Vf = sb + 2 * 64 * ASTR * 2;
        const float* mb = mbs + (ti & 1) * 64;

        // S = Q K^T  (bf16x3), per-p interleaved K loads
        float s[8][4];
        #pragma unroll
        for (int i = 0; i < 8; i++)
            #pragma unroll
            for (int j = 0; j < 4; j++) s[i][j] = 0.0f;

        #pragma unroll
        for (int k = 0; k < 4; k++) {
            #pragma unroll
            for (int p = 0; p < 4; p++) {
                const uint32_t nb = ((p * 16 + bRow) * ASTR + k * 16 + bK) * 2;
                uint32_t kh0, kh1, kh2, kh3, kl0, kl1, kl2, kl3;
                ldsm4(kh0, kh1, kh2, kh3, Kh + nb);
                ldsm4(kl0, kl1, kl2, kl3, Kl + nb);
                mma16816(s[2 * p + 0], qh[k], kh0, kh1);
                mma16816(s[2 * p + 1], qh[k], kh2, kh3);
                mma16816(s[2 * p + 0], qh[k], kl0, kl1);
                mma16816(s[2 * p + 1], qh[k], kl2, kl3);
                mma16816(s[2 * p + 0], ql[k], kh0, kh1);
                mma16816(s[2 * p + 1], ql[k], kh2, kh3);
            }
        }

        // bias (tile padding) + online softmax in log2 domain (ex2)
        float mx0 = -1e30f, mx1 = -1e30f;
        #pragma unroll
        for (int nt = 0; nt < 8; nt++) {
            const float b0 = mb[nt * 8 + tq2];
            const float b1 = mb[nt * 8 + tq2 + 1];
            s[nt][0] += b0; s[nt][1] += b1;
            s[nt][2] += b0; s[nt][3] += b1;
            mx0 = fmaxf(mx0, fmaxf(s[nt][0], s[nt][1]));
            mx1 = fmaxf(mx1, fmaxf(s[nt][2], s[nt][3]));
        }
        mx0 = fmaxf(mx0, __shfl_xor_sync(0xffffffffu, mx0, 1));
        mx0 = fmaxf(mx0, __shfl_xor_sync(0xffffffffu, mx0, 2));
        mx1 = fmaxf(mx1, __shfl_xor_sync(0xffffffffu, mx1, 1));
        mx1 = fmaxf(mx1, __shfl_xor_sync(0xffffffffu, mx1, 2));
        const float mn0 = fmaxf(m0, mx0), mn1 = fmaxf(m1, mx1);
        const float sc0 = ex2f(m0 - mn0), sc1 = ex2f(m1 - mn1);
        m0 = mn0; m1 = mn1;
        float ps0 = 0.0f, ps1 = 0.0f;
        #pragma unroll
        for (int nt = 0; nt < 8; nt++) {
            s[nt][0] = ex2f(s[nt][0] - m0);
            s[nt][1] = ex2f(s[nt][1] - m0);
            s[nt][2] = ex2f(s[nt][2] - m1);
            s[nt][3] = ex2f(s[nt][3] - m1);
            ps0 += s[nt][0] + s[nt][1];
            ps1 += s[nt][2] + s[nt][3];
        }
        ps0 += __shfl_xor_sync(0xffffffffu, ps0, 1);
        ps0 += __shfl_xor_sync(0xffffffffu, ps0, 2);
        ps1 += __shfl_xor_sync(0xffffffffu, ps1, 1);
        ps1 += __shfl_xor_sync(0xffffffffu, ps1, 2);
        l0 = l0 * sc0 + ps0;
        l1 = l1 * sc1 + ps1;
        #pragma unroll
        for (int nt = 0; nt < 8; nt++) {
            o[nt][0] *= sc0; o[nt][1] *= sc0;
            o[nt][2] *= sc1; o[nt][3] *= sc1;
        }

        // O += P V   (P fp16 hi/lo x V fp16, 2 passes; p in pairs)
        #pragma unroll
        for (int jj = 0; jj < 4; jj++) {
            uint32_t ph[4], pl[4];
            hl_pack_f16(s[2 * jj][0],     s[2 * jj][1],     ph[0], pl[0]);
            hl_pack_f16(s[2 * jj][2],     s[2 * jj][3],     ph[1], pl[1]);
            hl_pack_f16(s[2 * jj + 1][0], s[2 * jj + 1][1], ph[2], pl[2]);
            hl_pack_f16(s[2 * jj + 1][2], s[2 * jj + 1][3], ph[3], pl[3]);
            #pragma unroll
            for (int pp = 0; pp < 2; pp++) {
                uint32_t vh[2][4];
                #pragma unroll
                for (int q = 0; q < 2; q++) {
                    const int p = pp * 2 + q;
                    const uint32_t off = ((jj * 16 + vRow) * ASTR + p * 16 + vCol) * 2;
                    ldsm4t(vh[q][0], vh[q][1], vh[q][2], vh[q][3], Vf + off);
                }
                #pragma unroll
                for (int q = 0; q < 2; q++) {
                    const int p = pp * 2 + q;
                    mma16816h(o[2 * p + 0], ph, vh[q][0], vh[q][1]);
                    mma16816h(o[2 * p + 1], ph, vh[q][2], vh[q][3]);
                }
                #pragma unroll
                for (int q = 0; q < 2; q++) {
                    const int p = pp * 2 + q;
                    mma16816h(o[2 * p + 0], pl, vh[q][0], vh[q][1]);
                    mma16816h(o[2 * p + 1], pl, vh[q][2], vh[q][3]);
                }
            }
        }
        __syncthreads();
    }
    #undef ISSUE_ATT

    // epilogue -> g_ao hi/lo   [b, n, h*64+dh]
    const float inv0 = 1.0f / l0, inv1 = 1.0f / l1;
    const int g = lane >> 2;
    const int q0 = bq + wid * 16 + g;
    const size_t ob = ((size_t)(b * NN) + q0) * DD + h * DH;
    #pragma unroll
    for (int nt = 0; nt < 8; nt++) {
        const int dh = nt * 8 + tq2;
        hl2_store(o[nt][0] * inv0, o[nt][1] * inv0, g_ao_hi + ob + dh, g_ao_lo + ob + dh);
        hl2_store(o[nt][2] * inv1, o[nt][3] * inv1,
                  g_ao_hi + ob + 8 * DD + dh, g_ao_lo + ob + 8 * DD + dh);
    }
}

// ---------------------------------------------------------------------------
// Launch
// ---------------------------------------------------------------------------
extern "C" void kernel_launch(void* const* d_in, const int* in_sizes, int n_in,
                              void* d_out, int out_size)
{
    const float* x       = (const float*)d_in[0];
    const void*  mask    = (const void*)d_in[1];
    const float* norm_w  = (const float*)d_in[2];
    const float* norm_b  = (const float*)d_in[3];
    const float* qn_w    = (const float*)d_in[4];
    const float* qn_b    = (const float*)d_in[5];
    const float* kn_w    = (const float*)d_in[6];
    const float* kn_b    = (const float*)d_in[7];
    const float* Wq      = (const float*)d_in[8];
    const float* bq      = (const float*)d_in[9];
    const float* Wk      = (const float*)d_in[10];
    const float* bk      = (const float*)d_in[11];
    const float* Wv      = (const float*)d_in[12];
    const float* bv      = (const float*)d_in[13];
    const float* Wo      = (const float*)d_in[14];
    float* out = (float*)d_out;

    static bool attr_done = false;
    if (!attr_done) {
        cudaFuncSetAttribute(gemm_mma2<0>, cudaFuncAttributeMaxDynamicSharedMemorySize, GEMM_SMEM2);
        cudaFuncSetAttribute(gemm_mma2<6>, cudaFuncAttributeMaxDynamicSharedMemorySize, GEMM_SMEM2);
        cudaFuncSetAttribute(attn_mma_kernel, cudaFuncAttributeMaxDynamicSharedMemorySize, ATT_SMEM);
        attr_done = true;
    }

    // 0. Mask compaction + bias concat
    prep_kernel<<<1, 256>>>(mask, bq, bk, bv);

    // 1. Fused W-conversion + LN(x)
    wconv_ln_kernel<<<4096 + BN, 256>>>(x, norm_w, norm_b, Wq, Wk, Wv, Wo);

    // 2. Fused Q+KV projection (Q: all rows; KV: compacted rows, early-exit)
    gemm_mma2<6><<<dim3(3 * DD / 128, BN / 128), 256, GEMM_SMEM2>>>(
        nullptr, qn_w, qn_b, kn_w, kn_b);

    // 3. Tensor-core flash attention over compacted keys -> g_ao hi/lo
    attn_mma_kernel<<<dim3(NN / 256, HH, BB), 512, ATT_SMEM>>>();

    // 4. Output projection -> d_out
    gemm_mma2<0><<<dim3(DD / 128, BN / 128), 256, GEMM_SMEM2>>>(
        out, nullptr, nullptr, nullptr, nullptr);
}